// round 1
// baseline (speedup 1.0000x reference)
#include <cuda_runtime.h>
#include <math.h>

// ---------------------------------------------------------------------------
// Problem dims
//   B=2, S=1024, D=768, H=12, DH=64, M=64, DFF=3072
//   rows N = B*S = 2048
// Chunked causal linear attention: C=16 chunks of L=64 tokens.
// ---------------------------------------------------------------------------

#define ROWS   2048
#define DMODEL 768
#define D3     2304
#define DFF    3072
#define NH     12
#define BH     24          // B*H
#define DH     64
#define MF     64          // random features
#define CHUNK  64
#define NCHUNK 16

// Scratch (device globals; allocation is forbidden)
__device__ float g_a   [ROWS * DMODEL];      // LN1 out, later LN2 out
__device__ float g_qkv [ROWS * D3];
__device__ float g_phiq[BH * 1024 * MF];
__device__ float g_phik[BH * 1024 * MF];
__device__ float g_kv  [BH * NCHUNK * MF * DH];
__device__ float g_kvp [BH * NCHUNK * MF * DH];
__device__ float g_ks  [BH * NCHUNK * MF];
__device__ float g_ksp [BH * NCHUNK * MF];
__device__ float g_ctx [ROWS * DMODEL];
__device__ float g_x2  [ROWS * DMODEL];
__device__ float g_ffn [ROWS * DFF];

// ---------------------------------------------------------------------------
// LayerNorm: one block per row (768), 256 threads, 3 elems/thread
// ---------------------------------------------------------------------------
__global__ void ln_kernel(const float* __restrict__ in,
                          const float* __restrict__ gamma,
                          const float* __restrict__ beta,
                          float* __restrict__ out)
{
    int row = blockIdx.x;
    int t = threadIdx.x;
    const float* p = in + (size_t)row * DMODEL;
    float v[3];
    float s = 0.f, s2 = 0.f;
#pragma unroll
    for (int i = 0; i < 3; i++) {
        v[i] = p[t + i * 256];
        s += v[i];
        s2 += v[i] * v[i];
    }
#pragma unroll
    for (int o = 16; o; o >>= 1) {
        s  += __shfl_xor_sync(0xffffffffu, s, o);
        s2 += __shfl_xor_sync(0xffffffffu, s2, o);
    }
    __shared__ float ss[8], ss2[8];
    if ((t & 31) == 0) { ss[t >> 5] = s; ss2[t >> 5] = s2; }
    __syncthreads();
    s = 0.f; s2 = 0.f;
#pragma unroll
    for (int i = 0; i < 8; i++) { s += ss[i]; s2 += ss2[i]; }
    float mu  = s * (1.f / DMODEL);
    float var = s2 * (1.f / DMODEL) - mu * mu;
    float rstd = rsqrtf(var + 1e-5f);
    float* q = out + (size_t)row * DMODEL;
#pragma unroll
    for (int i = 0; i < 3; i++) {
        int c = t + i * 256;
        q[c] = (v[i] - mu) * rstd * gamma[c] + beta[c];
    }
}

// ---------------------------------------------------------------------------
// SGEMM: C[M,N] = A[M,K] @ B[K,N] + bias (+gelu) (+residual)
// 128x128 block tile, 8x8 micro tile, K-tile 8, register prefetch.
// M,N multiples of 128; K multiple of 8. Row-major everywhere.
// ---------------------------------------------------------------------------
template <bool GELU, bool RES>
__global__ __launch_bounds__(256, 2)
void sgemm_kernel(const float* __restrict__ A, const float* __restrict__ B,
                  const float* __restrict__ bias, const float* __restrict__ res,
                  float* __restrict__ C, int M, int N, int K)
{
    __shared__ float As[8][128];
    __shared__ float Bs[8][128];
    int t  = threadIdx.x;
    int bm = blockIdx.y * 128;
    int bn = blockIdx.x * 128;

    int arow = t >> 1, ak4 = (t & 1) * 4;      // A: 128 rows x 8 k, float4 along k
    int bkk  = t >> 5, bcol4 = (t & 31) * 4;   // B: 8 k x 128 cols, float4 along n

    const float* Aptr = A + (size_t)(bm + arow) * K + ak4;
    const float* Bptr = B + (size_t)bkk * N + bn + bcol4;

    float4 na = *(const float4*)Aptr;
    float4 nb = *(const float4*)Bptr;

    float acc[8][8];
#pragma unroll
    for (int i = 0; i < 8; i++)
#pragma unroll
        for (int j = 0; j < 8; j++) acc[i][j] = 0.f;

    int tr = (t >> 4) * 8;
    int tc = (t & 15) * 8;
    int nk = K >> 3;

    for (int kt = 0; kt < nk; kt++) {
        As[ak4 + 0][arow] = na.x;
        As[ak4 + 1][arow] = na.y;
        As[ak4 + 2][arow] = na.z;
        As[ak4 + 3][arow] = na.w;
        *(float4*)&Bs[bkk][bcol4] = nb;
        __syncthreads();
        if (kt + 1 < nk) {
            na = *(const float4*)(Aptr + (size_t)(kt + 1) * 8);
            nb = *(const float4*)(Bptr + (size_t)(kt + 1) * 8 * N);
        }
#pragma unroll
        for (int kk = 0; kk < 8; kk++) {
            float a[8], b[8];
#pragma unroll
            for (int i = 0; i < 8; i++) a[i] = As[kk][tr + i];
#pragma unroll
            for (int j = 0; j < 8; j++) b[j] = Bs[kk][tc + j];
#pragma unroll
            for (int i = 0; i < 8; i++)
#pragma unroll
                for (int j = 0; j < 8; j++) acc[i][j] += a[i] * b[j];
        }
        __syncthreads();
    }

#pragma unroll
    for (int i = 0; i < 8; i++) {
        int row = bm + tr + i;
#pragma unroll
        for (int j = 0; j < 8; j++) {
            int col = bn + tc + j;
            float v = acc[i][j] + bias[col];
            if (GELU) {
                float u = v;
                float c = u + 0.044715f * u * u * u;
                v = 0.5f * u * (1.f + tanhf(0.7978845608028654f * c));
            }
            if (RES) v += res[(size_t)row * N + col];
            C[(size_t)row * N + col] = v;
        }
    }
}

// ---------------------------------------------------------------------------
// FAVOR+ features: phi(x) = exp(x_s . w_m - 0.5|x_s|^2)/sqrt(M) + 1e-6
// grid (S, BH, 2[q/k]), 64 threads: thread m computes one feature.
// ---------------------------------------------------------------------------
__global__ void phi_kernel(const float* __restrict__ qkv,
                           const float* __restrict__ wf,
                           float* __restrict__ phiq,
                           float* __restrict__ phik)
{
    int s   = blockIdx.x;
    int bh  = blockIdx.y;
    int isk = blockIdx.z;
    int h = bh % NH, b = bh / NH;
    int t = threadIdx.x;

    __shared__ float xs[64];
    const float* src = qkv + ((size_t)(b * 1024 + s)) * D3 + isk * DMODEL + h * DH;
    xs[t] = src[t] * 0.3535533905932738f;   // DH^-0.25
    __syncthreads();

    float proj = 0.f, sq = 0.f;
    const float* wrow = wf + t * DH;
#pragma unroll 16
    for (int d = 0; d < 64; d++) {
        float x = xs[d];
        proj += x * wrow[d];
        sq   += x * x;
    }
    float val = expf(proj - 0.5f * sq) * 0.125f + 1e-6f;   // 1/sqrt(64)=0.125
    float* dst = (isk ? phik : phiq);
    dst[((size_t)bh * 1024 + s) * MF + t] = val;
}

// ---------------------------------------------------------------------------
// Per-chunk KV state: KV[m,d] = sum_{s in chunk} phi_k[s,m] * v[s,d]; ksum[m].
// grid (NCHUNK, BH), 256 threads. Lane-contiguous m => conflict-free smem.
// ---------------------------------------------------------------------------
__global__ void chunkkv_kernel(const float* __restrict__ qkv,
                               const float* __restrict__ phik,
                               float* __restrict__ kvs,
                               float* __restrict__ ks)
{
    int c  = blockIdx.x;
    int bh = blockIdx.y;
    int h = bh % NH, b = bh / NH;
    int t = threadIdx.x;

    __shared__ float pk[CHUNK][MF];
    __shared__ float sv[CHUNK][DH];

    for (int i = t; i < CHUNK * 64; i += 256) {
        int s = i >> 6, d = i & 63;
        pk[s][d] = phik[((size_t)bh * 1024 + c * CHUNK + s) * MF + d];
        sv[s][d] = qkv[((size_t)(b * 1024 + c * CHUNK + s)) * D3 + 2 * DMODEL + h * DH + d];
    }
    __syncthreads();

    int m  = t & 63;          // lane-contiguous
    int db = (t >> 6) * 16;   // warp-uniform
    float acc[16];
#pragma unroll
    for (int j = 0; j < 16; j++) acc[j] = 0.f;
    float sksum = 0.f;

    for (int s = 0; s < CHUNK; s++) {
        float pkm = pk[s][m];
        if (db == 0) sksum += pkm;
#pragma unroll
        for (int j = 0; j < 16; j++) acc[j] += pkm * sv[s][db + j];
    }
    float* dst = kvs + ((size_t)bh * NCHUNK + c) * (MF * DH) + m * DH + db;
#pragma unroll
    for (int j = 0; j < 16; j++) dst[j] = acc[j];
    if (db == 0) ks[((size_t)bh * NCHUNK + c) * MF + m] = sksum;
}

// ---------------------------------------------------------------------------
// Exclusive prefix over the 16 chunk states per (b,h). grid BH, 256 threads.
// ---------------------------------------------------------------------------
__global__ void scan_kernel(const float* __restrict__ kvs,
                            const float* __restrict__ ks,
                            float* __restrict__ kvp,
                            float* __restrict__ ksp)
{
    int bh = blockIdx.x;
    int t = threadIdx.x;
    float acc[16];
#pragma unroll
    for (int r = 0; r < 16; r++) acc[r] = 0.f;
    float accs = 0.f;

    for (int c = 0; c < NCHUNK; c++) {
        size_t base = ((size_t)bh * NCHUNK + c) * (MF * DH);
#pragma unroll
        for (int r = 0; r < 16; r++) {
            int idx = t + r * 256;
            float v = kvs[base + idx];
            kvp[base + idx] = acc[r];
            acc[r] += v;
        }
        if (t < MF) {
            size_t kb = ((size_t)bh * NCHUNK + c) * MF + t;
            float v = ks[kb];
            ksp[kb] = accs;
            accs += v;
        }
    }
}

// ---------------------------------------------------------------------------
// Intra-chunk causal combine:
//   A = tril(phi_q phi_k^T); num = A @ v + phi_q @ KVpre; den = A@1 + phi_q@kspre
//   ctx = num/den, written into [B,S,D] merged-head layout.
// grid (NCHUNK, BH), 256 threads, ~81 KB dynamic smem.
// ---------------------------------------------------------------------------
__global__ __launch_bounds__(256, 2)
void intra_kernel(const float* __restrict__ qkv,
                  const float* __restrict__ phiq,
                  const float* __restrict__ phik,
                  const float* __restrict__ kvpre,
                  const float* __restrict__ kspre,
                  float* __restrict__ ctx)
{
    extern __shared__ float sm[];
    // pq padded (per-lane row access), sA padded; pk/sv/skv broadcast-read.
    float (*pq)[65]  = (float(*)[65])sm;                   // 64*65
    float (*pk)[64]  = (float(*)[64])(sm + 64 * 65);       // 64*64
    float (*sA)[65]  = (float(*)[65])(sm + 64 * 65 + 64 * 64);
    float (*sv)[64]  = (float(*)[64])(sm + 2 * 64 * 65 + 64 * 64);
    float (*skv)[64] = (float(*)[64])(sm + 2 * 64 * 65 + 2 * 64 * 64);
    float* sks       = sm + 2 * 64 * 65 + 3 * 64 * 64;

    int c  = blockIdx.x;
    int bh = blockIdx.y;
    int h = bh % NH, b = bh / NH;
    int t = threadIdx.x;
    size_t kvbase = ((size_t)bh * NCHUNK + c) * (MF * DH);

    for (int i = t; i < 64 * 64; i += 256) {
        int s = i >> 6, d = i & 63;
        size_t prow = ((size_t)bh * 1024 + c * CHUNK + s) * MF + d;
        pq[s][d] = phiq[prow];
        pk[s][d] = phik[prow];
        sv[s][d] = qkv[((size_t)(b * 1024 + c * CHUNK + s)) * D3 + 2 * DMODEL + h * DH + d];
        skv[s][d] = kvpre[kvbase + i];
    }
    if (t < MF) sks[t] = kspre[((size_t)bh * NCHUNK + c) * MF + t];
    __syncthreads();

    int i  = t & 63;          // lane-contiguous row
    int jb = (t >> 6) * 16;   // warp-uniform slice

    // A[i, jb..jb+15]
    float a[16];
#pragma unroll
    for (int jj = 0; jj < 16; jj++) a[jj] = 0.f;
    for (int m = 0; m < MF; m++) {
        float pqv = pq[i][m];
#pragma unroll
        for (int jj = 0; jj < 16; jj++) a[jj] += pqv * pk[jb + jj][m];
    }
#pragma unroll
    for (int jj = 0; jj < 16; jj++) sA[i][jb + jj] = (jb + jj <= i) ? a[jj] : 0.f;
    __syncthreads();

    int db = jb;
    float num[16];
#pragma unroll
    for (int dd = 0; dd < 16; dd++) num[dd] = 0.f;
    float den = 0.f;

    for (int j = 0; j < CHUNK; j++) {       // zeros above diagonal
        float av = sA[i][j];
        den += av;
#pragma unroll
        for (int dd = 0; dd < 16; dd++) num[dd] += av * sv[j][db + dd];
    }
    for (int m = 0; m < MF; m++) {
        float pqv = pq[i][m];
        den += pqv * sks[m];
#pragma unroll
        for (int dd = 0; dd < 16; dd++) num[dd] += pqv * skv[m][db + dd];
    }

    float inv = 1.f / den;
    float* dst = ctx + ((size_t)(b * 1024 + c * CHUNK + i)) * DMODEL + h * DH + db;
#pragma unroll
    for (int dd = 0; dd < 16; dd++) dst[dd] = num[dd] * inv;
}

// ---------------------------------------------------------------------------
// Launch
// ---------------------------------------------------------------------------
static const int INTRA_SMEM = (2 * 64 * 65 + 3 * 64 * 64 + 64) * 4;  // 82944 B

extern "C" void kernel_launch(void* const* d_in, const int* in_sizes, int n_in,
                              void* d_out, int out_size)
{
    const float* x      = (const float*)d_in[0];
    const float* ln1_g  = (const float*)d_in[1];
    const float* ln1_b  = (const float*)d_in[2];
    const float* w_attn = (const float*)d_in[3];
    const float* b_attn = (const float*)d_in[4];
    const float* w_feat = (const float*)d_in[5];
    const float* w_proj = (const float*)d_in[6];
    const float* b_proj = (const float*)d_in[7];
    const float* ln2_g  = (const float*)d_in[8];
    const float* ln2_b  = (const float*)d_in[9];
    const float* w_fc   = (const float*)d_in[10];
    const float* b_fc   = (const float*)d_in[11];
    const float* w_out  = (const float*)d_in[12];
    const float* b_out  = (const float*)d_in[13];
    float* out = (float*)d_out;

    float *a, *qkv, *phiq, *phik, *kv, *kvp, *ks, *ksp, *ctx, *x2, *ffn;
    cudaGetSymbolAddress((void**)&a,    g_a);
    cudaGetSymbolAddress((void**)&qkv,  g_qkv);
    cudaGetSymbolAddress((void**)&phiq, g_phiq);
    cudaGetSymbolAddress((void**)&phik, g_phik);
    cudaGetSymbolAddress((void**)&kv,   g_kv);
    cudaGetSymbolAddress((void**)&kvp,  g_kvp);
    cudaGetSymbolAddress((void**)&ks,   g_ks);
    cudaGetSymbolAddress((void**)&ksp,  g_ksp);
    cudaGetSymbolAddress((void**)&ctx,  g_ctx);
    cudaGetSymbolAddress((void**)&x2,   g_x2);
    cudaGetSymbolAddress((void**)&ffn,  g_ffn);

    cudaFuncSetAttribute(intra_kernel, cudaFuncAttributeMaxDynamicSharedMemorySize,
                         INTRA_SMEM);

    // 1. LN1
    ln_kernel<<<ROWS, 256>>>(x, ln1_g, ln1_b, a);
    // 2. qkv = a @ w_attn + b_attn
    sgemm_kernel<false, false><<<dim3(D3 / 128, ROWS / 128), 256>>>(
        a, w_attn, b_attn, nullptr, qkv, ROWS, D3, DMODEL);
    // 3. FAVOR+ features
    phi_kernel<<<dim3(1024, BH, 2), 64>>>(qkv, w_feat, phiq, phik);
    // 4. per-chunk KV states
    chunkkv_kernel<<<dim3(NCHUNK, BH), 256>>>(qkv, phik, kv, ks);
    // 5. exclusive scan over chunks
    scan_kernel<<<BH, 256>>>(kv, ks, kvp, ksp);
    // 6. intra-chunk causal combine -> ctx (merged heads)
    intra_kernel<<<dim3(NCHUNK, BH), 256, INTRA_SMEM>>>(qkv, phiq, phik, kvp, ksp, ctx);
    // 7. x2 = x + ctx @ w_proj + b_proj
    sgemm_kernel<false, true><<<dim3(DMODEL / 128, ROWS / 128), 256>>>(
        ctx, w_proj, b_proj, x, x2, ROWS, DMODEL, DMODEL);
    // 8. LN2
    ln_kernel<<<ROWS, 256>>>(x2, ln2_g, ln2_b, a);
    // 9. ffn = gelu(a @ w_fc + b_fc)
    sgemm_kernel<true, false><<<dim3(DFF / 128, ROWS / 128), 256>>>(
        a, w_fc, b_fc, nullptr, ffn, ROWS, DFF, DMODEL);
    // 10. out = x2 + ffn @ w_out + b_out
    sgemm_kernel<false, true><<<dim3(DMODEL / 128, ROWS / 128), 256>>>(
        ffn, w_out, b_out, x2, out, ROWS, DMODEL, DFF);
}

// round 2
// speedup vs baseline: 1.5366x; 1.5366x over previous
#include <cuda_runtime.h>
#include <math.h>

// ---------------------------------------------------------------------------
// B=2, S=1024, D=768, H=12, DH=64, M=64, DFF=3072, rows = 2048
// Chunked causal linear attention: 16 chunks of 64 tokens.
// Big GEMMs: tf32 mma.sync m16n8k8 on the tensor pipe.
// ---------------------------------------------------------------------------

#define ROWS   2048
#define DMODEL 768
#define D3     2304
#define DFF    3072
#define NH     12
#define BH     24
#define DH     64
#define MF     64
#define CHUNK  64
#define NCHUNK 16

__device__ float g_a   [ROWS * DMODEL];
__device__ float g_qkv [ROWS * D3];
__device__ float g_phiq[BH * 1024 * MF];
__device__ float g_phik[BH * 1024 * MF];
__device__ float g_kv  [BH * NCHUNK * MF * DH];
__device__ float g_kvp [BH * NCHUNK * MF * DH];
__device__ float g_ks  [BH * NCHUNK * MF];
__device__ float g_ksp [BH * NCHUNK * MF];
__device__ float g_ctx [ROWS * DMODEL];
__device__ float g_x2  [ROWS * DMODEL];
__device__ float g_ffn [ROWS * DFF];

// ---------------------------------------------------------------------------
// LayerNorm
// ---------------------------------------------------------------------------
__global__ void ln_kernel(const float* __restrict__ in,
                          const float* __restrict__ gamma,
                          const float* __restrict__ beta,
                          float* __restrict__ out)
{
    int row = blockIdx.x;
    int t = threadIdx.x;
    const float* p = in + (size_t)row * DMODEL;
    float v[3];
    float s = 0.f, s2 = 0.f;
#pragma unroll
    for (int i = 0; i < 3; i++) {
        v[i] = p[t + i * 256];
        s += v[i];
        s2 += v[i] * v[i];
    }
#pragma unroll
    for (int o = 16; o; o >>= 1) {
        s  += __shfl_xor_sync(0xffffffffu, s, o);
        s2 += __shfl_xor_sync(0xffffffffu, s2, o);
    }
    __shared__ float ss[8], ss2[8];
    if ((t & 31) == 0) { ss[t >> 5] = s; ss2[t >> 5] = s2; }
    __syncthreads();
    s = 0.f; s2 = 0.f;
#pragma unroll
    for (int i = 0; i < 8; i++) { s += ss[i]; s2 += ss2[i]; }
    float mu  = s * (1.f / DMODEL);
    float var = s2 * (1.f / DMODEL) - mu * mu;
    float rstd = rsqrtf(var + 1e-5f);
    float* q = out + (size_t)row * DMODEL;
#pragma unroll
    for (int i = 0; i < 3; i++) {
        int c = t + i * 256;
        q[c] = (v[i] - mu) * rstd * gamma[c] + beta[c];
    }
}

// ---------------------------------------------------------------------------
// tf32 helpers
// ---------------------------------------------------------------------------
__device__ __forceinline__ unsigned f2tf(float x) {
    unsigned r;
    asm("cvt.rna.tf32.f32 %0, %1;" : "=r"(r) : "f"(x));
    return r;
}

__device__ __forceinline__ void mma_tf32(float* d,
                                         const unsigned* a,
                                         const unsigned* b)
{
    asm volatile(
        "mma.sync.aligned.m16n8k8.row.col.f32.tf32.tf32.f32 "
        "{%0,%1,%2,%3}, {%4,%5,%6,%7}, {%8,%9}, {%0,%1,%2,%3};\n"
        : "+f"(d[0]), "+f"(d[1]), "+f"(d[2]), "+f"(d[3])
        : "r"(a[0]), "r"(a[1]), "r"(a[2]), "r"(a[3]),
          "r"(b[0]), "r"(b[1]));
}

// ---------------------------------------------------------------------------
// tf32 tensor-core GEMM: C[M,N] = A[M,K] @ B[K,N] + bias (+gelu) (+residual)
// 128x128 CTA tile, BK=16, 8 warps each 64x32 (4x4 m16n8k8 tiles).
// M,N multiples of 128; K multiple of 16.
// Smem: As[row][k] stride 20 (fragment reads bank-free),
//       Bs[k][col] stride 136 (fragment reads bank-free).
// ---------------------------------------------------------------------------
#define AST 20
#define BST 136

template <bool GELU, bool RES>
__global__ __launch_bounds__(256, 2)
void tgemm_kernel(const float* __restrict__ A, const float* __restrict__ B,
                  const float* __restrict__ bias, const float* __restrict__ res,
                  float* __restrict__ C, int M, int N, int K)
{
    __shared__ unsigned As[128 * AST];
    __shared__ unsigned Bs[16 * BST];

    int t    = threadIdx.x;
    int lane = t & 31;
    int warp = t >> 5;
    int bm = blockIdx.y * 128;
    int bn = blockIdx.x * 128;

    int wr = warp >> 2;             // 0..1
    int wc = warp & 3;              // 0..3
    int mbase = wr * 64;
    int nbase = wc * 32;
    int g   = lane >> 2;            // 0..7
    int tig = lane & 3;             // 0..3

    // Global load mapping (2 float4 each for A and B per k-tile)
    int a_row0 = t >> 2;            // 0..63   (and +64)
    int a_k4   = (t & 3) * 4;
    int b_k0   = t >> 5;            // 0..7    (and +8)
    int b_col4 = (t & 31) * 4;

    const float* Aptr = A + (size_t)(bm + a_row0) * K + a_k4;
    const float* Bptr = B + (size_t)b_k0 * N + bn + b_col4;
    size_t Arow64 = (size_t)64 * K;
    size_t Brow8  = (size_t)8 * N;

    float4 na0 = *(const float4*)(Aptr);
    float4 na1 = *(const float4*)(Aptr + Arow64);
    float4 nb0 = *(const float4*)(Bptr);
    float4 nb1 = *(const float4*)(Bptr + Brow8);

    float acc[4][4][4];
#pragma unroll
    for (int i = 0; i < 4; i++)
#pragma unroll
        for (int j = 0; j < 4; j++)
#pragma unroll
            for (int r = 0; r < 4; r++) acc[i][j][r] = 0.f;

    int nk = K >> 4;
    for (int kt = 0; kt < nk; kt++) {
        // store (converted to tf32 bits)
        {
            unsigned* pa = &As[a_row0 * AST + a_k4];
            pa[0] = f2tf(na0.x); pa[1] = f2tf(na0.y);
            pa[2] = f2tf(na0.z); pa[3] = f2tf(na0.w);
            unsigned* pa2 = &As[(a_row0 + 64) * AST + a_k4];
            pa2[0] = f2tf(na1.x); pa2[1] = f2tf(na1.y);
            pa2[2] = f2tf(na1.z); pa2[3] = f2tf(na1.w);
            unsigned* pb = &Bs[b_k0 * BST + b_col4];
            pb[0] = f2tf(nb0.x); pb[1] = f2tf(nb0.y);
            pb[2] = f2tf(nb0.z); pb[3] = f2tf(nb0.w);
            unsigned* pb2 = &Bs[(b_k0 + 8) * BST + b_col4];
            pb2[0] = f2tf(nb1.x); pb2[1] = f2tf(nb1.y);
            pb2[2] = f2tf(nb1.z); pb2[3] = f2tf(nb1.w);
        }
        __syncthreads();
        if (kt + 1 < nk) {
            const float* Ap = Aptr + (size_t)(kt + 1) * 16;
            const float* Bp = Bptr + (size_t)(kt + 1) * 16 * N;
            na0 = *(const float4*)(Ap);
            na1 = *(const float4*)(Ap + Arow64);
            nb0 = *(const float4*)(Bp);
            nb1 = *(const float4*)(Bp + Brow8);
        }

#pragma unroll
        for (int k8 = 0; k8 < 2; k8++) {
            int kb = k8 * 8;
            unsigned af[4][4], bf[4][2];
#pragma unroll
            for (int i = 0; i < 4; i++) {
                int r0 = mbase + i * 16 + g;
                af[i][0] = As[r0 * AST + kb + tig];
                af[i][1] = As[(r0 + 8) * AST + kb + tig];
                af[i][2] = As[r0 * AST + kb + tig + 4];
                af[i][3] = As[(r0 + 8) * AST + kb + tig + 4];
            }
#pragma unroll
            for (int j = 0; j < 4; j++) {
                int c0 = nbase + j * 8 + g;
                bf[j][0] = Bs[(kb + tig) * BST + c0];
                bf[j][1] = Bs[(kb + tig + 4) * BST + c0];
            }
#pragma unroll
            for (int i = 0; i < 4; i++)
#pragma unroll
                for (int j = 0; j < 4; j++)
                    mma_tf32(acc[i][j], af[i], bf[j]);
        }
        __syncthreads();
    }

    // Epilogue: d0:(g, 2*tig) d1:(g, 2*tig+1) d2:(g+8, 2*tig) d3:(g+8, 2*tig+1)
#pragma unroll
    for (int i = 0; i < 4; i++) {
#pragma unroll
        for (int j = 0; j < 4; j++) {
            int col = bn + nbase + j * 8 + 2 * tig;
            float b0 = bias[col], b1 = bias[col + 1];
#pragma unroll
            for (int half = 0; half < 2; half++) {
                int row = bm + mbase + i * 16 + g + half * 8;
                float v0 = acc[i][j][half * 2 + 0] + b0;
                float v1 = acc[i][j][half * 2 + 1] + b1;
                if (GELU) {
                    float u = v0, cu = u + 0.044715f * u * u * u;
                    v0 = 0.5f * u * (1.f + tanhf(0.7978845608028654f * cu));
                    u = v1; cu = u + 0.044715f * u * u * u;
                    v1 = 0.5f * u * (1.f + tanhf(0.7978845608028654f * cu));
                }
                if (RES) {
                    v0 += res[(size_t)row * N + col];
                    v1 += res[(size_t)row * N + col + 1];
                }
                *(float2*)&C[(size_t)row * N + col] = make_float2(v0, v1);
            }
        }
    }
}

// ---------------------------------------------------------------------------
// FAVOR+ features
// ---------------------------------------------------------------------------
__global__ void phi_kernel(const float* __restrict__ qkv,
                           const float* __restrict__ wf,
                           float* __restrict__ phiq,
                           float* __restrict__ phik)
{
    int s   = blockIdx.x;
    int bh  = blockIdx.y;
    int isk = blockIdx.z;
    int h = bh % NH, b = bh / NH;
    int t = threadIdx.x;

    __shared__ float xs[64];
    const float* src = qkv + ((size_t)(b * 1024 + s)) * D3 + isk * DMODEL + h * DH;
    xs[t] = src[t] * 0.3535533905932738f;
    __syncthreads();

    float proj = 0.f, sq = 0.f;
    const float* wrow = wf + t * DH;
#pragma unroll 16
    for (int d = 0; d < 64; d++) {
        float x = xs[d];
        proj += x * wrow[d];
        sq   += x * x;
    }
    float val = expf(proj - 0.5f * sq) * 0.125f + 1e-6f;
    float* dst = (isk ? phik : phiq);
    dst[((size_t)bh * 1024 + s) * MF + t] = val;
}

// ---------------------------------------------------------------------------
// Per-chunk KV state
// ---------------------------------------------------------------------------
__global__ void chunkkv_kernel(const float* __restrict__ qkv,
                               const float* __restrict__ phik,
                               float* __restrict__ kvs,
                               float* __restrict__ ks)
{
    int c  = blockIdx.x;
    int bh = blockIdx.y;
    int h = bh % NH, b = bh / NH;
    int t = threadIdx.x;

    __shared__ float pk[CHUNK][MF];
    __shared__ float sv[CHUNK][DH];

    for (int i = t; i < CHUNK * 64; i += 256) {
        int s = i >> 6, d = i & 63;
        pk[s][d] = phik[((size_t)bh * 1024 + c * CHUNK + s) * MF + d];
        sv[s][d] = qkv[((size_t)(b * 1024 + c * CHUNK + s)) * D3 + 2 * DMODEL + h * DH + d];
    }
    __syncthreads();

    int m  = t & 63;
    int db = (t >> 6) * 16;
    float acc[16];
#pragma unroll
    for (int j = 0; j < 16; j++) acc[j] = 0.f;
    float sksum = 0.f;

    for (int s = 0; s < CHUNK; s++) {
        float pkm = pk[s][m];
        if (db == 0) sksum += pkm;
#pragma unroll
        for (int j = 0; j < 16; j++) acc[j] += pkm * sv[s][db + j];
    }
    float* dst = kvs + ((size_t)bh * NCHUNK + c) * (MF * DH) + m * DH + db;
#pragma unroll
    for (int j = 0; j < 16; j++) dst[j] = acc[j];
    if (db == 0) ks[((size_t)bh * NCHUNK + c) * MF + m] = sksum;
}

// ---------------------------------------------------------------------------
// Exclusive prefix over chunk states
// ---------------------------------------------------------------------------
__global__ void scan_kernel(const float* __restrict__ kvs,
                            const float* __restrict__ ks,
                            float* __restrict__ kvp,
                            float* __restrict__ ksp)
{
    int bh = blockIdx.x;
    int t = threadIdx.x;
    float acc[16];
#pragma unroll
    for (int r = 0; r < 16; r++) acc[r] = 0.f;
    float accs = 0.f;

    for (int c = 0; c < NCHUNK; c++) {
        size_t base = ((size_t)bh * NCHUNK + c) * (MF * DH);
#pragma unroll
        for (int r = 0; r < 16; r++) {
            int idx = t + r * 256;
            float v = kvs[base + idx];
            kvp[base + idx] = acc[r];
            acc[r] += v;
        }
        if (t < MF) {
            size_t kb = ((size_t)bh * NCHUNK + c) * MF + t;
            float v = ks[kb];
            ksp[kb] = accs;
            accs += v;
        }
    }
}

// ---------------------------------------------------------------------------
// Intra-chunk causal combine
// ---------------------------------------------------------------------------
__global__ __launch_bounds__(256, 2)
void intra_kernel(const float* __restrict__ qkv,
                  const float* __restrict__ phiq,
                  const float* __restrict__ phik,
                  const float* __restrict__ kvpre,
                  const float* __restrict__ kspre,
                  float* __restrict__ ctx)
{
    extern __shared__ float sm[];
    float (*pq)[65]  = (float(*)[65])sm;
    float (*pk)[64]  = (float(*)[64])(sm + 64 * 65);
    float (*sA)[65]  = (float(*)[65])(sm + 64 * 65 + 64 * 64);
    float (*sv)[64]  = (float(*)[64])(sm + 2 * 64 * 65 + 64 * 64);
    float (*skv)[64] = (float(*)[64])(sm + 2 * 64 * 65 + 2 * 64 * 64);
    float* sks       = sm + 2 * 64 * 65 + 3 * 64 * 64;

    int c  = blockIdx.x;
    int bh = blockIdx.y;
    int h = bh % NH, b = bh / NH;
    int t = threadIdx.x;
    size_t kvbase = ((size_t)bh * NCHUNK + c) * (MF * DH);

    for (int i = t; i < 64 * 64; i += 256) {
        int s = i >> 6, d = i & 63;
        size_t prow = ((size_t)bh * 1024 + c * CHUNK + s) * MF + d;
        pq[s][d] = phiq[prow];
        pk[s][d] = phik[prow];
        sv[s][d] = qkv[((size_t)(b * 1024 + c * CHUNK + s)) * D3 + 2 * DMODEL + h * DH + d];
        skv[s][d] = kvpre[kvbase + i];
    }
    if (t < MF) sks[t] = kspre[((size_t)bh * NCHUNK + c) * MF + t];
    __syncthreads();

    int i  = t & 63;
    int jb = (t >> 6) * 16;

    float a[16];
#pragma unroll
    for (int jj = 0; jj < 16; jj++) a[jj] = 0.f;
    for (int m = 0; m < MF; m++) {
        float pqv = pq[i][m];
#pragma unroll
        for (int jj = 0; jj < 16; jj++) a[jj] += pqv * pk[jb + jj][m];
    }
#pragma unroll
    for (int jj = 0; jj < 16; jj++) sA[i][jb + jj] = (jb + jj <= i) ? a[jj] : 0.f;
    __syncthreads();

    int db = jb;
    float num[16];
#pragma unroll
    for (int dd = 0; dd < 16; dd++) num[dd] = 0.f;
    float den = 0.f;

    for (int j = 0; j < CHUNK; j++) {
        float av = sA[i][j];
        den += av;
#pragma unroll
        for (int dd = 0; dd < 16; dd++) num[dd] += av * sv[j][db + dd];
    }
    for (int m = 0; m < MF; m++) {
        float pqv = pq[i][m];
        den += pqv * sks[m];
#pragma unroll
        for (int dd = 0; dd < 16; dd++) num[dd] += pqv * skv[m][db + dd];
    }

    float inv = 1.f / den;
    float* dst = ctx + ((size_t)(b * 1024 + c * CHUNK + i)) * DMODEL + h * DH + db;
#pragma unroll
    for (int dd = 0; dd < 16; dd++) dst[dd] = num[dd] * inv;
}

// ---------------------------------------------------------------------------
static const int INTRA_SMEM = (2 * 64 * 65 + 3 * 64 * 64 + 64) * 4;

extern "C" void kernel_launch(void* const* d_in, const int* in_sizes, int n_in,
                              void* d_out, int out_size)
{
    const float* x      = (const float*)d_in[0];
    const float* ln1_g  = (const float*)d_in[1];
    const float* ln1_b  = (const float*)d_in[2];
    const float* w_attn = (const float*)d_in[3];
    const float* b_attn = (const float*)d_in[4];
    const float* w_feat = (const float*)d_in[5];
    const float* w_proj = (const float*)d_in[6];
    const float* b_proj = (const float*)d_in[7];
    const float* ln2_g  = (const float*)d_in[8];
    const float* ln2_b  = (const float*)d_in[9];
    const float* w_fc   = (const float*)d_in[10];
    const float* b_fc   = (const float*)d_in[11];
    const float* w_out  = (const float*)d_in[12];
    const float* b_out  = (const float*)d_in[13];
    float* out = (float*)d_out;

    float *a, *qkv, *phiq, *phik, *kv, *kvp, *ks, *ksp, *ctx, *x2, *ffn;
    cudaGetSymbolAddress((void**)&a,    g_a);
    cudaGetSymbolAddress((void**)&qkv,  g_qkv);
    cudaGetSymbolAddress((void**)&phiq, g_phiq);
    cudaGetSymbolAddress((void**)&phik, g_phik);
    cudaGetSymbolAddress((void**)&kv,   g_kv);
    cudaGetSymbolAddress((void**)&kvp,  g_kvp);
    cudaGetSymbolAddress((void**)&ks,   g_ks);
    cudaGetSymbolAddress((void**)&ksp,  g_ksp);
    cudaGetSymbolAddress((void**)&ctx,  g_ctx);
    cudaGetSymbolAddress((void**)&x2,   g_x2);
    cudaGetSymbolAddress((void**)&ffn,  g_ffn);

    cudaFuncSetAttribute(intra_kernel, cudaFuncAttributeMaxDynamicSharedMemorySize,
                         INTRA_SMEM);

    ln_kernel<<<ROWS, 256>>>(x, ln1_g, ln1_b, a);
    tgemm_kernel<false, false><<<dim3(D3 / 128, ROWS / 128), 256>>>(
        a, w_attn, b_attn, nullptr, qkv, ROWS, D3, DMODEL);
    phi_kernel<<<dim3(1024, BH, 2), 64>>>(qkv, w_feat, phiq, phik);
    chunkkv_kernel<<<dim3(NCHUNK, BH), 256>>>(qkv, phik, kv, ks);
    scan_kernel<<<BH, 256>>>(kv, ks, kvp, ksp);
    intra_kernel<<<dim3(NCHUNK, BH), 256, INTRA_SMEM>>>(qkv, phiq, phik, kvp, ksp, ctx);
    tgemm_kernel<false, true><<<dim3(DMODEL / 128, ROWS / 128), 256>>>(
        ctx, w_proj, b_proj, x, x2, ROWS, DMODEL, DMODEL);
    ln_kernel<<<ROWS, 256>>>(x2, ln2_g, ln2_b, a);
    tgemm_kernel<true, false><<<dim3(DFF / 128, ROWS / 128), 256>>>(
        a, w_fc, b_fc, nullptr, ffn, ROWS, DFF, DMODEL);
    tgemm_kernel<false, true><<<dim3(DMODEL / 128, ROWS / 128), 256>>>(
        ffn, w_out, b_out, x2, out, ROWS, DMODEL, DFF);
}

// round 3
// speedup vs baseline: 1.6048x; 1.0444x over previous
#include <cuda_runtime.h>
#include <math.h>

// ---------------------------------------------------------------------------
// B=2, S=1024, D=768, H=12, DH=64, M=64, DFF=3072, rows = 2048
// tf32 mma.sync GEMMs with cp.async double-buffered pipeline.
// ---------------------------------------------------------------------------

#define ROWS   2048
#define DMODEL 768
#define D3     2304
#define DFF    3072
#define NH     12
#define BH     24
#define DH     64
#define MF     64
#define CHUNK  64
#define NCHUNK 16

__device__ float g_a   [ROWS * DMODEL];
__device__ float g_qkv [ROWS * D3];
__device__ float g_phiq[BH * 1024 * MF];
__device__ float g_phik[BH * 1024 * MF];
__device__ float g_kv  [BH * NCHUNK * MF * DH];
__device__ float g_kvp [BH * NCHUNK * MF * DH];
__device__ float g_ks  [BH * NCHUNK * MF];
__device__ float g_ksp [BH * NCHUNK * MF];
__device__ float g_ctx [ROWS * DMODEL];
__device__ float g_x2  [ROWS * DMODEL];
__device__ float g_ffn [ROWS * DFF];

// ---------------------------------------------------------------------------
// LayerNorm
// ---------------------------------------------------------------------------
__global__ void ln_kernel(const float* __restrict__ in,
                          const float* __restrict__ gamma,
                          const float* __restrict__ beta,
                          float* __restrict__ out)
{
    int row = blockIdx.x;
    int t = threadIdx.x;
    const float* p = in + (size_t)row * DMODEL;
    float v[3];
    float s = 0.f, s2 = 0.f;
#pragma unroll
    for (int i = 0; i < 3; i++) {
        v[i] = p[t + i * 256];
        s += v[i];
        s2 += v[i] * v[i];
    }
#pragma unroll
    for (int o = 16; o; o >>= 1) {
        s  += __shfl_xor_sync(0xffffffffu, s, o);
        s2 += __shfl_xor_sync(0xffffffffu, s2, o);
    }
    __shared__ float ss[8], ss2[8];
    if ((t & 31) == 0) { ss[t >> 5] = s; ss2[t >> 5] = s2; }
    __syncthreads();
    s = 0.f; s2 = 0.f;
#pragma unroll
    for (int i = 0; i < 8; i++) { s += ss[i]; s2 += ss2[i]; }
    float mu  = s * (1.f / DMODEL);
    float var = s2 * (1.f / DMODEL) - mu * mu;
    float rstd = rsqrtf(var + 1e-5f);
    float* q = out + (size_t)row * DMODEL;
#pragma unroll
    for (int i = 0; i < 3; i++) {
        int c = t + i * 256;
        q[c] = (v[i] - mu) * rstd * gamma[c] + beta[c];
    }
}

// ---------------------------------------------------------------------------
// async copy helpers
// ---------------------------------------------------------------------------
__device__ __forceinline__ void cp_async16(void* smem_dst, const void* gmem_src) {
    unsigned saddr = (unsigned)__cvta_generic_to_shared(smem_dst);
    asm volatile("cp.async.cg.shared.global [%0], [%1], 16;\n"
                 :: "r"(saddr), "l"(gmem_src));
}
__device__ __forceinline__ void cp_commit() {
    asm volatile("cp.async.commit_group;\n");
}
template <int N>
__device__ __forceinline__ void cp_wait() {
    asm volatile("cp.async.wait_group %0;\n" :: "n"(N));
}

__device__ __forceinline__ void mma_tf32(float* d,
                                         const unsigned* a,
                                         const unsigned* b)
{
    asm volatile(
        "mma.sync.aligned.m16n8k8.row.col.f32.tf32.tf32.f32 "
        "{%0,%1,%2,%3}, {%4,%5,%6,%7}, {%8,%9}, {%0,%1,%2,%3};\n"
        : "+f"(d[0]), "+f"(d[1]), "+f"(d[2]), "+f"(d[3])
        : "r"(a[0]), "r"(a[1]), "r"(a[2]), "r"(a[3]),
          "r"(b[0]), "r"(b[1]));
}

// ---------------------------------------------------------------------------
// tf32 tensor-core GEMM, 2-stage cp.async pipeline.
// 128x128 CTA tile, BK=16, 8 warps each 64x32 (4x4 m16n8k8).
// fp32 operands are fed directly to HMMA.TF32 (hardware truncates mantissa).
// ---------------------------------------------------------------------------
#define AST 20
#define BST 136

template <bool GELU, bool RES>
__global__ __launch_bounds__(256, 2)
void tgemm_kernel(const float* __restrict__ A, const float* __restrict__ B,
                  const float* __restrict__ bias, const float* __restrict__ res,
                  float* __restrict__ C, int M, int N, int K)
{
    __shared__ float As[2][128 * AST];
    __shared__ float Bs[2][16 * BST];

    int t    = threadIdx.x;
    int lane = t & 31;
    int warp = t >> 5;
    int bm = blockIdx.y * 128;
    int bn = blockIdx.x * 128;

    int wr = warp >> 2;
    int wc = warp & 3;
    int mbase = wr * 64;
    int nbase = wc * 32;
    int g   = lane >> 2;
    int tig = lane & 3;

    int a_row0 = t >> 2;            // 0..63 (and +64)
    int a_k4   = (t & 3) * 4;
    int b_k0   = t >> 5;            // 0..7 (and +8)
    int b_col4 = (t & 31) * 4;

    const float* Abase = A + (size_t)(bm + a_row0) * K + a_k4;
    const float* Bbase = B + (size_t)b_k0 * N + bn + b_col4;
    size_t Arow64 = (size_t)64 * K;
    size_t Brow8  = (size_t)8 * N;

    int nk = K >> 4;

    // stage issue
    auto issue = [&](int kt, int s) {
        const float* Ap = Abase + (size_t)kt * 16;
        cp_async16(&As[s][a_row0 * AST + a_k4], Ap);
        cp_async16(&As[s][(a_row0 + 64) * AST + a_k4], Ap + Arow64);
        const float* Bp = Bbase + (size_t)kt * 16 * N;
        cp_async16(&Bs[s][b_k0 * BST + b_col4], Bp);
        cp_async16(&Bs[s][(b_k0 + 8) * BST + b_col4], Bp + Brow8);
        cp_commit();
    };

    issue(0, 0);
    issue(1, 1);

    float acc[4][4][4];
#pragma unroll
    for (int i = 0; i < 4; i++)
#pragma unroll
        for (int j = 0; j < 4; j++)
#pragma unroll
            for (int r = 0; r < 4; r++) acc[i][j][r] = 0.f;

    for (int kt = 0; kt < nk; kt++) {
        cp_wait<1>();
        __syncthreads();
        int s = kt & 1;
        const float* AsS = As[s];
        const float* BsS = Bs[s];

#pragma unroll
        for (int k8 = 0; k8 < 2; k8++) {
            int kb = k8 * 8;
            unsigned af[4][4], bf[4][2];
#pragma unroll
            for (int i = 0; i < 4; i++) {
                int r0 = mbase + i * 16 + g;
                af[i][0] = __float_as_uint(AsS[r0 * AST + kb + tig]);
                af[i][1] = __float_as_uint(AsS[(r0 + 8) * AST + kb + tig]);
                af[i][2] = __float_as_uint(AsS[r0 * AST + kb + tig + 4]);
                af[i][3] = __float_as_uint(AsS[(r0 + 8) * AST + kb + tig + 4]);
            }
#pragma unroll
            for (int j = 0; j < 4; j++) {
                int c0 = nbase + j * 8 + g;
                bf[j][0] = __float_as_uint(BsS[(kb + tig) * BST + c0]);
                bf[j][1] = __float_as_uint(BsS[(kb + tig + 4) * BST + c0]);
            }
#pragma unroll
            for (int i = 0; i < 4; i++)
#pragma unroll
                for (int j = 0; j < 4; j++)
                    mma_tf32(acc[i][j], af[i], bf[j]);
        }
        __syncthreads();
        if (kt + 2 < nk) issue(kt + 2, s);
        else cp_commit();   // empty group keeps wait_group arithmetic uniform
    }

    // Epilogue
#pragma unroll
    for (int i = 0; i < 4; i++) {
#pragma unroll
        for (int j = 0; j < 4; j++) {
            int col = bn + nbase + j * 8 + 2 * tig;
            float b0 = bias[col], b1 = bias[col + 1];
#pragma unroll
            for (int half = 0; half < 2; half++) {
                int row = bm + mbase + i * 16 + g + half * 8;
                float v0 = acc[i][j][half * 2 + 0] + b0;
                float v1 = acc[i][j][half * 2 + 1] + b1;
                if (GELU) {
                    float u = v0, cu = u + 0.044715f * u * u * u;
                    v0 = 0.5f * u * (1.f + tanhf(0.7978845608028654f * cu));
                    u = v1; cu = u + 0.044715f * u * u * u;
                    v1 = 0.5f * u * (1.f + tanhf(0.7978845608028654f * cu));
                }
                if (RES) {
                    v0 += res[(size_t)row * N + col];
                    v1 += res[(size_t)row * N + col + 1];
                }
                *(float2*)&C[(size_t)row * N + col] = make_float2(v0, v1);
            }
        }
    }
}

// ---------------------------------------------------------------------------
// FAVOR+ features
// ---------------------------------------------------------------------------
__global__ void phi_kernel(const float* __restrict__ qkv,
                           const float* __restrict__ wf,
                           float* __restrict__ phiq,
                           float* __restrict__ phik)
{
    int s   = blockIdx.x;
    int bh  = blockIdx.y;
    int isk = blockIdx.z;
    int h = bh % NH, b = bh / NH;
    int t = threadIdx.x;

    __shared__ float xs[64];
    const float* src = qkv + ((size_t)(b * 1024 + s)) * D3 + isk * DMODEL + h * DH;
    xs[t] = src[t] * 0.3535533905932738f;
    __syncthreads();

    float proj = 0.f, sq = 0.f;
    const float* wrow = wf + t * DH;
#pragma unroll 16
    for (int d = 0; d < 64; d++) {
        float x = xs[d];
        proj += x * wrow[d];
        sq   += x * x;
    }
    float val = expf(proj - 0.5f * sq) * 0.125f + 1e-6f;
    float* dst = (isk ? phik : phiq);
    dst[((size_t)bh * 1024 + s) * MF + t] = val;
}

// ---------------------------------------------------------------------------
// Per-chunk KV state
// ---------------------------------------------------------------------------
__global__ void chunkkv_kernel(const float* __restrict__ qkv,
                               const float* __restrict__ phik,
                               float* __restrict__ kvs,
                               float* __restrict__ ks)
{
    int c  = blockIdx.x;
    int bh = blockIdx.y;
    int h = bh % NH, b = bh / NH;
    int t = threadIdx.x;

    __shared__ float pk[CHUNK][MF];
    __shared__ float sv[CHUNK][DH];

    for (int i = t; i < CHUNK * 64; i += 256) {
        int s = i >> 6, d = i & 63;
        pk[s][d] = phik[((size_t)bh * 1024 + c * CHUNK + s) * MF + d];
        sv[s][d] = qkv[((size_t)(b * 1024 + c * CHUNK + s)) * D3 + 2 * DMODEL + h * DH + d];
    }
    __syncthreads();

    int m  = t & 63;
    int db = (t >> 6) * 16;
    float acc[16];
#pragma unroll
    for (int j = 0; j < 16; j++) acc[j] = 0.f;
    float sksum = 0.f;

    for (int s = 0; s < CHUNK; s++) {
        float pkm = pk[s][m];
        if (db == 0) sksum += pkm;
#pragma unroll
        for (int j = 0; j < 16; j++) acc[j] += pkm * sv[s][db + j];
    }
    float* dst = kvs + ((size_t)bh * NCHUNK + c) * (MF * DH) + m * DH + db;
#pragma unroll
    for (int j = 0; j < 16; j++) dst[j] = acc[j];
    if (db == 0) ks[((size_t)bh * NCHUNK + c) * MF + m] = sksum;
}

// ---------------------------------------------------------------------------
// Exclusive prefix over chunk states
// ---------------------------------------------------------------------------
__global__ void scan_kernel(const float* __restrict__ kvs,
                            const float* __restrict__ ks,
                            float* __restrict__ kvp,
                            float* __restrict__ ksp)
{
    int bh = blockIdx.x;
    int t = threadIdx.x;
    float acc[16];
#pragma unroll
    for (int r = 0; r < 16; r++) acc[r] = 0.f;
    float accs = 0.f;

    for (int c = 0; c < NCHUNK; c++) {
        size_t base = ((size_t)bh * NCHUNK + c) * (MF * DH);
#pragma unroll
        for (int r = 0; r < 16; r++) {
            int idx = t + r * 256;
            float v = kvs[base + idx];
            kvp[base + idx] = acc[r];
            acc[r] += v;
        }
        if (t < MF) {
            size_t kb = ((size_t)bh * NCHUNK + c) * MF + t;
            float v = ks[kb];
            ksp[kb] = accs;
            accs += v;
        }
    }
}

// ---------------------------------------------------------------------------
// Intra-chunk causal combine
// ---------------------------------------------------------------------------
__global__ __launch_bounds__(256, 2)
void intra_kernel(const float* __restrict__ qkv,
                  const float* __restrict__ phiq,
                  const float* __restrict__ phik,
                  const float* __restrict__ kvpre,
                  const float* __restrict__ kspre,
                  float* __restrict__ ctx)
{
    extern __shared__ float sm[];
    float (*pq)[65]  = (float(*)[65])sm;
    float (*pk)[64]  = (float(*)[64])(sm + 64 * 65);
    float (*sA)[65]  = (float(*)[65])(sm + 64 * 65 + 64 * 64);
    float (*sv)[64]  = (float(*)[64])(sm + 2 * 64 * 65 + 64 * 64);
    float (*skv)[64] = (float(*)[64])(sm + 2 * 64 * 65 + 2 * 64 * 64);
    float* sks       = sm + 2 * 64 * 65 + 3 * 64 * 64;

    int c  = blockIdx.x;
    int bh = blockIdx.y;
    int h = bh % NH, b = bh / NH;
    int t = threadIdx.x;
    size_t kvbase = ((size_t)bh * NCHUNK + c) * (MF * DH);

    for (int i = t; i < 64 * 64; i += 256) {
        int s = i >> 6, d = i & 63;
        size_t prow = ((size_t)bh * 1024 + c * CHUNK + s) * MF + d;
        pq[s][d] = phiq[prow];
        pk[s][d] = phik[prow];
        sv[s][d] = qkv[((size_t)(b * 1024 + c * CHUNK + s)) * D3 + 2 * DMODEL + h * DH + d];
        skv[s][d] = kvpre[kvbase + i];
    }
    if (t < MF) sks[t] = kspre[((size_t)bh * NCHUNK + c) * MF + t];
    __syncthreads();

    int i  = t & 63;
    int jb = (t >> 6) * 16;

    float a[16];
#pragma unroll
    for (int jj = 0; jj < 16; jj++) a[jj] = 0.f;
    for (int m = 0; m < MF; m++) {
        float pqv = pq[i][m];
#pragma unroll
        for (int jj = 0; jj < 16; jj++) a[jj] += pqv * pk[jb + jj][m];
    }
#pragma unroll
    for (int jj = 0; jj < 16; jj++) sA[i][jb + jj] = (jb + jj <= i) ? a[jj] : 0.f;
    __syncthreads();

    int db = jb;
    float num[16];
#pragma unroll
    for (int dd = 0; dd < 16; dd++) num[dd] = 0.f;
    float den = 0.f;

    for (int j = 0; j < CHUNK; j++) {
        float av = sA[i][j];
        den += av;
#pragma unroll
        for (int dd = 0; dd < 16; dd++) num[dd] += av * sv[j][db + dd];
    }
    for (int m = 0; m < MF; m++) {
        float pqv = pq[i][m];
        den += pqv * sks[m];
#pragma unroll
        for (int dd = 0; dd < 16; dd++) num[dd] += pqv * skv[m][db + dd];
    }

    float inv = 1.f / den;
    float* dst = ctx + ((size_t)(b * 1024 + c * CHUNK + i)) * DMODEL + h * DH + db;
#pragma unroll
    for (int dd = 0; dd < 16; dd++) dst[dd] = num[dd] * inv;
}

// ---------------------------------------------------------------------------
static const int INTRA_SMEM = (2 * 64 * 65 + 3 * 64 * 64 + 64) * 4;

extern "C" void kernel_launch(void* const* d_in, const int* in_sizes, int n_in,
                              void* d_out, int out_size)
{
    const float* x      = (const float*)d_in[0];
    const float* ln1_g  = (const float*)d_in[1];
    const float* ln1_b  = (const float*)d_in[2];
    const float* w_attn = (const float*)d_in[3];
    const float* b_attn = (const float*)d_in[4];
    const float* w_feat = (const float*)d_in[5];
    const float* w_proj = (const float*)d_in[6];
    const float* b_proj = (const float*)d_in[7];
    const float* ln2_g  = (const float*)d_in[8];
    const float* ln2_b  = (const float*)d_in[9];
    const float* w_fc   = (const float*)d_in[10];
    const float* b_fc   = (const float*)d_in[11];
    const float* w_out  = (const float*)d_in[12];
    const float* b_out  = (const float*)d_in[13];
    float* out = (float*)d_out;

    float *a, *qkv, *phiq, *phik, *kv, *kvp, *ks, *ksp, *ctx, *x2, *ffn;
    cudaGetSymbolAddress((void**)&a,    g_a);
    cudaGetSymbolAddress((void**)&qkv,  g_qkv);
    cudaGetSymbolAddress((void**)&phiq, g_phiq);
    cudaGetSymbolAddress((void**)&phik, g_phik);
    cudaGetSymbolAddress((void**)&kv,   g_kv);
    cudaGetSymbolAddress((void**)&kvp,  g_kvp);
    cudaGetSymbolAddress((void**)&ks,   g_ks);
    cudaGetSymbolAddress((void**)&ksp,  g_ksp);
    cudaGetSymbolAddress((void**)&ctx,  g_ctx);
    cudaGetSymbolAddress((void**)&x2,   g_x2);
    cudaGetSymbolAddress((void**)&ffn,  g_ffn);

    cudaFuncSetAttribute(intra_kernel, cudaFuncAttributeMaxDynamicSharedMemorySize,
                         INTRA_SMEM);

    ln_kernel<<<ROWS, 256>>>(x, ln1_g, ln1_b, a);
    tgemm_kernel<false, false><<<dim3(D3 / 128, ROWS / 128), 256>>>(
        a, w_attn, b_attn, nullptr, qkv, ROWS, D3, DMODEL);
    phi_kernel<<<dim3(1024, BH, 2), 64>>>(qkv, w_feat, phiq, phik);
    chunkkv_kernel<<<dim3(NCHUNK, BH), 256>>>(qkv, phik, kv, ks);
    scan_kernel<<<BH, 256>>>(kv, ks, kvp, ksp);
    intra_kernel<<<dim3(NCHUNK, BH), 256, INTRA_SMEM>>>(qkv, phiq, phik, kvp, ksp, ctx);
    tgemm_kernel<false, true><<<dim3(DMODEL / 128, ROWS / 128), 256>>>(
        ctx, w_proj, b_proj, x, x2, ROWS, DMODEL, DMODEL);
    ln_kernel<<<ROWS, 256>>>(x2, ln2_g, ln2_b, a);
    tgemm_kernel<true, false><<<dim3(DFF / 128, ROWS / 128), 256>>>(
        a, w_fc, b_fc, nullptr, ffn, ROWS, DFF, DMODEL);
    tgemm_kernel<false, true><<<dim3(DMODEL / 128, ROWS / 128), 256>>>(
        ffn, w_out, b_out, x2, out, ROWS, DMODEL, DFF);
}

// round 6
// speedup vs baseline: 1.7577x; 1.0953x over previous
#include <cuda_runtime.h>
#include <cuda_fp16.h>
#include <math.h>
#include <stdint.h>

// ---------------------------------------------------------------------------
// B=2, S=1024, D=768, H=12, DH=64, M=64, DFF=3072, rows = 2048
// Big GEMMs: fp16 mma.sync m16n8k16 (fp32 accum) + ldmatrix + cp.async.
// ---------------------------------------------------------------------------

#define ROWS   2048
#define DMODEL 768
#define D3     2304
#define DFF    3072
#define NH     12
#define BH     24
#define DH     64
#define MF     64
#define CHUNK  64
#define NCHUNK 16

__device__ float  g_qkv [ROWS * D3];
__device__ float  g_phiq[BH * 1024 * MF];
__device__ float  g_phik[BH * 1024 * MF];
__device__ float  g_kv  [BH * NCHUNK * MF * DH];
__device__ float  g_kvp [BH * NCHUNK * MF * DH];
__device__ float  g_ks  [BH * NCHUNK * MF];
__device__ float  g_ksp [BH * NCHUNK * MF];
__device__ float  g_x2  [ROWS * DMODEL];
// half operand buffers
__device__ __half g_ah  [ROWS * DMODEL];     // ln1/ln2 out
__device__ __half g_ctxh[ROWS * DMODEL];
__device__ __half g_ffnh[ROWS * DFF];
__device__ __half g_wAT [D3 * DMODEL];       // [N,K] transposed weights
__device__ __half g_wPT [DMODEL * DMODEL];
__device__ __half g_wFT [DFF * DMODEL];
__device__ __half g_wOT [DMODEL * DFF];

// ---------------------------------------------------------------------------
// helpers
// ---------------------------------------------------------------------------
__device__ __forceinline__ void cp_async16s(unsigned saddr, const void* gsrc) {
    asm volatile("cp.async.cg.shared.global [%0], [%1], 16;\n"
                 :: "r"(saddr), "l"(gsrc));
}
__device__ __forceinline__ void cp_commit() {
    asm volatile("cp.async.commit_group;\n");
}
template <int N>
__device__ __forceinline__ void cp_wait() {
    asm volatile("cp.async.wait_group %0;\n" :: "n"(N));
}

__device__ __forceinline__ void ldsm_x4(unsigned& r0, unsigned& r1,
                                        unsigned& r2, unsigned& r3,
                                        unsigned addr) {
    asm volatile("ldmatrix.sync.aligned.m8n8.x4.shared.b16 {%0,%1,%2,%3}, [%4];"
                 : "=r"(r0), "=r"(r1), "=r"(r2), "=r"(r3) : "r"(addr));
}

__device__ __forceinline__ void mma_f16(float* d, const unsigned* a,
                                        unsigned b0, unsigned b1) {
    asm volatile(
        "mma.sync.aligned.m16n8k16.row.col.f32.f16.f16.f32 "
        "{%0,%1,%2,%3}, {%4,%5,%6,%7}, {%8,%9}, {%0,%1,%2,%3};\n"
        : "+f"(d[0]), "+f"(d[1]), "+f"(d[2]), "+f"(d[3])
        : "r"(a[0]), "r"(a[1]), "r"(a[2]), "r"(a[3]), "r"(b0), "r"(b1));
}

// ---------------------------------------------------------------------------
// fp16 GEMM: C[M,N(=Ncols)] = A[M,K]@Bw^T + bias (+gelu) (+res)
// A half [M,K] row-major, Bw half [N,K] row-major (K-major for B operand).
// CTA 128x128, BK=32, 256 threads (8 warps, 64x32 each), 2-stage cp.async.
// Smem rows padded to 40 halves (80B) -> conflict-free cp.async + ldmatrix.
// ---------------------------------------------------------------------------
#define HST 40          // halves per smem row
#define STAGE_B 10240   // bytes per stage (128 * 80)

template <bool GELU, bool RES, bool HOUT>
__global__ __launch_bounds__(256, 2)
void hgemm(const __half* __restrict__ A, const __half* __restrict__ Bw,
           const float* __restrict__ bias, const float* __restrict__ res,
           float* __restrict__ Cf, __half* __restrict__ Ch, int N, int K)
{
    __shared__ __half As[2][128 * HST];
    __shared__ __half Bs[2][128 * HST];
    unsigned asb = (unsigned)__cvta_generic_to_shared(&As[0][0]);
    unsigned bsb = (unsigned)__cvta_generic_to_shared(&Bs[0][0]);

    int t    = threadIdx.x;
    int lane = t & 31;
    int warp = t >> 5;
    int bm = blockIdx.y * 128;
    int bn = blockIdx.x * 128;
    int mbase = (warp >> 2) * 64;
    int nbase = (warp & 3) * 32;
    int g   = lane >> 2;
    int tig = lane & 3;

    const __half* Ag0 = A + (size_t)bm * K;
    const __half* Bg0 = Bw + (size_t)bn * K;

    int ld_row = t >> 1;            // 0..127
    int ld_c   = (t & 1) * 2;       // chunk pairs: c in {0,1} and {2,3}

    auto load_tile = [&](int kt, int s) {
        const __half* Ag = Ag0 + (size_t)kt * 32;
        const __half* Bg = Bg0 + (size_t)kt * 32;
        unsigned arow = asb + s * STAGE_B + ld_row * 80;
        unsigned brow = bsb + s * STAGE_B + ld_row * 80;
        cp_async16s(arow + ld_c * 16,       Ag + (size_t)ld_row * K + ld_c * 8);
        cp_async16s(arow + (ld_c + 1) * 16, Ag + (size_t)ld_row * K + (ld_c + 1) * 8);
        cp_async16s(brow + ld_c * 16,       Bg + (size_t)ld_row * K + ld_c * 8);
        cp_async16s(brow + (ld_c + 1) * 16, Bg + (size_t)ld_row * K + (ld_c + 1) * 8);
        cp_commit();
    };

    int nk = K >> 5;
    load_tile(0, 0);
    load_tile(1, 1);

    float acc[4][4][4];
#pragma unroll
    for (int i = 0; i < 4; i++)
#pragma unroll
        for (int j = 0; j < 4; j++)
#pragma unroll
            for (int r = 0; r < 4; r++) acc[i][j][r] = 0.f;

    // ldmatrix address components (constant across kt)
    int a_r  = lane & 15;           // row within 16-row m-tile
    int a_kh = (lane >> 4) * 8;     // k offset 0/8
    int b_mi = lane >> 3;           // matrix index 0..3
    int b_n  = ((b_mi >> 1) << 3) + (lane & 7);
    int b_kh = (b_mi & 1) * 8;

    for (int kt = 0; kt < nk; kt++) {
        cp_wait<1>();
        __syncthreads();
        int s = kt & 1;
        unsigned as_s = asb + s * STAGE_B;
        unsigned bs_s = bsb + s * STAGE_B;

#pragma unroll
        for (int ks = 0; ks < 2; ks++) {
            int kb = ks * 16;
            unsigned af[4][4], bfA[4], bfB[4];
#pragma unroll
            for (int i = 0; i < 4; i++) {
                unsigned addr = as_s + (mbase + i * 16 + a_r) * 80
                              + (kb + a_kh) * 2;
                ldsm_x4(af[i][0], af[i][1], af[i][2], af[i][3], addr);
            }
            {
                unsigned addr0 = bs_s + (nbase + b_n) * 80 + (kb + b_kh) * 2;
                ldsm_x4(bfA[0], bfA[1], bfA[2], bfA[3], addr0);
                unsigned addr1 = bs_s + (nbase + 16 + b_n) * 80 + (kb + b_kh) * 2;
                ldsm_x4(bfB[0], bfB[1], bfB[2], bfB[3], addr1);
            }
#pragma unroll
            for (int i = 0; i < 4; i++) {
                mma_f16(acc[i][0], af[i], bfA[0], bfA[1]);
                mma_f16(acc[i][1], af[i], bfA[2], bfA[3]);
                mma_f16(acc[i][2], af[i], bfB[0], bfB[1]);
                mma_f16(acc[i][3], af[i], bfB[2], bfB[3]);
            }
        }
        __syncthreads();
        if (kt + 2 < nk) load_tile(kt + 2, s);
        else cp_commit();
    }

    // Epilogue
#pragma unroll
    for (int i = 0; i < 4; i++) {
#pragma unroll
        for (int j = 0; j < 4; j++) {
            int col = bn + nbase + j * 8 + 2 * tig;
            float b0 = bias[col], b1 = bias[col + 1];
#pragma unroll
            for (int half = 0; half < 2; half++) {
                int row = bm + mbase + i * 16 + g + half * 8;
                float v0 = acc[i][j][half * 2 + 0] + b0;
                float v1 = acc[i][j][half * 2 + 1] + b1;
                if (GELU) {
                    float u = v0, cu = u + 0.044715f * u * u * u;
                    v0 = 0.5f * u * (1.f + tanhf(0.7978845608028654f * cu));
                    u = v1; cu = u + 0.044715f * u * u * u;
                    v1 = 0.5f * u * (1.f + tanhf(0.7978845608028654f * cu));
                }
                if (RES) {
                    v0 += res[(size_t)row * N + col];
                    v1 += res[(size_t)row * N + col + 1];
                }
                if (HOUT) {
                    *(__half2*)&Ch[(size_t)row * N + col] =
                        __floats2half2_rn(v0, v1);
                } else {
                    *(float2*)&Cf[(size_t)row * N + col] = make_float2(v0, v1);
                }
            }
        }
    }
}

// ---------------------------------------------------------------------------
// weight transpose to half: dst[C,R] = (half)src[R,C]^T
// ---------------------------------------------------------------------------
__global__ void transpose_half_kernel(const float* __restrict__ src,
                                      __half* __restrict__ dst, int R, int C)
{
    __shared__ float tile[32][33];
    int bx = blockIdx.x * 32, by = blockIdx.y * 32;
    int tx = threadIdx.x, ty = threadIdx.y;
    for (int i = ty; i < 32; i += 8)
        tile[i][tx] = src[(size_t)(by + i) * C + bx + tx];
    __syncthreads();
    for (int i = ty; i < 32; i += 8)
        dst[(size_t)(bx + i) * R + by + tx] = __float2half_rn(tile[tx][i]);
}

// ---------------------------------------------------------------------------
// LayerNorm -> half output (feeds GEMM A operand only)
// ---------------------------------------------------------------------------
__global__ void ln_kernel(const float* __restrict__ in,
                          const float* __restrict__ gamma,
                          const float* __restrict__ beta,
                          __half* __restrict__ out)
{
    int row = blockIdx.x;
    int t = threadIdx.x;
    const float* p = in + (size_t)row * DMODEL;
    float v[3];
    float s = 0.f, s2 = 0.f;
#pragma unroll
    for (int i = 0; i < 3; i++) {
        v[i] = p[t + i * 256];
        s += v[i];
        s2 += v[i] * v[i];
    }
#pragma unroll
    for (int o = 16; o; o >>= 1) {
        s  += __shfl_xor_sync(0xffffffffu, s, o);
        s2 += __shfl_xor_sync(0xffffffffu, s2, o);
    }
    __shared__ float ss[8], ss2[8];
    if ((t & 31) == 0) { ss[t >> 5] = s; ss2[t >> 5] = s2; }
    __syncthreads();
    s = 0.f; s2 = 0.f;
#pragma unroll
    for (int i = 0; i < 8; i++) { s += ss[i]; s2 += ss2[i]; }
    float mu  = s * (1.f / DMODEL);
    float var = s2 * (1.f / DMODEL) - mu * mu;
    float rstd = rsqrtf(var + 1e-5f);
    __half* q = out + (size_t)row * DMODEL;
#pragma unroll
    for (int i = 0; i < 3; i++) {
        int c = t + i * 256;
        q[c] = __float2half_rn((v[i] - mu) * rstd * gamma[c] + beta[c]);
    }
}

// ---------------------------------------------------------------------------
// FAVOR+ features: 4 tokens per block, 256 threads
// ---------------------------------------------------------------------------
__global__ void phi_kernel(const float* __restrict__ qkv,
                           const float* __restrict__ wf,
                           float* __restrict__ phiq,
                           float* __restrict__ phik)
{
    int s4  = blockIdx.x;             // token group (4 tokens)
    int bh  = blockIdx.y;
    int isk = blockIdx.z;
    int h = bh % NH, b = bh / NH;
    int t = threadIdx.x;
    int sub = t >> 6, m = t & 63;
    int s = s4 * 4 + sub;

    __shared__ float xs[4][64];
    const float* src = qkv + ((size_t)(b * 1024 + s)) * D3 + isk * DMODEL + h * DH;
    xs[sub][m] = src[m] * 0.3535533905932738f;
    __syncthreads();

    float proj = 0.f, sq = 0.f;
    const float* wrow = wf + m * DH;
#pragma unroll 16
    for (int d = 0; d < 64; d++) {
        float x = xs[sub][d];
        proj += x * wrow[d];
        sq   += x * x;
    }
    float val = expf(proj - 0.5f * sq) * 0.125f + 1e-6f;
    float* dst = (isk ? phik : phiq);
    dst[((size_t)bh * 1024 + s) * MF + m] = val;
}

// ---------------------------------------------------------------------------
// Per-chunk KV state
// ---------------------------------------------------------------------------
__global__ void chunkkv_kernel(const float* __restrict__ qkv,
                               const float* __restrict__ phik,
                               float* __restrict__ kvs,
                               float* __restrict__ ks)
{
    int c  = blockIdx.x;
    int bh = blockIdx.y;
    int h = bh % NH, b = bh / NH;
    int t = threadIdx.x;

    __shared__ float pk[CHUNK][MF];
    __shared__ float sv[CHUNK][DH];

    for (int i = t; i < CHUNK * 64; i += 256) {
        int s = i >> 6, d = i & 63;
        pk[s][d] = phik[((size_t)bh * 1024 + c * CHUNK + s) * MF + d];
        sv[s][d] = qkv[((size_t)(b * 1024 + c * CHUNK + s)) * D3 + 2 * DMODEL + h * DH + d];
    }
    __syncthreads();

    int m  = t & 63;
    int db = (t >> 6) * 16;
    float acc[16];
#pragma unroll
    for (int j = 0; j < 16; j++) acc[j] = 0.f;
    float sksum = 0.f;

    for (int s = 0; s < CHUNK; s++) {
        float pkm = pk[s][m];
        if (db == 0) sksum += pkm;
#pragma unroll
        for (int j = 0; j < 16; j++) acc[j] += pkm * sv[s][db + j];
    }
    float* dst = kvs + ((size_t)bh * NCHUNK + c) * (MF * DH) + m * DH + db;
#pragma unroll
    for (int j = 0; j < 16; j++) dst[j] = acc[j];
    if (db == 0) ks[((size_t)bh * NCHUNK + c) * MF + m] = sksum;
}

// ---------------------------------------------------------------------------
// Exclusive prefix over chunk states
// ---------------------------------------------------------------------------
__global__ void scan_kernel(const float* __restrict__ kvs,
                            const float* __restrict__ ks,
                            float* __restrict__ kvp,
                            float* __restrict__ ksp)
{
    int bh = blockIdx.x;
    int t = threadIdx.x;
    float acc[16];
#pragma unroll
    for (int r = 0; r < 16; r++) acc[r] = 0.f;
    float accs = 0.f;

    for (int c = 0; c < NCHUNK; c++) {
        size_t base = ((size_t)bh * NCHUNK + c) * (MF * DH);
#pragma unroll
        for (int r = 0; r < 16; r++) {
            int idx = t + r * 256;
            float v = kvs[base + idx];
            kvp[base + idx] = acc[r];
            acc[r] += v;
        }
        if (t < MF) {
            size_t kb = ((size_t)bh * NCHUNK + c) * MF + t;
            float v = ks[kb];
            ksp[kb] = accs;
            accs += v;
        }
    }
}

// ---------------------------------------------------------------------------
// Intra-chunk causal combine -> ctx half (feeds proj GEMM)
// ---------------------------------------------------------------------------
__global__ __launch_bounds__(256, 2)
void intra_kernel(const float* __restrict__ qkv,
                  const float* __restrict__ phiq,
                  const float* __restrict__ phik,
                  const float* __restrict__ kvpre,
                  const float* __restrict__ kspre,
                  __half* __restrict__ ctx)
{
    extern __shared__ float smf[];
    float (*pq)[65]  = (float(*)[65])smf;
    float (*pk)[64]  = (float(*)[64])(smf + 64 * 65);
    float (*sA)[65]  = (float(*)[65])(smf + 64 * 65 + 64 * 64);
    float (*sv)[64]  = (float(*)[64])(smf + 2 * 64 * 65 + 64 * 64);
    float (*skv)[64] = (float(*)[64])(smf + 2 * 64 * 65 + 2 * 64 * 64);
    float* sks       = smf + 2 * 64 * 65 + 3 * 64 * 64;

    int c  = blockIdx.x;
    int bh = blockIdx.y;
    int h = bh % NH, b = bh / NH;
    int t = threadIdx.x;
    size_t kvbase = ((size_t)bh * NCHUNK + c) * (MF * DH);

    for (int i = t; i < 64 * 64; i += 256) {
        int s = i >> 6, d = i & 63;
        size_t prow = ((size_t)bh * 1024 + c * CHUNK + s) * MF + d;
        pq[s][d] = phiq[prow];
        pk[s][d] = phik[prow];
        sv[s][d] = qkv[((size_t)(b * 1024 + c * CHUNK + s)) * D3 + 2 * DMODEL + h * DH + d];
        skv[s][d] = kvpre[kvbase + i];
    }
    if (t < MF) sks[t] = kspre[((size_t)bh * NCHUNK + c) * MF + t];
    __syncthreads();

    int i  = t & 63;
    int jb = (t >> 6) * 16;

    float a[16];
#pragma unroll
    for (int jj = 0; jj < 16; jj++) a[jj] = 0.f;
    for (int m = 0; m < MF; m++) {
        float pqv = pq[i][m];
#pragma unroll
        for (int jj = 0; jj < 16; jj++) a[jj] += pqv * pk[jb + jj][m];
    }
#pragma unroll
    for (int jj = 0; jj < 16; jj++) sA[i][jb + jj] = (jb + jj <= i) ? a[jj] : 0.f;
    __syncthreads();

    int db = jb;
    float num[16];
#pragma unroll
    for (int dd = 0; dd < 16; dd++) num[dd] = 0.f;
    float den = 0.f;

    for (int j = 0; j < CHUNK; j++) {
        float av = sA[i][j];
        den += av;
#pragma unroll
        for (int dd = 0; dd < 16; dd++) num[dd] += av * sv[j][db + dd];
    }
    for (int m = 0; m < MF; m++) {
        float pqv = pq[i][m];
        den += pqv * sks[m];
#pragma unroll
        for (int dd = 0; dd < 16; dd++) num[dd] += pqv * skv[m][db + dd];
    }

    float inv = 1.f / den;
    __half* dst = ctx + ((size_t)(b * 1024 + c * CHUNK + i)) * DMODEL + h * DH + db;
#pragma unroll
    for (int dd = 0; dd < 16; dd += 2)
        *(__half2*)&dst[dd] = __floats2half2_rn(num[dd] * inv, num[dd + 1] * inv);
}

// ---------------------------------------------------------------------------
static const int INTRA_SMEM = (2 * 64 * 65 + 3 * 64 * 64 + 64) * 4;

extern "C" void kernel_launch(void* const* d_in, const int* in_sizes, int n_in,
                              void* d_out, int out_size)
{
    const float* x      = (const float*)d_in[0];
    const float* ln1_g  = (const float*)d_in[1];
    const float* ln1_b  = (const float*)d_in[2];
    const float* w_attn = (const float*)d_in[3];
    const float* b_attn = (const float*)d_in[4];
    const float* w_feat = (const float*)d_in[5];
    const float* w_proj = (const float*)d_in[6];
    const float* b_proj = (const float*)d_in[7];
    const float* ln2_g  = (const float*)d_in[8];
    const float* ln2_b  = (const float*)d_in[9];
    const float* w_fc   = (const float*)d_in[10];
    const float* b_fc   = (const float*)d_in[11];
    const float* w_out  = (const float*)d_in[12];
    const float* b_out  = (const float*)d_in[13];
    float* out = (float*)d_out;

    float *qkv, *phiq, *phik, *kv, *kvp, *ks, *ksp, *x2;
    __half *ah, *ctxh, *ffnh, *wAT, *wPT, *wFT, *wOT;
    cudaGetSymbolAddress((void**)&qkv,  g_qkv);
    cudaGetSymbolAddress((void**)&phiq, g_phiq);
    cudaGetSymbolAddress((void**)&phik, g_phik);
    cudaGetSymbolAddress((void**)&kv,   g_kv);
    cudaGetSymbolAddress((void**)&kvp,  g_kvp);
    cudaGetSymbolAddress((void**)&ks,   g_ks);
    cudaGetSymbolAddress((void**)&ksp,  g_ksp);
    cudaGetSymbolAddress((void**)&x2,   g_x2);
    cudaGetSymbolAddress((void**)&ah,   g_ah);
    cudaGetSymbolAddress((void**)&ctxh, g_ctxh);
    cudaGetSymbolAddress((void**)&ffnh, g_ffnh);
    cudaGetSymbolAddress((void**)&wAT,  g_wAT);
    cudaGetSymbolAddress((void**)&wPT,  g_wPT);
    cudaGetSymbolAddress((void**)&wFT,  g_wFT);
    cudaGetSymbolAddress((void**)&wOT,  g_wOT);

    cudaFuncSetAttribute(intra_kernel,
        cudaFuncAttributeMaxDynamicSharedMemorySize, INTRA_SMEM);

    // weight transposes to half [N,K]
    transpose_half_kernel<<<dim3(D3 / 32, DMODEL / 32), dim3(32, 8)>>>(
        w_attn, wAT, DMODEL, D3);
    transpose_half_kernel<<<dim3(DMODEL / 32, DMODEL / 32), dim3(32, 8)>>>(
        w_proj, wPT, DMODEL, DMODEL);
    transpose_half_kernel<<<dim3(DFF / 32, DMODEL / 32), dim3(32, 8)>>>(
        w_fc, wFT, DMODEL, DFF);
    transpose_half_kernel<<<dim3(DMODEL / 32, DFF / 32), dim3(32, 8)>>>(
        w_out, wOT, DFF, DMODEL);

    // 1. LN1 -> half
    ln_kernel<<<ROWS, 256>>>(x, ln1_g, ln1_b, ah);
    // 2. qkv = a @ w_attn + b (fp32 out)
    hgemm<false, false, false><<<dim3(D3 / 128, ROWS / 128), 256>>>(
        ah, wAT, b_attn, nullptr, qkv, nullptr, D3, DMODEL);
    // 3-6. attention
    phi_kernel<<<dim3(256, BH, 2), 256>>>(qkv, w_feat, phiq, phik);
    chunkkv_kernel<<<dim3(NCHUNK, BH), 256>>>(qkv, phik, kv, ks);
    scan_kernel<<<BH, 256>>>(kv, ks, kvp, ksp);
    intra_kernel<<<dim3(NCHUNK, BH), 256, INTRA_SMEM>>>(qkv, phiq, phik, kvp, ksp, ctxh);
    // 7. x2 = x + ctx @ w_proj + b
    hgemm<false, true, false><<<dim3(DMODEL / 128, ROWS / 128), 256>>>(
        ctxh, wPT, b_proj, x, x2, nullptr, DMODEL, DMODEL);
    // 8. LN2 -> half
    ln_kernel<<<ROWS, 256>>>(x2, ln2_g, ln2_b, ah);
    // 9. ffn = gelu(a @ w_fc + b) -> half
    hgemm<true, false, true><<<dim3(DFF / 128, ROWS / 128), 256>>>(
        ah, wFT, b_fc, nullptr, nullptr, ffnh, DFF, DMODEL);
    // 10. out = x2 + ffn @ w_out + b
    hgemm<false, true, false><<<dim3(DMODEL / 128, ROWS / 128), 256>>>(
        ffnh, wOT, b_out, x2, out, nullptr, DMODEL, DFF);
}

// round 11
// speedup vs baseline: 5.4920x; 3.1246x over previous
#include <cuda_runtime.h>
#include <cuda_fp16.h>
#include <math.h>
#include <stdint.h>

// ---------------------------------------------------------------------------
// B=2, S=1024, D=768, H=12, DH=64, M=64, DFF=3072, rows = 2048
// fp16 mma.sync GEMMs, 4-stage cp.async single-sync pipeline.
// ---------------------------------------------------------------------------

#define ROWS   2048
#define DMODEL 768
#define D3     2304
#define DFF    3072
#define NH     12
#define BH     24
#define DH     64
#define MF     64
#define CHUNK  64
#define NCHUNK 16

__device__ float  g_qkv [ROWS * D3];
__device__ float  g_phiq[BH * 1024 * MF];
__device__ float  g_phik[BH * 1024 * MF];
__device__ float  g_kv  [BH * NCHUNK * MF * DH];
__device__ float  g_kvp [BH * NCHUNK * MF * DH];
__device__ float  g_ks  [BH * NCHUNK * MF];
__device__ float  g_ksp [BH * NCHUNK * MF];
__device__ float  g_x2  [ROWS * DMODEL];
__device__ __half g_ah  [ROWS * DMODEL];
__device__ __half g_ctxh[ROWS * DMODEL];
__device__ __half g_ffnh[ROWS * DFF];
__device__ __half g_wAT [D3 * DMODEL];
__device__ __half g_wPT [DMODEL * DMODEL];
__device__ __half g_wFT [DFF * DMODEL];
__device__ __half g_wOT [DMODEL * DFF];

// ---------------------------------------------------------------------------
__device__ __forceinline__ void cp_async16s(unsigned saddr, const void* gsrc) {
    asm volatile("cp.async.cg.shared.global [%0], [%1], 16;\n"
                 :: "r"(saddr), "l"(gsrc));
}
__device__ __forceinline__ void cp_commit() {
    asm volatile("cp.async.commit_group;\n");
}
template <int N>
__device__ __forceinline__ void cp_wait() {
    asm volatile("cp.async.wait_group %0;\n" :: "n"(N));
}
__device__ __forceinline__ void ldsm_x4(unsigned& r0, unsigned& r1,
                                        unsigned& r2, unsigned& r3,
                                        unsigned addr) {
    asm volatile("ldmatrix.sync.aligned.m8n8.x4.shared.b16 {%0,%1,%2,%3}, [%4];"
                 : "=r"(r0), "=r"(r1), "=r"(r2), "=r"(r3) : "r"(addr));
}
__device__ __forceinline__ void mma_f16(float* d, const unsigned* a,
                                        unsigned b0, unsigned b1) {
    asm volatile(
        "mma.sync.aligned.m16n8k16.row.col.f32.f16.f16.f32 "
        "{%0,%1,%2,%3}, {%4,%5,%6,%7}, {%8,%9}, {%0,%1,%2,%3};\n"
        : "+f"(d[0]), "+f"(d[1]), "+f"(d[2]), "+f"(d[3])
        : "r"(a[0]), "r"(a[1]), "r"(a[2]), "r"(a[3]), "r"(b0), "r"(b1));
}

// ---------------------------------------------------------------------------
// fp16 GEMM: C[M, N] = A[M,K] @ Bw^T + bias (+gelu) (+res)
// CTA tile MT x 128, BK=32, 256 threads (8 warps: 2m x 4n, warp (MT/2)x32).
// 4-stage cp.async ring, one __syncthreads per k-tile. 80B smem rows.
// ---------------------------------------------------------------------------
template <int MT, bool GELU, bool RES, bool HOUT>
__global__ __launch_bounds__(256, 2)
void hgemm(const __half* __restrict__ A, const __half* __restrict__ Bw,
           const float* __restrict__ bias, const float* __restrict__ res,
           float* __restrict__ Cf, __half* __restrict__ Ch, int N, int K)
{
    constexpr int MI = MT / 32;          // m16 tiles per warp
    constexpr int A_STAGE = MT * 80;     // bytes
    constexpr int B_STAGE = 128 * 80;

    extern __shared__ __align__(16) char dsm[];
    unsigned asb = (unsigned)__cvta_generic_to_shared(dsm);
    unsigned bsb = asb + 4 * A_STAGE;

    int t    = threadIdx.x;
    int lane = t & 31;
    int warp = t >> 5;
    int bm = blockIdx.y * MT;
    int bn = blockIdx.x * 128;
    int mbase = (warp >> 2) * (MT / 2);
    int nbase = (warp & 3) * 32;
    int g   = lane >> 2;
    int tig = lane & 3;

    const __half* Ag0 = A + (size_t)bm * K;
    const __half* Bg0 = Bw + (size_t)bn * K;

    auto load_tile = [&](int kt, int s) {
        const __half* Ag = Ag0 + (size_t)kt * 32;
        const __half* Bg = Bg0 + (size_t)kt * 32;
        unsigned ab = asb + s * A_STAGE;
        unsigned bb = bsb + s * B_STAGE;
#pragma unroll
        for (int i = 0; i < MT / 64; i++) {
            int idx = i * 256 + t, row = idx >> 2, c = idx & 3;
            cp_async16s(ab + row * 80 + c * 16, Ag + (size_t)row * K + c * 8);
        }
#pragma unroll
        for (int i = 0; i < 2; i++) {
            int idx = i * 256 + t, row = idx >> 2, c = idx & 3;
            cp_async16s(bb + row * 80 + c * 16, Bg + (size_t)row * K + c * 8);
        }
        cp_commit();
    };

    int nk = K >> 5;
    load_tile(0, 0);
    load_tile(1, 1);
    load_tile(2, 2);

    float acc[MI][4][4];
#pragma unroll
    for (int i = 0; i < MI; i++)
#pragma unroll
        for (int j = 0; j < 4; j++)
#pragma unroll
            for (int r = 0; r < 4; r++) acc[i][j][r] = 0.f;

    int a_r  = lane & 15;
    int a_kh = (lane >> 4) * 8;
    int b_mi = lane >> 3;
    int b_n  = ((b_mi >> 1) << 3) + (lane & 7);
    int b_kh = (b_mi & 1) * 8;

    for (int kt = 0; kt < nk; kt++) {
        int s = kt & 3;
        cp_wait<2>();
        __syncthreads();
        if (kt + 3 < nk) load_tile(kt + 3, (kt + 3) & 3);
        else cp_commit();

        unsigned as_s = asb + s * A_STAGE;
        unsigned bs_s = bsb + s * B_STAGE;
#pragma unroll
        for (int ks = 0; ks < 2; ks++) {
            int kb = ks * 16;
            unsigned af[MI][4], bfA[4], bfB[4];
#pragma unroll
            for (int i = 0; i < MI; i++) {
                unsigned addr = as_s + (mbase + i * 16 + a_r) * 80
                              + (kb + a_kh) * 2;
                ldsm_x4(af[i][0], af[i][1], af[i][2], af[i][3], addr);
            }
            ldsm_x4(bfA[0], bfA[1], bfA[2], bfA[3],
                    bs_s + (nbase + b_n) * 80 + (kb + b_kh) * 2);
            ldsm_x4(bfB[0], bfB[1], bfB[2], bfB[3],
                    bs_s + (nbase + 16 + b_n) * 80 + (kb + b_kh) * 2);
#pragma unroll
            for (int i = 0; i < MI; i++) {
                mma_f16(acc[i][0], af[i], bfA[0], bfA[1]);
                mma_f16(acc[i][1], af[i], bfA[2], bfA[3]);
                mma_f16(acc[i][2], af[i], bfB[0], bfB[1]);
                mma_f16(acc[i][3], af[i], bfB[2], bfB[3]);
            }
        }
    }

    // Epilogue
#pragma unroll
    for (int i = 0; i < MI; i++) {
#pragma unroll
        for (int j = 0; j < 4; j++) {
            int col = bn + nbase + j * 8 + 2 * tig;
            float b0 = bias[col], b1 = bias[col + 1];
#pragma unroll
            for (int half = 0; half < 2; half++) {
                int row = bm + mbase + i * 16 + g + half * 8;
                float v0 = acc[i][j][half * 2 + 0] + b0;
                float v1 = acc[i][j][half * 2 + 1] + b1;
                if (GELU) {
                    float u = v0, cu = u + 0.044715f * u * u * u;
                    v0 = 0.5f * u * (1.f + tanhf(0.7978845608028654f * cu));
                    u = v1; cu = u + 0.044715f * u * u * u;
                    v1 = 0.5f * u * (1.f + tanhf(0.7978845608028654f * cu));
                }
                if (RES) {
                    v0 += res[(size_t)row * N + col];
                    v1 += res[(size_t)row * N + col + 1];
                }
                if (HOUT) {
                    *(__half2*)&Ch[(size_t)row * N + col] =
                        __floats2half2_rn(v0, v1);
                } else {
                    *(float2*)&Cf[(size_t)row * N + col] = make_float2(v0, v1);
                }
            }
        }
    }
}

// ---------------------------------------------------------------------------
// weight transpose to half
// ---------------------------------------------------------------------------
__global__ void transpose_half_kernel(const float* __restrict__ src,
                                      __half* __restrict__ dst, int R, int C)
{
    __shared__ float tile[32][33];
    int bx = blockIdx.x * 32, by = blockIdx.y * 32;
    int tx = threadIdx.x, ty = threadIdx.y;
    for (int i = ty; i < 32; i += 8)
        tile[i][tx] = src[(size_t)(by + i) * C + bx + tx];
    __syncthreads();
    for (int i = ty; i < 32; i += 8)
        dst[(size_t)(bx + i) * R + by + tx] = __float2half_rn(tile[tx][i]);
}

// ---------------------------------------------------------------------------
// LayerNorm -> half
// ---------------------------------------------------------------------------
__global__ void ln_kernel(const float* __restrict__ in,
                          const float* __restrict__ gamma,
                          const float* __restrict__ beta,
                          __half* __restrict__ out)
{
    int row = blockIdx.x;
    int t = threadIdx.x;
    const float* p = in + (size_t)row * DMODEL;
    float v[3];
    float s = 0.f, s2 = 0.f;
#pragma unroll
    for (int i = 0; i < 3; i++) {
        v[i] = p[t + i * 256];
        s += v[i];
        s2 += v[i] * v[i];
    }
#pragma unroll
    for (int o = 16; o; o >>= 1) {
        s  += __shfl_xor_sync(0xffffffffu, s, o);
        s2 += __shfl_xor_sync(0xffffffffu, s2, o);
    }
    __shared__ float ss[8], ss2[8];
    if ((t & 31) == 0) { ss[t >> 5] = s; ss2[t >> 5] = s2; }
    __syncthreads();
    s = 0.f; s2 = 0.f;
#pragma unroll
    for (int i = 0; i < 8; i++) { s += ss[i]; s2 += ss2[i]; }
    float mu  = s * (1.f / DMODEL);
    float var = s2 * (1.f / DMODEL) - mu * mu;
    float rstd = rsqrtf(var + 1e-5f);
    __half* q = out + (size_t)row * DMODEL;
#pragma unroll
    for (int i = 0; i < 3; i++) {
        int c = t + i * 256;
        q[c] = __float2half_rn((v[i] - mu) * rstd * gamma[c] + beta[c]);
    }
}

// ---------------------------------------------------------------------------
// FAVOR+ features: 32 tokens per block, w_feat staged in smem (transposed)
// ---------------------------------------------------------------------------
__global__ __launch_bounds__(256)
void phi_kernel(const float* __restrict__ qkv,
                const float* __restrict__ wf,
                float* __restrict__ phiq,
                float* __restrict__ phik)
{
    int grp = blockIdx.x;              // 32-token group
    int bh  = blockIdx.y;
    int isk = blockIdx.z;
    int h = bh % NH, b = bh / NH;
    int t = threadIdx.x;

    __shared__ float wfs[64][65];      // transposed w_feat
    __shared__ float xs[32][65];
    __shared__ float sqs[32];

    for (int i = t; i < 4096; i += 256) {
        int m = i >> 6, d = i & 63;
        wfs[d][m] = wf[i];
    }
    int base_s = grp * 32;
    for (int i = t; i < 32 * 64; i += 256) {
        int tok = i >> 6, d = i & 63;
        xs[tok][d] = qkv[((size_t)(b * 1024 + base_s + tok)) * D3
                         + isk * DMODEL + h * DH + d] * 0.3535533905932738f;
    }
    __syncthreads();
    if (t < 32) {
        float sq = 0.f;
#pragma unroll 16
        for (int d = 0; d < 64; d++) sq += xs[t][d] * xs[t][d];
        sqs[t] = 0.5f * sq;
    }
    __syncthreads();

    int m = t & 63;
    float* dst = (isk ? phik : phiq);
#pragma unroll
    for (int it = 0; it < 8; it++) {
        int tok = (t >> 6) * 8 + it;
        float proj = 0.f;
#pragma unroll 16
        for (int d = 0; d < 64; d++) proj += xs[tok][d] * wfs[d][m];
        dst[((size_t)bh * 1024 + base_s + tok) * MF + m] =
            expf(proj - sqs[tok]) * 0.125f + 1e-6f;
    }
}

// ---------------------------------------------------------------------------
// Per-chunk KV state
// ---------------------------------------------------------------------------
__global__ void chunkkv_kernel(const float* __restrict__ qkv,
                               const float* __restrict__ phik,
                               float* __restrict__ kvs,
                               float* __restrict__ ks)
{
    int c  = blockIdx.x;
    int bh = blockIdx.y;
    int h = bh % NH, b = bh / NH;
    int t = threadIdx.x;

    __shared__ float pk[CHUNK][MF];
    __shared__ float sv[CHUNK][DH];

    for (int i = t; i < CHUNK * 64; i += 256) {
        int s = i >> 6, d = i & 63;
        pk[s][d] = phik[((size_t)bh * 1024 + c * CHUNK + s) * MF + d];
        sv[s][d] = qkv[((size_t)(b * 1024 + c * CHUNK + s)) * D3 + 2 * DMODEL + h * DH + d];
    }
    __syncthreads();

    int m  = t & 63;
    int db = (t >> 6) * 16;
    float acc[16];
#pragma unroll
    for (int j = 0; j < 16; j++) acc[j] = 0.f;
    float sksum = 0.f;

    for (int s = 0; s < CHUNK; s++) {
        float pkm = pk[s][m];
        if (db == 0) sksum += pkm;
#pragma unroll
        for (int j = 0; j < 16; j++) acc[j] += pkm * sv[s][db + j];
    }
    float* dst = kvs + ((size_t)bh * NCHUNK + c) * (MF * DH) + m * DH + db;
#pragma unroll
    for (int j = 0; j < 16; j++) dst[j] = acc[j];
    if (db == 0) ks[((size_t)bh * NCHUNK + c) * MF + m] = sksum;
}

// ---------------------------------------------------------------------------
// Exclusive prefix over chunk states: grid (BH, 16)
// ---------------------------------------------------------------------------
__global__ void scan_kernel(const float* __restrict__ kvs,
                            const float* __restrict__ ks,
                            float* __restrict__ kvp,
                            float* __restrict__ ksp)
{
    int bh = blockIdx.x;
    int grp = blockIdx.y;
    int t = threadIdx.x;
    int idx = grp * 256 + t;

    float acc = 0.f;
    size_t base = (size_t)bh * NCHUNK * (MF * DH) + idx;
#pragma unroll
    for (int c = 0; c < NCHUNK; c++) {
        float v = kvs[base + (size_t)c * (MF * DH)];
        kvp[base + (size_t)c * (MF * DH)] = acc;
        acc += v;
    }
    if (grp == 0 && t < MF) {
        float a2 = 0.f;
        size_t kb = (size_t)bh * NCHUNK * MF + t;
#pragma unroll
        for (int c = 0; c < NCHUNK; c++) {
            float v = ks[kb + (size_t)c * MF];
            ksp[kb + (size_t)c * MF] = a2;
            a2 += v;
        }
    }
}

// ---------------------------------------------------------------------------
// Intra-chunk causal combine -> ctx half
// ---------------------------------------------------------------------------
__global__ __launch_bounds__(256, 2)
void intra_kernel(const float* __restrict__ qkv,
                  const float* __restrict__ phiq,
                  const float* __restrict__ phik,
                  const float* __restrict__ kvpre,
                  const float* __restrict__ kspre,
                  __half* __restrict__ ctx)
{
    extern __shared__ float smf[];
    float (*pq)[65]  = (float(*)[65])smf;
    float (*pk)[64]  = (float(*)[64])(smf + 64 * 65);
    float (*sA)[65]  = (float(*)[65])(smf + 64 * 65 + 64 * 64);
    float (*sv)[64]  = (float(*)[64])(smf + 2 * 64 * 65 + 64 * 64);
    float (*skv)[64] = (float(*)[64])(smf + 2 * 64 * 65 + 2 * 64 * 64);
    float* sks       = smf + 2 * 64 * 65 + 3 * 64 * 64;

    int c  = blockIdx.x;
    int bh = blockIdx.y;
    int h = bh % NH, b = bh / NH;
    int t = threadIdx.x;
    size_t kvbase = ((size_t)bh * NCHUNK + c) * (MF * DH);

    for (int i = t; i < 64 * 64; i += 256) {
        int s = i >> 6, d = i & 63;
        size_t prow = ((size_t)bh * 1024 + c * CHUNK + s) * MF + d;
        pq[s][d] = phiq[prow];
        pk[s][d] = phik[prow];
        sv[s][d] = qkv[((size_t)(b * 1024 + c * CHUNK + s)) * D3 + 2 * DMODEL + h * DH + d];
        skv[s][d] = kvpre[kvbase + i];
    }
    if (t < MF) sks[t] = kspre[((size_t)bh * NCHUNK + c) * MF + t];
    __syncthreads();

    int i  = t & 63;
    int jb = (t >> 6) * 16;

    float a[16];
#pragma unroll
    for (int jj = 0; jj < 16; jj++) a[jj] = 0.f;
    for (int m = 0; m < MF; m++) {
        float pqv = pq[i][m];
#pragma unroll
        for (int jj = 0; jj < 16; jj++) a[jj] += pqv * pk[jb + jj][m];
    }
#pragma unroll
    for (int jj = 0; jj < 16; jj++) sA[i][jb + jj] = (jb + jj <= i) ? a[jj] : 0.f;
    __syncthreads();

    int db = jb;
    float num[16];
#pragma unroll
    for (int dd = 0; dd < 16; dd++) num[dd] = 0.f;
    float den = 0.f;

    for (int j = 0; j < CHUNK; j++) {
        float av = sA[i][j];
        den += av;
#pragma unroll
        for (int dd = 0; dd < 16; dd++) num[dd] += av * sv[j][db + dd];
    }
    for (int m = 0; m < MF; m++) {
        float pqv = pq[i][m];
        den += pqv * sks[m];
#pragma unroll
        for (int dd = 0; dd < 16; dd++) num[dd] += pqv * skv[m][db + dd];
    }

    float inv = 1.f / den;
    __half* dst = ctx + ((size_t)(b * 1024 + c * CHUNK + i)) * DMODEL + h * DH + db;
#pragma unroll
    for (int dd = 0; dd < 16; dd += 2)
        *(__half2*)&dst[dd] = __floats2half2_rn(num[dd] * inv, num[dd + 1] * inv);
}

// ---------------------------------------------------------------------------
static const int INTRA_SMEM = (2 * 64 * 65 + 3 * 64 * 64 + 64) * 4;
static const int GSM_128 = 4 * (128 * 80 + 128 * 80);   // 81920
static const int GSM_64  = 4 * (64 * 80 + 128 * 80);    // 61440

extern "C" void kernel_launch(void* const* d_in, const int* in_sizes, int n_in,
                              void* d_out, int out_size)
{
    const float* x      = (const float*)d_in[0];
    const float* ln1_g  = (const float*)d_in[1];
    const float* ln1_b  = (const float*)d_in[2];
    const float* w_attn = (const float*)d_in[3];
    const float* b_attn = (const float*)d_in[4];
    const float* w_feat = (const float*)d_in[5];
    const float* w_proj = (const float*)d_in[6];
    const float* b_proj = (const float*)d_in[7];
    const float* ln2_g  = (const float*)d_in[8];
    const float* ln2_b  = (const float*)d_in[9];
    const float* w_fc   = (const float*)d_in[10];
    const float* b_fc   = (const float*)d_in[11];
    const float* w_out  = (const float*)d_in[12];
    const float* b_out  = (const float*)d_in[13];
    float* out = (float*)d_out;

    float *qkv, *phiq, *phik, *kv, *kvp, *ks, *ksp, *x2;
    __half *ah, *ctxh, *ffnh, *wAT, *wPT, *wFT, *wOT;
    cudaGetSymbolAddress((void**)&qkv,  g_qkv);
    cudaGetSymbolAddress((void**)&phiq, g_phiq);
    cudaGetSymbolAddress((void**)&phik, g_phik);
    cudaGetSymbolAddress((void**)&kv,   g_kv);
    cudaGetSymbolAddress((void**)&kvp,  g_kvp);
    cudaGetSymbolAddress((void**)&ks,   g_ks);
    cudaGetSymbolAddress((void**)&ksp,  g_ksp);
    cudaGetSymbolAddress((void**)&x2,   g_x2);
    cudaGetSymbolAddress((void**)&ah,   g_ah);
    cudaGetSymbolAddress((void**)&ctxh, g_ctxh);
    cudaGetSymbolAddress((void**)&ffnh, g_ffnh);
    cudaGetSymbolAddress((void**)&wAT,  g_wAT);
    cudaGetSymbolAddress((void**)&wPT,  g_wPT);
    cudaGetSymbolAddress((void**)&wFT,  g_wFT);
    cudaGetSymbolAddress((void**)&wOT,  g_wOT);

    cudaFuncSetAttribute(intra_kernel,
        cudaFuncAttributeMaxDynamicSharedMemorySize, INTRA_SMEM);
    cudaFuncSetAttribute(hgemm<128, false, false, false>,
        cudaFuncAttributeMaxDynamicSharedMemorySize, GSM_128);
    cudaFuncSetAttribute(hgemm<128, true, false, true>,
        cudaFuncAttributeMaxDynamicSharedMemorySize, GSM_128);
    cudaFuncSetAttribute(hgemm<64, false, true, false>,
        cudaFuncAttributeMaxDynamicSharedMemorySize, GSM_64);

    transpose_half_kernel<<<dim3(D3 / 32, DMODEL / 32), dim3(32, 8)>>>(
        w_attn, wAT, DMODEL, D3);
    transpose_half_kernel<<<dim3(DMODEL / 32, DMODEL / 32), dim3(32, 8)>>>(
        w_proj, wPT, DMODEL, DMODEL);
    transpose_half_kernel<<<dim3(DFF / 32, DMODEL / 32), dim3(32, 8)>>>(
        w_fc, wFT, DMODEL, DFF);
    transpose_half_kernel<<<dim3(DMODEL / 32, DFF / 32), dim3(32, 8)>>>(
        w_out, wOT, DFF, DMODEL);

    ln_kernel<<<ROWS, 256>>>(x, ln1_g, ln1_b, ah);
    hgemm<128, false, false, false><<<dim3(D3 / 128, ROWS / 128), 256, GSM_128>>>(
        ah, wAT, b_attn, nullptr, qkv, nullptr, D3, DMODEL);
    phi_kernel<<<dim3(32, BH, 2), 256>>>(qkv, w_feat, phiq, phik);
    chunkkv_kernel<<<dim3(NCHUNK, BH), 256>>>(qkv, phik, kv, ks);
    scan_kernel<<<dim3(BH, 16), 256>>>(kv, ks, kvp, ksp);
    intra_kernel<<<dim3(NCHUNK, BH), 256, INTRA_SMEM>>>(qkv, phiq, phik, kvp, ksp, ctxh);
    hgemm<64, false, true, false><<<dim3(DMODEL / 128, ROWS / 64), 256, GSM_64>>>(
        ctxh, wPT, b_proj, x, x2, nullptr, DMODEL, DMODEL);
    ln_kernel<<<ROWS, 256>>>(x2, ln2_g, ln2_b, ah);
    hgemm<128, true, false, true><<<dim3(DFF / 128, ROWS / 128), 256, GSM_128>>>(
        ah, wFT, b_fc, nullptr, nullptr, ffnh, DFF, DMODEL);
    hgemm<64, false, true, false><<<dim3(DMODEL / 128, ROWS / 64), 256, GSM_64>>>(
        ffnh, wOT, b_out, x2, out, nullptr, DMODEL, DFF);
}

// round 14
// speedup vs baseline: 5.9551x; 1.0843x over previous
#include <cuda_runtime.h>
#include <cuda_fp16.h>
#include <math.h>
#include <stdint.h>

// ---------------------------------------------------------------------------
// B=2, S=1024, D=768, H=12, DH=64, M=64, DFF=3072, rows = 2048
// fp16 mma.sync GEMMs, 4-stage cp.async pipeline, B via ldmatrix.trans
// from natural [K,N] weights (no transpose kernels).
// ---------------------------------------------------------------------------

#define ROWS   2048
#define DMODEL 768
#define D3     2304
#define DFF    3072
#define NH     12
#define BH     24
#define DH     64
#define MF     64
#define CHUNK  64
#define NCHUNK 16

__device__ float  g_qkv [ROWS * D3];
__device__ float  g_phiq[BH * 1024 * MF];
__device__ float  g_phik[BH * 1024 * MF];
__device__ float  g_kv  [BH * NCHUNK * MF * DH];
__device__ float  g_kvp [BH * NCHUNK * MF * DH];
__device__ float  g_ks  [BH * NCHUNK * MF];
__device__ float  g_ksp [BH * NCHUNK * MF];
__device__ float  g_x2  [ROWS * DMODEL];
__device__ __half g_ah  [ROWS * DMODEL];
__device__ __half g_ctxh[ROWS * DMODEL];
__device__ __half g_ffnh[ROWS * DFF];
__device__ __half g_wAh [DMODEL * D3];      // [K,N] half weights
__device__ __half g_wPh [DMODEL * DMODEL];
__device__ __half g_wFh [DMODEL * DFF];
__device__ __half g_wOh [DFF * DMODEL];

// ---------------------------------------------------------------------------
__device__ __forceinline__ void cp_async16s(unsigned saddr, const void* gsrc) {
    asm volatile("cp.async.cg.shared.global [%0], [%1], 16;\n"
                 :: "r"(saddr), "l"(gsrc));
}
__device__ __forceinline__ void cp_commit() {
    asm volatile("cp.async.commit_group;\n");
}
template <int N>
__device__ __forceinline__ void cp_wait() {
    asm volatile("cp.async.wait_group %0;\n" :: "n"(N));
}
__device__ __forceinline__ void ldsm_x4(unsigned& r0, unsigned& r1,
                                        unsigned& r2, unsigned& r3,
                                        unsigned addr) {
    asm volatile("ldmatrix.sync.aligned.m8n8.x4.shared.b16 {%0,%1,%2,%3}, [%4];"
                 : "=r"(r0), "=r"(r1), "=r"(r2), "=r"(r3) : "r"(addr));
}
__device__ __forceinline__ void ldsm_x4t(unsigned& r0, unsigned& r1,
                                         unsigned& r2, unsigned& r3,
                                         unsigned addr) {
    asm volatile("ldmatrix.sync.aligned.m8n8.x4.trans.shared.b16 {%0,%1,%2,%3}, [%4];"
                 : "=r"(r0), "=r"(r1), "=r"(r2), "=r"(r3) : "r"(addr));
}
__device__ __forceinline__ void mma_f16(float* d, const unsigned* a,
                                        unsigned b0, unsigned b1) {
    asm volatile(
        "mma.sync.aligned.m16n8k16.row.col.f32.f16.f16.f32 "
        "{%0,%1,%2,%3}, {%4,%5,%6,%7}, {%8,%9}, {%0,%1,%2,%3};\n"
        : "+f"(d[0]), "+f"(d[1]), "+f"(d[2]), "+f"(d[3])
        : "r"(a[0]), "r"(a[1]), "r"(a[2]), "r"(a[3]), "r"(b0), "r"(b1));
}

// ---------------------------------------------------------------------------
// fp16 GEMM: C[M,N] = A[M,K] @ W[K,N] + bias (+gelu) (+res)
// A half [M,K] row-major; W half [K,N] row-major (B frags via ldmatrix.trans).
// CTA MT x 128, BK=32, 256 threads (8 warps: 2m x 4n). 4-stage cp.async.
// A rows 80B pad; B rows 272B pad (conflict-free trans loads).
// ---------------------------------------------------------------------------
#define BROW 272

template <int MT, bool GELU, bool RES, bool HOUT>
__global__ __launch_bounds__(256, 2)
void hgemm(const __half* __restrict__ A, const __half* __restrict__ W,
           const float* __restrict__ bias, const float* __restrict__ res,
           float* __restrict__ Cf, __half* __restrict__ Ch, int N, int K)
{
    constexpr int MI = MT / 32;
    constexpr int A_STAGE = MT * 80;
    constexpr int B_STAGE = 32 * BROW;   // 8704

    extern __shared__ __align__(16) char dsm[];
    unsigned asb = (unsigned)__cvta_generic_to_shared(dsm);
    unsigned bsb = asb + 4 * A_STAGE;

    int t    = threadIdx.x;
    int lane = t & 31;
    int warp = t >> 5;
    int bm = blockIdx.y * MT;
    int bn = blockIdx.x * 128;
    int mbase = (warp >> 2) * (MT / 2);
    int nbase = (warp & 3) * 32;
    int g   = lane >> 2;
    int tig = lane & 3;

    const __half* Ag0 = A + (size_t)bm * K;

    auto load_tile = [&](int kt, int s) {
        const __half* Ag = Ag0 + (size_t)kt * 32;
        unsigned ab = asb + s * A_STAGE;
#pragma unroll
        for (int i = 0; i < MT / 64; i++) {
            int idx = i * 256 + t, row = idx >> 2, c = idx & 3;
            cp_async16s(ab + row * 80 + c * 16, Ag + (size_t)row * K + c * 8);
        }
        const __half* Bg = W + (size_t)(kt * 32) * N + bn;
        unsigned bb = bsb + s * B_STAGE;
#pragma unroll
        for (int i = 0; i < 2; i++) {
            int idx = i * 256 + t, r = idx >> 4, c = idx & 15;
            cp_async16s(bb + r * BROW + c * 16, Bg + (size_t)r * N + c * 8);
        }
        cp_commit();
    };

    int nk = K >> 5;
    load_tile(0, 0);
    load_tile(1, 1);
    load_tile(2, 2);

    float acc[MI][4][4];
#pragma unroll
    for (int i = 0; i < MI; i++)
#pragma unroll
        for (int j = 0; j < 4; j++)
#pragma unroll
            for (int r = 0; r < 4; r++) acc[i][j][r] = 0.f;

    int a_r  = lane & 15;
    int a_kh = (lane >> 4) * 8;
    int b_r   = lane & 7;             // row within k8 block
    int b_mi  = lane >> 3;            // matrix index
    int b_kh2 = (b_mi & 1) * 8;       // k-half
    int b_no  = (b_mi >> 1) * 8;      // n8 offset within n16

    for (int kt = 0; kt < nk; kt++) {
        int s = kt & 3;
        cp_wait<2>();
        __syncthreads();
        if (kt + 3 < nk) load_tile(kt + 3, (kt + 3) & 3);
        else cp_commit();

        unsigned as_s = asb + s * A_STAGE;
        unsigned bs_s = bsb + s * B_STAGE;
#pragma unroll
        for (int ks = 0; ks < 2; ks++) {
            int kb = ks * 16;
            unsigned af[MI][4], bfA[4], bfB[4];
#pragma unroll
            for (int i = 0; i < MI; i++) {
                unsigned addr = as_s + (mbase + i * 16 + a_r) * 80
                              + (kb + a_kh) * 2;
                ldsm_x4(af[i][0], af[i][1], af[i][2], af[i][3], addr);
            }
            unsigned brow = bs_s + (kb + b_kh2 + b_r) * BROW;
            ldsm_x4t(bfA[0], bfA[1], bfA[2], bfA[3],
                     brow + (nbase + b_no) * 2);
            ldsm_x4t(bfB[0], bfB[1], bfB[2], bfB[3],
                     brow + (nbase + 16 + b_no) * 2);
#pragma unroll
            for (int i = 0; i < MI; i++) {
                mma_f16(acc[i][0], af[i], bfA[0], bfA[1]);
                mma_f16(acc[i][1], af[i], bfA[2], bfA[3]);
                mma_f16(acc[i][2], af[i], bfB[0], bfB[1]);
                mma_f16(acc[i][3], af[i], bfB[2], bfB[3]);
            }
        }
    }

    // Epilogue
#pragma unroll
    for (int i = 0; i < MI; i++) {
#pragma unroll
        for (int j = 0; j < 4; j++) {
            int col = bn + nbase + j * 8 + 2 * tig;
            float b0 = bias[col], b1 = bias[col + 1];
#pragma unroll
            for (int half = 0; half < 2; half++) {
                int row = bm + mbase + i * 16 + g + half * 8;
                float v0 = acc[i][j][half * 2 + 0] + b0;
                float v1 = acc[i][j][half * 2 + 1] + b1;
                if (GELU) {
                    float u = v0, cu = u + 0.044715f * u * u * u;
                    v0 = 0.5f * u * (1.f + tanhf(0.7978845608028654f * cu));
                    u = v1; cu = u + 0.044715f * u * u * u;
                    v1 = 0.5f * u * (1.f + tanhf(0.7978845608028654f * cu));
                }
                if (RES) {
                    v0 += res[(size_t)row * N + col];
                    v1 += res[(size_t)row * N + col + 1];
                }
                if (HOUT) {
                    *(__half2*)&Ch[(size_t)row * N + col] =
                        __floats2half2_rn(v0, v1);
                } else {
                    *(float2*)&Cf[(size_t)row * N + col] = make_float2(v0, v1);
                }
            }
        }
    }
}

// ---------------------------------------------------------------------------
// elementwise fp32 -> fp16 convert (coalesced, 8 elems/thread)
// ---------------------------------------------------------------------------
__global__ void conv_half_kernel(const float* __restrict__ src,
                                 __half* __restrict__ dst, int n)
{
    int i = (blockIdx.x * 256 + threadIdx.x) * 8;
    if (i >= n) return;
    float4 a = *(const float4*)(src + i);
    float4 b = *(const float4*)(src + i + 4);
    union { __half2 h[4]; uint4 v; } u;
    u.h[0] = __floats2half2_rn(a.x, a.y);
    u.h[1] = __floats2half2_rn(a.z, a.w);
    u.h[2] = __floats2half2_rn(b.x, b.y);
    u.h[3] = __floats2half2_rn(b.z, b.w);
    *(uint4*)(dst + i) = u.v;
}

// ---------------------------------------------------------------------------
// LayerNorm -> half
// ---------------------------------------------------------------------------
__global__ void ln_kernel(const float* __restrict__ in,
                          const float* __restrict__ gamma,
                          const float* __restrict__ beta,
                          __half* __restrict__ out)
{
    int row = blockIdx.x;
    int t = threadIdx.x;
    const float* p = in + (size_t)row * DMODEL;
    float v[3];
    float s = 0.f, s2 = 0.f;
#pragma unroll
    for (int i = 0; i < 3; i++) {
        v[i] = p[t + i * 256];
        s += v[i];
        s2 += v[i] * v[i];
    }
#pragma unroll
    for (int o = 16; o; o >>= 1) {
        s  += __shfl_xor_sync(0xffffffffu, s, o);
        s2 += __shfl_xor_sync(0xffffffffu, s2, o);
    }
    __shared__ float ss[8], ss2[8];
    if ((t & 31) == 0) { ss[t >> 5] = s; ss2[t >> 5] = s2; }
    __syncthreads();
    s = 0.f; s2 = 0.f;
#pragma unroll
    for (int i = 0; i < 8; i++) { s += ss[i]; s2 += ss2[i]; }
    float mu  = s * (1.f / DMODEL);
    float var = s2 * (1.f / DMODEL) - mu * mu;
    float rstd = rsqrtf(var + 1e-5f);
    __half* q = out + (size_t)row * DMODEL;
#pragma unroll
    for (int i = 0; i < 3; i++) {
        int c = t + i * 256;
        q[c] = __float2half_rn((v[i] - mu) * rstd * gamma[c] + beta[c]);
    }
}

// ---------------------------------------------------------------------------
// FAVOR+ features: 32 tokens per block, w_feat staged transposed in smem
// ---------------------------------------------------------------------------
__global__ __launch_bounds__(256)
void phi_kernel(const float* __restrict__ qkv,
                const float* __restrict__ wf,
                float* __restrict__ phiq,
                float* __restrict__ phik)
{
    int grp = blockIdx.x;
    int bh  = blockIdx.y;
    int isk = blockIdx.z;
    int h = bh % NH, b = bh / NH;
    int t = threadIdx.x;

    __shared__ float wfs[64][65];
    __shared__ float xs[32][65];
    __shared__ float sqs[32];

    for (int i = t; i < 4096; i += 256) {
        int m = i >> 6, d = i & 63;
        wfs[d][m] = wf[i];
    }
    int base_s = grp * 32;
    for (int i = t; i < 32 * 64; i += 256) {
        int tok = i >> 6, d = i & 63;
        xs[tok][d] = qkv[((size_t)(b * 1024 + base_s + tok)) * D3
                         + isk * DMODEL + h * DH + d] * 0.3535533905932738f;
    }
    __syncthreads();
    if (t < 32) {
        float sq = 0.f;
#pragma unroll 16
        for (int d = 0; d < 64; d++) sq += xs[t][d] * xs[t][d];
        sqs[t] = 0.5f * sq;
    }
    __syncthreads();

    int m = t & 63;
    float* dst = (isk ? phik : phiq);
#pragma unroll
    for (int it = 0; it < 8; it++) {
        int tok = (t >> 6) * 8 + it;
        float proj = 0.f;
#pragma unroll 16
        for (int d = 0; d < 64; d++) proj += xs[tok][d] * wfs[d][m];
        dst[((size_t)bh * 1024 + base_s + tok) * MF + m] =
            expf(proj - sqs[tok]) * 0.125f + 1e-6f;
    }
}

// ---------------------------------------------------------------------------
// Per-chunk KV state, d-split x2: grid (NCHUNK, BH, 2)
// ---------------------------------------------------------------------------
__global__ void chunkkv_kernel(const float* __restrict__ qkv,
                               const float* __restrict__ phik,
                               float* __restrict__ kvs,
                               float* __restrict__ ks)
{
    int c  = blockIdx.x;
    int bh = blockIdx.y;
    int z  = blockIdx.z;
    int h = bh % NH, b = bh / NH;
    int t = threadIdx.x;

    __shared__ float pk[CHUNK][MF];
    __shared__ float sv[CHUNK][32];

    for (int i = t; i < CHUNK * 64; i += 256) {
        int s = i >> 6, d = i & 63;
        pk[s][d] = phik[((size_t)bh * 1024 + c * CHUNK + s) * MF + d];
    }
    for (int i = t; i < CHUNK * 32; i += 256) {
        int s = i >> 5, d = i & 31;
        sv[s][d] = qkv[((size_t)(b * 1024 + c * CHUNK + s)) * D3
                       + 2 * DMODEL + h * DH + z * 32 + d];
    }
    __syncthreads();

    int m  = t & 63;
    int dl = (t >> 6) * 8;              // local d base (0,8,16,24)
    float acc[8];
#pragma unroll
    for (int j = 0; j < 8; j++) acc[j] = 0.f;
    float sksum = 0.f;

    for (int s = 0; s < CHUNK; s++) {
        float pkm = pk[s][m];
        if (dl == 0) sksum += pkm;
#pragma unroll
        for (int j = 0; j < 8; j++) acc[j] += pkm * sv[s][dl + j];
    }
    float* dst = kvs + ((size_t)bh * NCHUNK + c) * (MF * DH) + m * DH + z * 32 + dl;
#pragma unroll
    for (int j = 0; j < 8; j++) dst[j] = acc[j];
    if (z == 0 && dl == 0) ks[((size_t)bh * NCHUNK + c) * MF + m] = sksum;
}

// ---------------------------------------------------------------------------
// Exclusive prefix over chunk states: grid (BH, 16)
// ---------------------------------------------------------------------------
__global__ void scan_kernel(const float* __restrict__ kvs,
                            const float* __restrict__ ks,
                            float* __restrict__ kvp,
                            float* __restrict__ ksp)
{
    int bh = blockIdx.x;
    int grp = blockIdx.y;
    int t = threadIdx.x;
    int idx = grp * 256 + t;

    float acc = 0.f;
    size_t base = (size_t)bh * NCHUNK * (MF * DH) + idx;
#pragma unroll
    for (int c = 0; c < NCHUNK; c++) {
        float v = kvs[base + (size_t)c * (MF * DH)];
        kvp[base + (size_t)c * (MF * DH)] = acc;
        acc += v;
    }
    if (grp == 0 && t < MF) {
        float a2 = 0.f;
        size_t kb = (size_t)bh * NCHUNK * MF + t;
#pragma unroll
        for (int c = 0; c < NCHUNK; c++) {
            float v = ks[kb + (size_t)c * MF];
            ksp[kb + (size_t)c * MF] = a2;
            a2 += v;
        }
    }
}

// ---------------------------------------------------------------------------
// Intra-chunk causal combine -> ctx half
// ---------------------------------------------------------------------------
__global__ __launch_bounds__(256, 2)
void intra_kernel(const float* __restrict__ qkv,
                  const float* __restrict__ phiq,
                  const float* __restrict__ phik,
                  const float* __restrict__ kvpre,
                  const float* __restrict__ kspre,
                  __half* __restrict__ ctx)
{
    extern __shared__ float smf[];
    float (*pq)[65]  = (float(*)[65])smf;
    float (*pk)[64]  = (float(*)[64])(smf + 64 * 65);
    float (*sA)[65]  = (float(*)[65])(smf + 64 * 65 + 64 * 64);
    float (*sv)[64]  = (float(*)[64])(smf + 2 * 64 * 65 + 64 * 64);
    float (*skv)[64] = (float(*)[64])(smf + 2 * 64 * 65 + 2 * 64 * 64);
    float* sks       = smf + 2 * 64 * 65 + 3 * 64 * 64;

    int c  = blockIdx.x;
    int bh = blockIdx.y;
    int h = bh % NH, b = bh / NH;
    int t = threadIdx.x;
    size_t kvbase = ((size_t)bh * NCHUNK + c) * (MF * DH);

    for (int i = t; i < 64 * 64; i += 256) {
        int s = i >> 6, d = i & 63;
        size_t prow = ((size_t)bh * 1024 + c * CHUNK + s) * MF + d;
        pq[s][d] = phiq[prow];
        pk[s][d] = phik[prow];
        sv[s][d] = qkv[((size_t)(b * 1024 + c * CHUNK + s)) * D3 + 2 * DMODEL + h * DH + d];
        skv[s][d] = kvpre[kvbase + i];
    }
    if (t < MF) sks[t] = kspre[((size_t)bh * NCHUNK + c) * MF + t];
    __syncthreads();

    int i  = t & 63;
    int jb = (t >> 6) * 16;

    float a[16];
#pragma unroll
    for (int jj = 0; jj < 16; jj++) a[jj] = 0.f;
    for (int m = 0; m < MF; m++) {
        float pqv = pq[i][m];
#pragma unroll
        for (int jj = 0; jj < 16; jj++) a[jj] += pqv * pk[jb + jj][m];
    }
#pragma unroll
    for (int jj = 0; jj < 16; jj++) sA[i][jb + jj] = (jb + jj <= i) ? a[jj] : 0.f;
    __syncthreads();

    int db = jb;
    float num[16];
#pragma unroll
    for (int dd = 0; dd < 16; dd++) num[dd] = 0.f;
    float den = 0.f;

    for (int j = 0; j < CHUNK; j++) {
        float av = sA[i][j];
        den += av;
#pragma unroll
        for (int dd = 0; dd < 16; dd++) num[dd] += av * sv[j][db + dd];
    }
    for (int m = 0; m < MF; m++) {
        float pqv = pq[i][m];
        den += pqv * sks[m];
#pragma unroll
        for (int dd = 0; dd < 16; dd++) num[dd] += pqv * skv[m][db + dd];
    }

    float inv = 1.f / den;
    __half* dst = ctx + ((size_t)(b * 1024 + c * CHUNK + i)) * DMODEL + h * DH + db;
#pragma unroll
    for (int dd = 0; dd < 16; dd += 2)
        *(__half2*)&dst[dd] = __floats2half2_rn(num[dd] * inv, num[dd + 1] * inv);
}

// ---------------------------------------------------------------------------
static const int INTRA_SMEM = (2 * 64 * 65 + 3 * 64 * 64 + 64) * 4;
static const int GSM_128 = 4 * (128 * 80 + 32 * BROW);  // 75776
static const int GSM_64  = 4 * (64 * 80 + 32 * BROW);   // 55296

extern "C" void kernel_launch(void* const* d_in, const int* in_sizes, int n_in,
                              void* d_out, int out_size)
{
    const float* x      = (const float*)d_in[0];
    const float* ln1_g  = (const float*)d_in[1];
    const float* ln1_b  = (const float*)d_in[2];
    const float* w_attn = (const float*)d_in[3];
    const float* b_attn = (const float*)d_in[4];
    const float* w_feat = (const float*)d_in[5];
    const float* w_proj = (const float*)d_in[6];
    const float* b_proj = (const float*)d_in[7];
    const float* ln2_g  = (const float*)d_in[8];
    const float* ln2_b  = (const float*)d_in[9];
    const float* w_fc   = (const float*)d_in[10];
    const float* b_fc   = (const float*)d_in[11];
    const float* w_out  = (const float*)d_in[12];
    const float* b_out  = (const float*)d_in[13];
    float* out = (float*)d_out;

    float *qkv, *phiq, *phik, *kv, *kvp, *ks, *ksp, *x2;
    __half *ah, *ctxh, *ffnh, *wAh, *wPh, *wFh, *wOh;
    cudaGetSymbolAddress((void**)&qkv,  g_qkv);
    cudaGetSymbolAddress((void**)&phiq, g_phiq);
    cudaGetSymbolAddress((void**)&phik, g_phik);
    cudaGetSymbolAddress((void**)&kv,   g_kv);
    cudaGetSymbolAddress((void**)&kvp,  g_kvp);
    cudaGetSymbolAddress((void**)&ks,   g_ks);
    cudaGetSymbolAddress((void**)&ksp,  g_ksp);
    cudaGetSymbolAddress((void**)&x2,   g_x2);
    cudaGetSymbolAddress((void**)&ah,   g_ah);
    cudaGetSymbolAddress((void**)&ctxh, g_ctxh);
    cudaGetSymbolAddress((void**)&ffnh, g_ffnh);
    cudaGetSymbolAddress((void**)&wAh,  g_wAh);
    cudaGetSymbolAddress((void**)&wPh,  g_wPh);
    cudaGetSymbolAddress((void**)&wFh,  g_wFh);
    cudaGetSymbolAddress((void**)&wOh,  g_wOh);

    cudaFuncSetAttribute(intra_kernel,
        cudaFuncAttributeMaxDynamicSharedMemorySize, INTRA_SMEM);
    cudaFuncSetAttribute(hgemm<128, false, false, false>,
        cudaFuncAttributeMaxDynamicSharedMemorySize, GSM_128);
    cudaFuncSetAttribute(hgemm<128, true, false, true>,
        cudaFuncAttributeMaxDynamicSharedMemorySize, GSM_128);
    cudaFuncSetAttribute(hgemm<64, false, true, false>,
        cudaFuncAttributeMaxDynamicSharedMemorySize, GSM_64);

    // weight converts (elementwise, natural [K,N] layout)
    conv_half_kernel<<<(DMODEL * D3 / 8 + 255) / 256, 256>>>(w_attn, wAh, DMODEL * D3);
    conv_half_kernel<<<(DMODEL * DMODEL / 8 + 255) / 256, 256>>>(w_proj, wPh, DMODEL * DMODEL);
    conv_half_kernel<<<(DMODEL * DFF / 8 + 255) / 256, 256>>>(w_fc, wFh, DMODEL * DFF);
    conv_half_kernel<<<(DFF * DMODEL / 8 + 255) / 256, 256>>>(w_out, wOh, DFF * DMODEL);

    ln_kernel<<<ROWS, 256>>>(x, ln1_g, ln1_b, ah);
    hgemm<128, false, false, false><<<dim3(D3 / 128, ROWS / 128), 256, GSM_128>>>(
        ah, wAh, b_attn, nullptr, qkv, nullptr, D3, DMODEL);
    phi_kernel<<<dim3(32, BH, 2), 256>>>(qkv, w_feat, phiq, phik);
    chunkkv_kernel<<<dim3(NCHUNK, BH, 2), 256>>>(qkv, phik, kv, ks);
    scan_kernel<<<dim3(BH, 16), 256>>>(kv, ks, kvp, ksp);
    intra_kernel<<<dim3(NCHUNK, BH), 256, INTRA_SMEM>>>(qkv, phiq, phik, kvp, ksp, ctxh);
    hgemm<64, false, true, false><<<dim3(DMODEL / 128, ROWS / 64), 256, GSM_64>>>(
        ctxh, wPh, b_proj, x, x2, nullptr, DMODEL, DMODEL);
    ln_kernel<<<ROWS, 256>>>(x2, ln2_g, ln2_b, ah);
    hgemm<128, true, false, true><<<dim3(DFF / 128, ROWS / 128), 256, GSM_128>>>(
        ah, wFh, b_fc, nullptr, nullptr, ffnh, DFF, DMODEL);
    hgemm<64, false, true, false><<<dim3(DMODEL / 128, ROWS / 64), 256, GSM_64>>>(
        ffnh, wOh, b_out, x2, out, nullptr, DMODEL, DFF);
}

// round 15
// speedup vs baseline: 6.8688x; 1.1534x over previous
#include <cuda_runtime.h>
#include <cuda_fp16.h>
#include <math.h>
#include <stdint.h>

// ---------------------------------------------------------------------------
// B=2, S=1024, D=768, H=12, DH=64, M=64, DFF=3072, rows = 2048
// fp16 mma.sync GEMMs (4-stage cp.async) + tensorized intra-chunk attention.
// ---------------------------------------------------------------------------

#define ROWS   2048
#define DMODEL 768
#define D3     2304
#define DFF    3072
#define NH     12
#define BH     24
#define DH     64
#define MF     64
#define CHUNK  64
#define NCHUNK 16

__device__ float  g_qkv [ROWS * D3];
__device__ __half g_phiq[BH * 1024 * MF];
__device__ __half g_phik[BH * 1024 * MF];
__device__ float  g_kv  [BH * NCHUNK * MF * DH];
__device__ float  g_kvp [BH * NCHUNK * MF * DH];
__device__ float  g_ks  [BH * NCHUNK * MF];
__device__ float  g_ksp [BH * NCHUNK * MF];
__device__ float  g_x2  [ROWS * DMODEL];
__device__ __half g_ah  [ROWS * DMODEL];
__device__ __half g_ctxh[ROWS * DMODEL];
__device__ __half g_ffnh[ROWS * DFF];
__device__ __half g_wAh [DMODEL * D3];
__device__ __half g_wPh [DMODEL * DMODEL];
__device__ __half g_wFh [DMODEL * DFF];
__device__ __half g_wOh [DFF * DMODEL];

// ---------------------------------------------------------------------------
__device__ __forceinline__ void cp_async16s(unsigned saddr, const void* gsrc) {
    asm volatile("cp.async.cg.shared.global [%0], [%1], 16;\n"
                 :: "r"(saddr), "l"(gsrc));
}
__device__ __forceinline__ void cp_commit() {
    asm volatile("cp.async.commit_group;\n");
}
template <int N>
__device__ __forceinline__ void cp_wait() {
    asm volatile("cp.async.wait_group %0;\n" :: "n"(N));
}
__device__ __forceinline__ void ldsm_x4(unsigned& r0, unsigned& r1,
                                        unsigned& r2, unsigned& r3,
                                        unsigned addr) {
    asm volatile("ldmatrix.sync.aligned.m8n8.x4.shared.b16 {%0,%1,%2,%3}, [%4];"
                 : "=r"(r0), "=r"(r1), "=r"(r2), "=r"(r3) : "r"(addr));
}
__device__ __forceinline__ void ldsm_x4t(unsigned& r0, unsigned& r1,
                                         unsigned& r2, unsigned& r3,
                                         unsigned addr) {
    asm volatile("ldmatrix.sync.aligned.m8n8.x4.trans.shared.b16 {%0,%1,%2,%3}, [%4];"
                 : "=r"(r0), "=r"(r1), "=r"(r2), "=r"(r3) : "r"(addr));
}
__device__ __forceinline__ void mma_f16(float* d, const unsigned* a,
                                        unsigned b0, unsigned b1) {
    asm volatile(
        "mma.sync.aligned.m16n8k16.row.col.f32.f16.f16.f32 "
        "{%0,%1,%2,%3}, {%4,%5,%6,%7}, {%8,%9}, {%0,%1,%2,%3};\n"
        : "+f"(d[0]), "+f"(d[1]), "+f"(d[2]), "+f"(d[3])
        : "r"(a[0]), "r"(a[1]), "r"(a[2]), "r"(a[3]), "r"(b0), "r"(b1));
}

// ---------------------------------------------------------------------------
// fp16 GEMM: C[M,N] = A[M,K] @ W[K,N] + bias (+gelu) (+res)
// ---------------------------------------------------------------------------
#define BROW 272

template <int MT, bool GELU, bool RES, bool HOUT>
__global__ __launch_bounds__(256, 2)
void hgemm(const __half* __restrict__ A, const __half* __restrict__ W,
           const float* __restrict__ bias, const float* __restrict__ res,
           float* __restrict__ Cf, __half* __restrict__ Ch, int N, int K)
{
    constexpr int MI = MT / 32;
    constexpr int A_STAGE = MT * 80;
    constexpr int B_STAGE = 32 * BROW;

    extern __shared__ __align__(16) char dsm[];
    unsigned asb = (unsigned)__cvta_generic_to_shared(dsm);
    unsigned bsb = asb + 4 * A_STAGE;

    int t    = threadIdx.x;
    int lane = t & 31;
    int warp = t >> 5;
    int bm = blockIdx.y * MT;
    int bn = blockIdx.x * 128;
    int mbase = (warp >> 2) * (MT / 2);
    int nbase = (warp & 3) * 32;
    int g   = lane >> 2;
    int tig = lane & 3;

    const __half* Ag0 = A + (size_t)bm * K;

    auto load_tile = [&](int kt, int s) {
        const __half* Ag = Ag0 + (size_t)kt * 32;
        unsigned ab = asb + s * A_STAGE;
#pragma unroll
        for (int i = 0; i < MT / 64; i++) {
            int idx = i * 256 + t, row = idx >> 2, c = idx & 3;
            cp_async16s(ab + row * 80 + c * 16, Ag + (size_t)row * K + c * 8);
        }
        const __half* Bg = W + (size_t)(kt * 32) * N + bn;
        unsigned bb = bsb + s * B_STAGE;
#pragma unroll
        for (int i = 0; i < 2; i++) {
            int idx = i * 256 + t, r = idx >> 4, c = idx & 15;
            cp_async16s(bb + r * BROW + c * 16, Bg + (size_t)r * N + c * 8);
        }
        cp_commit();
    };

    int nk = K >> 5;
    load_tile(0, 0);
    load_tile(1, 1);
    load_tile(2, 2);

    float acc[MI][4][4];
#pragma unroll
    for (int i = 0; i < MI; i++)
#pragma unroll
        for (int j = 0; j < 4; j++)
#pragma unroll
            for (int r = 0; r < 4; r++) acc[i][j][r] = 0.f;

    int a_r  = lane & 15;
    int a_kh = (lane >> 4) * 8;
    int b_r   = lane & 7;
    int b_mi  = lane >> 3;
    int b_kh2 = (b_mi & 1) * 8;
    int b_no  = (b_mi >> 1) * 8;

    for (int kt = 0; kt < nk; kt++) {
        int s = kt & 3;
        cp_wait<2>();
        __syncthreads();
        if (kt + 3 < nk) load_tile(kt + 3, (kt + 3) & 3);
        else cp_commit();

        unsigned as_s = asb + s * A_STAGE;
        unsigned bs_s = bsb + s * B_STAGE;
#pragma unroll
        for (int ks = 0; ks < 2; ks++) {
            int kb = ks * 16;
            unsigned af[MI][4], bfA[4], bfB[4];
#pragma unroll
            for (int i = 0; i < MI; i++) {
                unsigned addr = as_s + (mbase + i * 16 + a_r) * 80
                              + (kb + a_kh) * 2;
                ldsm_x4(af[i][0], af[i][1], af[i][2], af[i][3], addr);
            }
            unsigned brow = bs_s + (kb + b_kh2 + b_r) * BROW;
            ldsm_x4t(bfA[0], bfA[1], bfA[2], bfA[3],
                     brow + (nbase + b_no) * 2);
            ldsm_x4t(bfB[0], bfB[1], bfB[2], bfB[3],
                     brow + (nbase + 16 + b_no) * 2);
#pragma unroll
            for (int i = 0; i < MI; i++) {
                mma_f16(acc[i][0], af[i], bfA[0], bfA[1]);
                mma_f16(acc[i][1], af[i], bfA[2], bfA[3]);
                mma_f16(acc[i][2], af[i], bfB[0], bfB[1]);
                mma_f16(acc[i][3], af[i], bfB[2], bfB[3]);
            }
        }
    }

#pragma unroll
    for (int i = 0; i < MI; i++) {
#pragma unroll
        for (int j = 0; j < 4; j++) {
            int col = bn + nbase + j * 8 + 2 * tig;
            float b0 = bias[col], b1 = bias[col + 1];
#pragma unroll
            for (int half = 0; half < 2; half++) {
                int row = bm + mbase + i * 16 + g + half * 8;
                float v0 = acc[i][j][half * 2 + 0] + b0;
                float v1 = acc[i][j][half * 2 + 1] + b1;
                if (GELU) {
                    float u = v0, cu = u + 0.044715f * u * u * u;
                    v0 = 0.5f * u * (1.f + tanhf(0.7978845608028654f * cu));
                    u = v1; cu = u + 0.044715f * u * u * u;
                    v1 = 0.5f * u * (1.f + tanhf(0.7978845608028654f * cu));
                }
                if (RES) {
                    v0 += res[(size_t)row * N + col];
                    v1 += res[(size_t)row * N + col + 1];
                }
                if (HOUT) {
                    *(__half2*)&Ch[(size_t)row * N + col] =
                        __floats2half2_rn(v0, v1);
                } else {
                    *(float2*)&Cf[(size_t)row * N + col] = make_float2(v0, v1);
                }
            }
        }
    }
}

// ---------------------------------------------------------------------------
// merged fp32 -> fp16 convert for all four weights (one launch)
// ---------------------------------------------------------------------------
#define NW1 (DMODEL * D3)
#define NW2 (DMODEL * DMODEL)
#define NW3 (DMODEL * DFF)
#define NW4 (DFF * DMODEL)

__global__ void conv4_kernel(const float* __restrict__ s1, const float* __restrict__ s2,
                             const float* __restrict__ s3, const float* __restrict__ s4,
                             __half* __restrict__ d1, __half* __restrict__ d2,
                             __half* __restrict__ d3, __half* __restrict__ d4)
{
    long i = (long)(blockIdx.x * 256 + threadIdx.x) * 8;
    const float* s; __half* d; long off;
    if      (i < NW1)                   { s = s1; d = d1; off = i; }
    else if (i < NW1 + NW2)             { s = s2; d = d2; off = i - NW1; }
    else if (i < NW1 + NW2 + NW3)       { s = s3; d = d3; off = i - NW1 - NW2; }
    else if (i < NW1 + NW2 + NW3 + NW4) { s = s4; d = d4; off = i - NW1 - NW2 - NW3; }
    else return;
    float4 a = *(const float4*)(s + off);
    float4 b = *(const float4*)(s + off + 4);
    union { __half2 h[4]; uint4 v; } u;
    u.h[0] = __floats2half2_rn(a.x, a.y);
    u.h[1] = __floats2half2_rn(a.z, a.w);
    u.h[2] = __floats2half2_rn(b.x, b.y);
    u.h[3] = __floats2half2_rn(b.z, b.w);
    *(uint4*)(d + off) = u.v;
}

// ---------------------------------------------------------------------------
// LayerNorm -> half
// ---------------------------------------------------------------------------
__global__ void ln_kernel(const float* __restrict__ in,
                          const float* __restrict__ gamma,
                          const float* __restrict__ beta,
                          __half* __restrict__ out)
{
    int row = blockIdx.x;
    int t = threadIdx.x;
    const float* p = in + (size_t)row * DMODEL;
    float v[3];
    float s = 0.f, s2 = 0.f;
#pragma unroll
    for (int i = 0; i < 3; i++) {
        v[i] = p[t + i * 256];
        s += v[i];
        s2 += v[i] * v[i];
    }
#pragma unroll
    for (int o = 16; o; o >>= 1) {
        s  += __shfl_xor_sync(0xffffffffu, s, o);
        s2 += __shfl_xor_sync(0xffffffffu, s2, o);
    }
    __shared__ float ss[8], ss2[8];
    if ((t & 31) == 0) { ss[t >> 5] = s; ss2[t >> 5] = s2; }
    __syncthreads();
    s = 0.f; s2 = 0.f;
#pragma unroll
    for (int i = 0; i < 8; i++) { s += ss[i]; s2 += ss2[i]; }
    float mu  = s * (1.f / DMODEL);
    float var = s2 * (1.f / DMODEL) - mu * mu;
    float rstd = rsqrtf(var + 1e-5f);
    __half* q = out + (size_t)row * DMODEL;
#pragma unroll
    for (int i = 0; i < 3; i++) {
        int c = t + i * 256;
        q[c] = __float2half_rn((v[i] - mu) * rstd * gamma[c] + beta[c]);
    }
}

// ---------------------------------------------------------------------------
// FAVOR+ features -> HALF phi outputs
// ---------------------------------------------------------------------------
__global__ __launch_bounds__(256)
void phi_kernel(const float* __restrict__ qkv,
                const float* __restrict__ wf,
                __half* __restrict__ phiq,
                __half* __restrict__ phik)
{
    int grp = blockIdx.x;
    int bh  = blockIdx.y;
    int isk = blockIdx.z;
    int h = bh % NH, b = bh / NH;
    int t = threadIdx.x;

    __shared__ float wfs[64][65];
    __shared__ float xs[32][65];
    __shared__ float sqs[32];

    for (int i = t; i < 4096; i += 256) {
        int m = i >> 6, d = i & 63;
        wfs[d][m] = wf[i];
    }
    int base_s = grp * 32;
    for (int i = t; i < 32 * 64; i += 256) {
        int tok = i >> 6, d = i & 63;
        xs[tok][d] = qkv[((size_t)(b * 1024 + base_s + tok)) * D3
                         + isk * DMODEL + h * DH + d] * 0.3535533905932738f;
    }
    __syncthreads();
    if (t < 32) {
        float sq = 0.f;
#pragma unroll 16
        for (int d = 0; d < 64; d++) sq += xs[t][d] * xs[t][d];
        sqs[t] = 0.5f * sq;
    }
    __syncthreads();

    int m = t & 63;
    __half* dst = (isk ? phik : phiq);
#pragma unroll
    for (int it = 0; it < 8; it++) {
        int tok = (t >> 6) * 8 + it;
        float proj = 0.f;
#pragma unroll 16
        for (int d = 0; d < 64; d++) proj += xs[tok][d] * wfs[d][m];
        dst[((size_t)bh * 1024 + base_s + tok) * MF + m] =
            __float2half_rn(expf(proj - sqs[tok]) * 0.125f + 1e-6f);
    }
}

// ---------------------------------------------------------------------------
// Per-chunk KV state (phik now half), d-split x2: grid (NCHUNK, BH, 2)
// ---------------------------------------------------------------------------
__global__ void chunkkv_kernel(const float* __restrict__ qkv,
                               const __half* __restrict__ phik,
                               float* __restrict__ kvs,
                               float* __restrict__ ks)
{
    int c  = blockIdx.x;
    int bh = blockIdx.y;
    int z  = blockIdx.z;
    int h = bh % NH, b = bh / NH;
    int t = threadIdx.x;

    __shared__ float pk[CHUNK][MF];
    __shared__ float sv[CHUNK][32];

    for (int i = t; i < CHUNK * 64; i += 256) {
        int s = i >> 6, d = i & 63;
        pk[s][d] = __half2float(phik[((size_t)bh * 1024 + c * CHUNK + s) * MF + d]);
    }
    for (int i = t; i < CHUNK * 32; i += 256) {
        int s = i >> 5, d = i & 31;
        sv[s][d] = qkv[((size_t)(b * 1024 + c * CHUNK + s)) * D3
                       + 2 * DMODEL + h * DH + z * 32 + d];
    }
    __syncthreads();

    int m  = t & 63;
    int dl = (t >> 6) * 8;
    float acc[8];
#pragma unroll
    for (int j = 0; j < 8; j++) acc[j] = 0.f;
    float sksum = 0.f;

    for (int s = 0; s < CHUNK; s++) {
        float pkm = pk[s][m];
        if (dl == 0) sksum += pkm;
#pragma unroll
        for (int j = 0; j < 8; j++) acc[j] += pkm * sv[s][dl + j];
    }
    float* dst = kvs + ((size_t)bh * NCHUNK + c) * (MF * DH) + m * DH + z * 32 + dl;
#pragma unroll
    for (int j = 0; j < 8; j++) dst[j] = acc[j];
    if (z == 0 && dl == 0) ks[((size_t)bh * NCHUNK + c) * MF + m] = sksum;
}

// ---------------------------------------------------------------------------
// Exclusive prefix over chunk states
// ---------------------------------------------------------------------------
__global__ void scan_kernel(const float* __restrict__ kvs,
                            const float* __restrict__ ks,
                            float* __restrict__ kvp,
                            float* __restrict__ ksp)
{
    int bh = blockIdx.x;
    int grp = blockIdx.y;
    int t = threadIdx.x;
    int idx = grp * 256 + t;

    float acc = 0.f;
    size_t base = (size_t)bh * NCHUNK * (MF * DH) + idx;
#pragma unroll
    for (int c = 0; c < NCHUNK; c++) {
        float v = kvs[base + (size_t)c * (MF * DH)];
        kvp[base + (size_t)c * (MF * DH)] = acc;
        acc += v;
    }
    if (grp == 0 && t < MF) {
        float a2 = 0.f;
        size_t kb = (size_t)bh * NCHUNK * MF + t;
#pragma unroll
        for (int c = 0; c < NCHUNK; c++) {
            float v = ks[kb + (size_t)c * MF];
            ksp[kb + (size_t)c * MF] = a2;
            a2 += v;
        }
    }
}

// ---------------------------------------------------------------------------
// Tensorized intra-chunk causal combine.
// Phase 1: A = phi_q @ phi_k^T (mma, fp32 acc), causal mask, store A half.
// Phase 2: [A | phi_q](64x128) @ [[V, 1];[KVpre, kspre]](128x72) -> num|den.
// 128 threads (4 warps x 16 rows). Smem: pkh[64][72], Xh[64][136], Wh[128][168].
// ---------------------------------------------------------------------------
#define XROW 136
#define WROW 168

__global__ __launch_bounds__(128)
void intra_kernel(const float* __restrict__ qkv,
                  const __half* __restrict__ phiq,
                  const __half* __restrict__ phik,
                  const float* __restrict__ kvpre,
                  const float* __restrict__ kspre,
                  __half* __restrict__ ctx)
{
    extern __shared__ __align__(16) char ism[];
    __half* pkh = (__half*)ism;                    // 64*72
    __half* Xh  = (__half*)(ism + 9216);           // 64*136
    __half* Wh  = (__half*)(ism + 9216 + 17408);   // 128*168
    unsigned pksb = (unsigned)__cvta_generic_to_shared(pkh);
    unsigned xsb  = (unsigned)__cvta_generic_to_shared(Xh);
    unsigned wsb  = (unsigned)__cvta_generic_to_shared(Wh);

    int c  = blockIdx.x;
    int bh = blockIdx.y;
    int h = bh % NH, b = bh / NH;
    int t = threadIdx.x;
    int lane = t & 31, warp = t >> 5;
    int g = lane >> 2, tig = lane & 3;

    // ---- stage ----
    const __half* pkg = phik + ((size_t)bh * 1024 + c * CHUNK) * MF;
    const __half* pqg = phiq + ((size_t)bh * 1024 + c * CHUNK) * MF;
#pragma unroll
    for (int k = 0; k < 4; k++) {                 // 512 16B chunks
        int idx = t + k * 128, r = idx >> 3, ch = idx & 7;
        uint4 vk = *(const uint4*)(pkg + (size_t)r * MF + ch * 8);
        *(uint4*)(pkh + r * 72 + ch * 8) = vk;
        uint4 vq = *(const uint4*)(pqg + (size_t)r * MF + ch * 8);
        *(uint4*)(Xh + r * XROW + 64 + ch * 8) = vq;
    }
    size_t kvbase = ((size_t)bh * NCHUNK + c) * (MF * DH);
#pragma unroll
    for (int k = 0; k < 8; k++) {                 // 1024 float4 chunks
        int idx = t + k * 128, r = idx >> 4, ch = idx & 15;
        float4 fv = *(const float4*)(qkv + ((size_t)(b * 1024 + c * CHUNK + r)) * D3
                                     + 2 * DMODEL + h * DH + ch * 4);
        __half2 h0 = __floats2half2_rn(fv.x, fv.y);
        __half2 h1 = __floats2half2_rn(fv.z, fv.w);
        *(__half2*)(Wh + r * WROW + ch * 4)     = h0;
        *(__half2*)(Wh + r * WROW + ch * 4 + 2) = h1;
        float4 fk = *(const float4*)(kvpre + kvbase + (size_t)r * DH + ch * 4);
        h0 = __floats2half2_rn(fk.x, fk.y);
        h1 = __floats2half2_rn(fk.z, fk.w);
        *(__half2*)(Wh + (64 + r) * WROW + ch * 4)     = h0;
        *(__half2*)(Wh + (64 + r) * WROW + ch * 4 + 2) = h1;
    }
    {   // col 64 = ones / kspre; cols 65..79 = 0
        int r = t;
        __half c64 = (r < 64) ? __float2half(1.f)
                   : __float2half_rn(kspre[((size_t)bh * NCHUNK + c) * MF + (r - 64)]);
        Wh[r * WROW + 64] = c64;
#pragma unroll
        for (int cc = 65; cc < 80; cc++) Wh[r * WROW + cc] = __float2half(0.f);
    }
    __syncthreads();

    // fragment index components
    int a_r  = lane & 15;
    int a_kh = (lane >> 4) * 8;
    int b_n  = ((lane >> 4) << 3) + (lane & 7);   // [N,K] non-trans mapping
    int b_kh = ((lane >> 3) & 1) * 8;
    int b_r   = lane & 7;                          // [K,N] trans mapping
    int b_mi  = lane >> 3;
    int b_kh2 = (b_mi & 1) * 8;
    int b_no  = (b_mi >> 1) * 8;

    int rbase = warp * 16;

    // ---- phase 1: A = pq @ pk^T ----
    float acc1[8][4];
#pragma unroll
    for (int j = 0; j < 8; j++)
#pragma unroll
        for (int r = 0; r < 4; r++) acc1[j][r] = 0.f;

#pragma unroll
    for (int ks = 0; ks < 4; ks++) {
        int kb = ks * 16;
        unsigned af[4];
        ldsm_x4(af[0], af[1], af[2], af[3],
                xsb + (rbase + a_r) * (XROW * 2) + (64 + kb + a_kh) * 2);
#pragma unroll
        for (int j16 = 0; j16 < 4; j16++) {
            unsigned bf[4];
            ldsm_x4(bf[0], bf[1], bf[2], bf[3],
                    pksb + (j16 * 16 + b_n) * 144 + (kb + b_kh) * 2);
            mma_f16(acc1[j16 * 2],     af, bf[0], bf[1]);
            mma_f16(acc1[j16 * 2 + 1], af, bf[2], bf[3]);
        }
    }
    // causal mask + store A (half) into Xh cols 0..63
    {
        int row0 = rbase + g, row1 = row0 + 8;
#pragma unroll
        for (int j = 0; j < 8; j++) {
            int col = j * 8 + 2 * tig;
            __half2 v0 = __floats2half2_rn(col <= row0 ? acc1[j][0] : 0.f,
                                           col + 1 <= row0 ? acc1[j][1] : 0.f);
            __half2 v1 = __floats2half2_rn(col <= row1 ? acc1[j][2] : 0.f,
                                           col + 1 <= row1 ? acc1[j][3] : 0.f);
            *(__half2*)(Xh + row0 * XROW + col) = v0;
            *(__half2*)(Xh + row1 * XROW + col) = v1;
        }
    }
    __syncthreads();

    // ---- phase 2: [A|pq] @ Wh ----
    float acc2[9][4];
#pragma unroll
    for (int j = 0; j < 9; j++)
#pragma unroll
        for (int r = 0; r < 4; r++) acc2[j][r] = 0.f;

#pragma unroll
    for (int ks = 0; ks < 8; ks++) {
        int kb = ks * 16;
        unsigned af[4];
        ldsm_x4(af[0], af[1], af[2], af[3],
                xsb + (rbase + a_r) * (XROW * 2) + (kb + a_kh) * 2);
        unsigned brow = wsb + (kb + b_kh2 + b_r) * (WROW * 2);
#pragma unroll
        for (int p = 0; p < 4; p++) {
            unsigned bf[4];
            ldsm_x4t(bf[0], bf[1], bf[2], bf[3], brow + (p * 16 + b_no) * 2);
            mma_f16(acc2[p * 2],     af, bf[0], bf[1]);
            mma_f16(acc2[p * 2 + 1], af, bf[2], bf[3]);
        }
        unsigned bf[4];
        ldsm_x4t(bf[0], bf[1], bf[2], bf[3], brow + (64 + b_no) * 2);
        mma_f16(acc2[8], af, bf[0], bf[1]);
    }

    // den broadcast within quad (den lives at col 64 -> tig==0)
    float den0 = __shfl_sync(0xffffffffu, acc2[8][0], lane & ~3);
    float den1 = __shfl_sync(0xffffffffu, acc2[8][2], lane & ~3);
    float inv0 = 1.f / den0, inv1 = 1.f / den1;

    int row0 = rbase + g, row1 = row0 + 8;
    __half* c0 = ctx + ((size_t)(b * 1024 + c * CHUNK + row0)) * DMODEL + h * DH;
    __half* c1 = ctx + ((size_t)(b * 1024 + c * CHUNK + row1)) * DMODEL + h * DH;
#pragma unroll
    for (int j = 0; j < 8; j++) {
        int col = j * 8 + 2 * tig;
        *(__half2*)(c0 + col) = __floats2half2_rn(acc2[j][0] * inv0, acc2[j][1] * inv0);
        *(__half2*)(c1 + col) = __floats2half2_rn(acc2[j][2] * inv1, acc2[j][3] * inv1);
    }
}

// ---------------------------------------------------------------------------
static const int INTRA_SMEM = 9216 + 17408 + 43008;     // 69632
static const int GSM_128 = 4 * (128 * 80 + 32 * BROW);  // 75776
static const int GSM_64  = 4 * (64 * 80 + 32 * BROW);   // 55296

extern "C" void kernel_launch(void* const* d_in, const int* in_sizes, int n_in,
                              void* d_out, int out_size)
{
    const float* x      = (const float*)d_in[0];
    const float* ln1_g  = (const float*)d_in[1];
    const float* ln1_b  = (const float*)d_in[2];
    const float* w_attn = (const float*)d_in[3];
    const float* b_attn = (const float*)d_in[4];
    const float* w_feat = (const float*)d_in[5];
    const float* w_proj = (const float*)d_in[6];
    const float* b_proj = (const float*)d_in[7];
    const float* ln2_g  = (const float*)d_in[8];
    const float* ln2_b  = (const float*)d_in[9];
    const float* w_fc   = (const float*)d_in[10];
    const float* b_fc   = (const float*)d_in[11];
    const float* w_out  = (const float*)d_in[12];
    const float* b_out  = (const float*)d_in[13];
    float* out = (float*)d_out;

    float *qkv, *kv, *kvp, *ks, *ksp, *x2;
    __half *phiq, *phik, *ah, *ctxh, *ffnh, *wAh, *wPh, *wFh, *wOh;
    cudaGetSymbolAddress((void**)&qkv,  g_qkv);
    cudaGetSymbolAddress((void**)&phiq, g_phiq);
    cudaGetSymbolAddress((void**)&phik, g_phik);
    cudaGetSymbolAddress((void**)&kv,   g_kv);
    cudaGetSymbolAddress((void**)&kvp,  g_kvp);
    cudaGetSymbolAddress((void**)&ks,   g_ks);
    cudaGetSymbolAddress((void**)&ksp,  g_ksp);
    cudaGetSymbolAddress((void**)&x2,   g_x2);
    cudaGetSymbolAddress((void**)&ah,   g_ah);
    cudaGetSymbolAddress((void**)&ctxh, g_ctxh);
    cudaGetSymbolAddress((void**)&ffnh, g_ffnh);
    cudaGetSymbolAddress((void**)&wAh,  g_wAh);
    cudaGetSymbolAddress((void**)&wPh,  g_wPh);
    cudaGetSymbolAddress((void**)&wFh,  g_wFh);
    cudaGetSymbolAddress((void**)&wOh,  g_wOh);

    cudaFuncSetAttribute(intra_kernel,
        cudaFuncAttributeMaxDynamicSharedMemorySize, INTRA_SMEM);
    cudaFuncSetAttribute(hgemm<128, false, false, false>,
        cudaFuncAttributeMaxDynamicSharedMemorySize, GSM_128);
    cudaFuncSetAttribute(hgemm<128, true, false, true>,
        cudaFuncAttributeMaxDynamicSharedMemorySize, GSM_128);
    cudaFuncSetAttribute(hgemm<64, false, true, false>,
        cudaFuncAttributeMaxDynamicSharedMemorySize, GSM_64);

    // merged weight convert (one launch)
    conv4_kernel<<<(NW1 + NW2 + NW3 + NW4) / 8 / 256, 256>>>(
        w_attn, w_proj, w_fc, w_out, wAh, wPh, wFh, wOh);

    ln_kernel<<<ROWS, 256>>>(x, ln1_g, ln1_b, ah);
    hgemm<128, false, false, false><<<dim3(D3 / 128, ROWS / 128), 256, GSM_128>>>(
        ah, wAh, b_attn, nullptr, qkv, nullptr, D3, DMODEL);
    phi_kernel<<<dim3(32, BH, 2), 256>>>(qkv, w_feat, phiq, phik);
    chunkkv_kernel<<<dim3(NCHUNK, BH, 2), 256>>>(qkv, phik, kv, ks);
    scan_kernel<<<dim3(BH, 16), 256>>>(kv, ks, kvp, ksp);
    intra_kernel<<<dim3(NCHUNK, BH), 128, INTRA_SMEM>>>(qkv, phiq, phik, kvp, ksp, ctxh);
    hgemm<64, false, true, false><<<dim3(DMODEL / 128, ROWS / 64), 256, GSM_64>>>(
        ctxh, wPh, b_proj, x, x2, nullptr, DMODEL, DMODEL);
    ln_kernel<<<ROWS, 256>>>(x2, ln2_g, ln2_b, ah);
    hgemm<128, true, false, true><<<dim3(DFF / 128, ROWS / 128), 256, GSM_128>>>(
        ah, wFh, b_fc, nullptr, nullptr, ffnh, DFF, DMODEL);
    hgemm<64, false, true, false><<<dim3(DMODEL / 128, ROWS / 64), 256, GSM_64>>>(
        ffnh, wOh, b_out, x2, out, nullptr, DMODEL, DFF);
}

// round 16
// speedup vs baseline: 7.7322x; 1.1257x over previous
#include <cuda_runtime.h>
#include <cuda_fp16.h>
#include <math.h>
#include <stdint.h>

// ---------------------------------------------------------------------------
// B=2, S=1024, D=768, H=12, DH=64, M=64, DFF=3072, rows = 2048
// fp16 mma.sync GEMMs (4-stage cp.async) + tensorized intra-chunk attention.
// phi with vectorized (float4) smem dot products.
// ---------------------------------------------------------------------------

#define ROWS   2048
#define DMODEL 768
#define D3     2304
#define DFF    3072
#define NH     12
#define BH     24
#define DH     64
#define MF     64
#define CHUNK  64
#define NCHUNK 16

__device__ float  g_qkv [ROWS * D3];
__device__ __half g_phiq[BH * 1024 * MF];
__device__ __half g_phik[BH * 1024 * MF];
__device__ float  g_kv  [BH * NCHUNK * MF * DH];
__device__ float  g_kvp [BH * NCHUNK * MF * DH];
__device__ float  g_ks  [BH * NCHUNK * MF];
__device__ float  g_ksp [BH * NCHUNK * MF];
__device__ float  g_x2  [ROWS * DMODEL];
__device__ __half g_ah  [ROWS * DMODEL];
__device__ __half g_ctxh[ROWS * DMODEL];
__device__ __half g_ffnh[ROWS * DFF];
__device__ __half g_wAh [DMODEL * D3];
__device__ __half g_wPh [DMODEL * DMODEL];
__device__ __half g_wFh [DMODEL * DFF];
__device__ __half g_wOh [DFF * DMODEL];

// ---------------------------------------------------------------------------
__device__ __forceinline__ void cp_async16s(unsigned saddr, const void* gsrc) {
    asm volatile("cp.async.cg.shared.global [%0], [%1], 16;\n"
                 :: "r"(saddr), "l"(gsrc));
}
__device__ __forceinline__ void cp_commit() {
    asm volatile("cp.async.commit_group;\n");
}
template <int N>
__device__ __forceinline__ void cp_wait() {
    asm volatile("cp.async.wait_group %0;\n" :: "n"(N));
}
__device__ __forceinline__ void ldsm_x4(unsigned& r0, unsigned& r1,
                                        unsigned& r2, unsigned& r3,
                                        unsigned addr) {
    asm volatile("ldmatrix.sync.aligned.m8n8.x4.shared.b16 {%0,%1,%2,%3}, [%4];"
                 : "=r"(r0), "=r"(r1), "=r"(r2), "=r"(r3) : "r"(addr));
}
__device__ __forceinline__ void ldsm_x4t(unsigned& r0, unsigned& r1,
                                         unsigned& r2, unsigned& r3,
                                         unsigned addr) {
    asm volatile("ldmatrix.sync.aligned.m8n8.x4.trans.shared.b16 {%0,%1,%2,%3}, [%4];"
                 : "=r"(r0), "=r"(r1), "=r"(r2), "=r"(r3) : "r"(addr));
}
__device__ __forceinline__ void mma_f16(float* d, const unsigned* a,
                                        unsigned b0, unsigned b1) {
    asm volatile(
        "mma.sync.aligned.m16n8k16.row.col.f32.f16.f16.f32 "
        "{%0,%1,%2,%3}, {%4,%5,%6,%7}, {%8,%9}, {%0,%1,%2,%3};\n"
        : "+f"(d[0]), "+f"(d[1]), "+f"(d[2]), "+f"(d[3])
        : "r"(a[0]), "r"(a[1]), "r"(a[2]), "r"(a[3]), "r"(b0), "r"(b1));
}

// ---------------------------------------------------------------------------
// fp16 GEMM: C[M,N] = A[M,K] @ W[K,N] + bias (+gelu) (+res)
// ---------------------------------------------------------------------------
#define BROW 272

template <int MT, bool GELU, bool RES, bool HOUT>
__global__ __launch_bounds__(256, 2)
void hgemm(const __half* __restrict__ A, const __half* __restrict__ W,
           const float* __restrict__ bias, const float* __restrict__ res,
           float* __restrict__ Cf, __half* __restrict__ Ch, int N, int K)
{
    constexpr int MI = MT / 32;
    constexpr int A_STAGE = MT * 80;
    constexpr int B_STAGE = 32 * BROW;

    extern __shared__ __align__(16) char dsm[];
    unsigned asb = (unsigned)__cvta_generic_to_shared(dsm);
    unsigned bsb = asb + 4 * A_STAGE;

    int t    = threadIdx.x;
    int lane = t & 31;
    int warp = t >> 5;
    int bm = blockIdx.y * MT;
    int bn = blockIdx.x * 128;
    int mbase = (warp >> 2) * (MT / 2);
    int nbase = (warp & 3) * 32;
    int g   = lane >> 2;
    int tig = lane & 3;

    const __half* Ag0 = A + (size_t)bm * K;

    auto load_tile = [&](int kt, int s) {
        const __half* Ag = Ag0 + (size_t)kt * 32;
        unsigned ab = asb + s * A_STAGE;
#pragma unroll
        for (int i = 0; i < MT / 64; i++) {
            int idx = i * 256 + t, row = idx >> 2, c = idx & 3;
            cp_async16s(ab + row * 80 + c * 16, Ag + (size_t)row * K + c * 8);
        }
        const __half* Bg = W + (size_t)(kt * 32) * N + bn;
        unsigned bb = bsb + s * B_STAGE;
#pragma unroll
        for (int i = 0; i < 2; i++) {
            int idx = i * 256 + t, r = idx >> 4, c = idx & 15;
            cp_async16s(bb + r * BROW + c * 16, Bg + (size_t)r * N + c * 8);
        }
        cp_commit();
    };

    int nk = K >> 5;
    load_tile(0, 0);
    load_tile(1, 1);
    load_tile(2, 2);

    float acc[MI][4][4];
#pragma unroll
    for (int i = 0; i < MI; i++)
#pragma unroll
        for (int j = 0; j < 4; j++)
#pragma unroll
            for (int r = 0; r < 4; r++) acc[i][j][r] = 0.f;

    int a_r  = lane & 15;
    int a_kh = (lane >> 4) * 8;
    int b_r   = lane & 7;
    int b_mi  = lane >> 3;
    int b_kh2 = (b_mi & 1) * 8;
    int b_no  = (b_mi >> 1) * 8;

    for (int kt = 0; kt < nk; kt++) {
        int s = kt & 3;
        cp_wait<2>();
        __syncthreads();
        if (kt + 3 < nk) load_tile(kt + 3, (kt + 3) & 3);
        else cp_commit();

        unsigned as_s = asb + s * A_STAGE;
        unsigned bs_s = bsb + s * B_STAGE;
#pragma unroll
        for (int ks = 0; ks < 2; ks++) {
            int kb = ks * 16;
            unsigned af[MI][4], bfA[4], bfB[4];
#pragma unroll
            for (int i = 0; i < MI; i++) {
                unsigned addr = as_s + (mbase + i * 16 + a_r) * 80
                              + (kb + a_kh) * 2;
                ldsm_x4(af[i][0], af[i][1], af[i][2], af[i][3], addr);
            }
            unsigned brow = bs_s + (kb + b_kh2 + b_r) * BROW;
            ldsm_x4t(bfA[0], bfA[1], bfA[2], bfA[3],
                     brow + (nbase + b_no) * 2);
            ldsm_x4t(bfB[0], bfB[1], bfB[2], bfB[3],
                     brow + (nbase + 16 + b_no) * 2);
#pragma unroll
            for (int i = 0; i < MI; i++) {
                mma_f16(acc[i][0], af[i], bfA[0], bfA[1]);
                mma_f16(acc[i][1], af[i], bfA[2], bfA[3]);
                mma_f16(acc[i][2], af[i], bfB[0], bfB[1]);
                mma_f16(acc[i][3], af[i], bfB[2], bfB[3]);
            }
        }
    }

#pragma unroll
    for (int i = 0; i < MI; i++) {
#pragma unroll
        for (int j = 0; j < 4; j++) {
            int col = bn + nbase + j * 8 + 2 * tig;
            float b0 = bias[col], b1 = bias[col + 1];
#pragma unroll
            for (int half = 0; half < 2; half++) {
                int row = bm + mbase + i * 16 + g + half * 8;
                float v0 = acc[i][j][half * 2 + 0] + b0;
                float v1 = acc[i][j][half * 2 + 1] + b1;
                if (GELU) {
                    float u = v0, cu = u + 0.044715f * u * u * u;
                    v0 = 0.5f * u * (1.f + tanhf(0.7978845608028654f * cu));
                    u = v1; cu = u + 0.044715f * u * u * u;
                    v1 = 0.5f * u * (1.f + tanhf(0.7978845608028654f * cu));
                }
                if (RES) {
                    v0 += res[(size_t)row * N + col];
                    v1 += res[(size_t)row * N + col + 1];
                }
                if (HOUT) {
                    *(__half2*)&Ch[(size_t)row * N + col] =
                        __floats2half2_rn(v0, v1);
                } else {
                    *(float2*)&Cf[(size_t)row * N + col] = make_float2(v0, v1);
                }
            }
        }
    }
}

// ---------------------------------------------------------------------------
// merged fp32 -> fp16 convert for all four weights (one launch)
// ---------------------------------------------------------------------------
#define NW1 (DMODEL * D3)
#define NW2 (DMODEL * DMODEL)
#define NW3 (DMODEL * DFF)
#define NW4 (DFF * DMODEL)

__global__ void conv4_kernel(const float* __restrict__ s1, const float* __restrict__ s2,
                             const float* __restrict__ s3, const float* __restrict__ s4,
                             __half* __restrict__ d1, __half* __restrict__ d2,
                             __half* __restrict__ d3, __half* __restrict__ d4)
{
    long i = (long)(blockIdx.x * 256 + threadIdx.x) * 8;
    const float* s; __half* d; long off;
    if      (i < NW1)                   { s = s1; d = d1; off = i; }
    else if (i < NW1 + NW2)             { s = s2; d = d2; off = i - NW1; }
    else if (i < NW1 + NW2 + NW3)       { s = s3; d = d3; off = i - NW1 - NW2; }
    else if (i < NW1 + NW2 + NW3 + NW4) { s = s4; d = d4; off = i - NW1 - NW2 - NW3; }
    else return;
    float4 a = *(const float4*)(s + off);
    float4 b = *(const float4*)(s + off + 4);
    union { __half2 h[4]; uint4 v; } u;
    u.h[0] = __floats2half2_rn(a.x, a.y);
    u.h[1] = __floats2half2_rn(a.z, a.w);
    u.h[2] = __floats2half2_rn(b.x, b.y);
    u.h[3] = __floats2half2_rn(b.z, b.w);
    *(uint4*)(d + off) = u.v;
}

// ---------------------------------------------------------------------------
// LayerNorm -> half
// ---------------------------------------------------------------------------
__global__ void ln_kernel(const float* __restrict__ in,
                          const float* __restrict__ gamma,
                          const float* __restrict__ beta,
                          __half* __restrict__ out)
{
    int row = blockIdx.x;
    int t = threadIdx.x;
    const float* p = in + (size_t)row * DMODEL;
    float v[3];
    float s = 0.f, s2 = 0.f;
#pragma unroll
    for (int i = 0; i < 3; i++) {
        v[i] = p[t + i * 256];
        s += v[i];
        s2 += v[i] * v[i];
    }
#pragma unroll
    for (int o = 16; o; o >>= 1) {
        s  += __shfl_xor_sync(0xffffffffu, s, o);
        s2 += __shfl_xor_sync(0xffffffffu, s2, o);
    }
    __shared__ float ss[8], ss2[8];
    if ((t & 31) == 0) { ss[t >> 5] = s; ss2[t >> 5] = s2; }
    __syncthreads();
    s = 0.f; s2 = 0.f;
#pragma unroll
    for (int i = 0; i < 8; i++) { s += ss[i]; s2 += ss2[i]; }
    float mu  = s * (1.f / DMODEL);
    float var = s2 * (1.f / DMODEL) - mu * mu;
    float rstd = rsqrtf(var + 1e-5f);
    __half* q = out + (size_t)row * DMODEL;
#pragma unroll
    for (int i = 0; i < 3; i++) {
        int c = t + i * 256;
        q[c] = __float2half_rn((v[i] - mu) * rstd * gamma[c] + beta[c]);
    }
}

// ---------------------------------------------------------------------------
// FAVOR+ features -> half. Natural [m][d]/[tok][d] layout, float4 smem reads.
// Summation order over d unchanged (sequential) => bit-identical results.
// ---------------------------------------------------------------------------
__global__ __launch_bounds__(256)
void phi_kernel(const float* __restrict__ qkv,
                const float* __restrict__ wf,
                __half* __restrict__ phiq,
                __half* __restrict__ phik)
{
    int grp = blockIdx.x;
    int bh  = blockIdx.y;
    int isk = blockIdx.z;
    int h = bh % NH, b = bh / NH;
    int t = threadIdx.x;

    __shared__ float wfs[64][68];      // natural [m][d], padded
    __shared__ float xs[32][68];       // [tok][d], padded
    __shared__ float sqs[32];

    // stage wf: 1024 float4 chunks
    for (int i = t; i < 1024; i += 256) {
        int m = i >> 4, ch = i & 15;
        *(float4*)&wfs[m][ch * 4] = *(const float4*)(wf + m * 64 + ch * 4);
    }
    int base_s = grp * 32;
    // stage x: 512 float4 chunks, scaled
    for (int i = t; i < 512; i += 256) {
        int tok = i >> 4, ch = i & 15;
        float4 v = *(const float4*)(qkv + ((size_t)(b * 1024 + base_s + tok)) * D3
                                    + isk * DMODEL + h * DH + ch * 4);
        const float sc = 0.3535533905932738f;
        v.x *= sc; v.y *= sc; v.z *= sc; v.w *= sc;
        *(float4*)&xs[tok][ch * 4] = v;
    }
    __syncthreads();
    if (t < 32) {
        float sq = 0.f;
#pragma unroll
        for (int ch = 0; ch < 16; ch++) {
            float4 v = *(float4*)&xs[t][ch * 4];
            sq += v.x * v.x + v.y * v.y + v.z * v.z + v.w * v.w;
        }
        sqs[t] = 0.5f * sq;
    }
    __syncthreads();

    int m = t & 63;
    __half* dst = (isk ? phik : phiq);
#pragma unroll
    for (int it = 0; it < 8; it++) {
        int tok = (t >> 6) * 8 + it;
        float proj = 0.f;
#pragma unroll
        for (int ch = 0; ch < 16; ch++) {
            float4 xv = *(float4*)&xs[tok][ch * 4];
            float4 wv = *(float4*)&wfs[m][ch * 4];
            proj += xv.x * wv.x;
            proj += xv.y * wv.y;
            proj += xv.z * wv.z;
            proj += xv.w * wv.w;
        }
        dst[((size_t)bh * 1024 + base_s + tok) * MF + m] =
            __float2half_rn(expf(proj - sqs[tok]) * 0.125f + 1e-6f);
    }
}

// ---------------------------------------------------------------------------
// Per-chunk KV state (phik half), d-split x2: grid (NCHUNK, BH, 2)
// ---------------------------------------------------------------------------
__global__ void chunkkv_kernel(const float* __restrict__ qkv,
                               const __half* __restrict__ phik,
                               float* __restrict__ kvs,
                               float* __restrict__ ks)
{
    int c  = blockIdx.x;
    int bh = blockIdx.y;
    int z  = blockIdx.z;
    int h = bh % NH, b = bh / NH;
    int t = threadIdx.x;

    __shared__ float pk[CHUNK][MF];
    __shared__ float sv[CHUNK][32];

    for (int i = t; i < CHUNK * 64; i += 256) {
        int s = i >> 6, d = i & 63;
        pk[s][d] = __half2float(phik[((size_t)bh * 1024 + c * CHUNK + s) * MF + d]);
    }
    for (int i = t; i < CHUNK * 32; i += 256) {
        int s = i >> 5, d = i & 31;
        sv[s][d] = qkv[((size_t)(b * 1024 + c * CHUNK + s)) * D3
                       + 2 * DMODEL + h * DH + z * 32 + d];
    }
    __syncthreads();

    int m  = t & 63;
    int dl = (t >> 6) * 8;
    float acc[8];
#pragma unroll
    for (int j = 0; j < 8; j++) acc[j] = 0.f;
    float sksum = 0.f;

    for (int s = 0; s < CHUNK; s++) {
        float pkm = pk[s][m];
        if (dl == 0) sksum += pkm;
#pragma unroll
        for (int j = 0; j < 8; j++) acc[j] += pkm * sv[s][dl + j];
    }
    float* dst = kvs + ((size_t)bh * NCHUNK + c) * (MF * DH) + m * DH + z * 32 + dl;
#pragma unroll
    for (int j = 0; j < 8; j++) dst[j] = acc[j];
    if (z == 0 && dl == 0) ks[((size_t)bh * NCHUNK + c) * MF + m] = sksum;
}

// ---------------------------------------------------------------------------
// Exclusive prefix over chunk states
// ---------------------------------------------------------------------------
__global__ void scan_kernel(const float* __restrict__ kvs,
                            const float* __restrict__ ks,
                            float* __restrict__ kvp,
                            float* __restrict__ ksp)
{
    int bh = blockIdx.x;
    int grp = blockIdx.y;
    int t = threadIdx.x;
    int idx = grp * 256 + t;

    float acc = 0.f;
    size_t base = (size_t)bh * NCHUNK * (MF * DH) + idx;
#pragma unroll
    for (int c = 0; c < NCHUNK; c++) {
        float v = kvs[base + (size_t)c * (MF * DH)];
        kvp[base + (size_t)c * (MF * DH)] = acc;
        acc += v;
    }
    if (grp == 0 && t < MF) {
        float a2 = 0.f;
        size_t kb = (size_t)bh * NCHUNK * MF + t;
#pragma unroll
        for (int c = 0; c < NCHUNK; c++) {
            float v = ks[kb + (size_t)c * MF];
            ksp[kb + (size_t)c * MF] = a2;
            a2 += v;
        }
    }
}

// ---------------------------------------------------------------------------
// Tensorized intra-chunk causal combine.
// ---------------------------------------------------------------------------
#define XROW 136
#define WROW 168

__global__ __launch_bounds__(128)
void intra_kernel(const float* __restrict__ qkv,
                  const __half* __restrict__ phiq,
                  const __half* __restrict__ phik,
                  const float* __restrict__ kvpre,
                  const float* __restrict__ kspre,
                  __half* __restrict__ ctx)
{
    extern __shared__ __align__(16) char ism[];
    __half* pkh = (__half*)ism;                    // 64*72
    __half* Xh  = (__half*)(ism + 9216);           // 64*136
    __half* Wh  = (__half*)(ism + 9216 + 17408);   // 128*168
    unsigned pksb = (unsigned)__cvta_generic_to_shared(pkh);
    unsigned xsb  = (unsigned)__cvta_generic_to_shared(Xh);
    unsigned wsb  = (unsigned)__cvta_generic_to_shared(Wh);

    int c  = blockIdx.x;
    int bh = blockIdx.y;
    int h = bh % NH, b = bh / NH;
    int t = threadIdx.x;
    int lane = t & 31, warp = t >> 5;
    int g = lane >> 2, tig = lane & 3;

    const __half* pkg = phik + ((size_t)bh * 1024 + c * CHUNK) * MF;
    const __half* pqg = phiq + ((size_t)bh * 1024 + c * CHUNK) * MF;
#pragma unroll
    for (int k = 0; k < 4; k++) {
        int idx = t + k * 128, r = idx >> 3, ch = idx & 7;
        uint4 vk = *(const uint4*)(pkg + (size_t)r * MF + ch * 8);
        *(uint4*)(pkh + r * 72 + ch * 8) = vk;
        uint4 vq = *(const uint4*)(pqg + (size_t)r * MF + ch * 8);
        *(uint4*)(Xh + r * XROW + 64 + ch * 8) = vq;
    }
    size_t kvbase = ((size_t)bh * NCHUNK + c) * (MF * DH);
#pragma unroll
    for (int k = 0; k < 8; k++) {
        int idx = t + k * 128, r = idx >> 4, ch = idx & 15;
        float4 fv = *(const float4*)(qkv + ((size_t)(b * 1024 + c * CHUNK + r)) * D3
                                     + 2 * DMODEL + h * DH + ch * 4);
        __half2 h0 = __floats2half2_rn(fv.x, fv.y);
        __half2 h1 = __floats2half2_rn(fv.z, fv.w);
        *(__half2*)(Wh + r * WROW + ch * 4)     = h0;
        *(__half2*)(Wh + r * WROW + ch * 4 + 2) = h1;
        float4 fk = *(const float4*)(kvpre + kvbase + (size_t)r * DH + ch * 4);
        h0 = __floats2half2_rn(fk.x, fk.y);
        h1 = __floats2half2_rn(fk.z, fk.w);
        *(__half2*)(Wh + (64 + r) * WROW + ch * 4)     = h0;
        *(__half2*)(Wh + (64 + r) * WROW + ch * 4 + 2) = h1;
    }
    {
        int r = t;
        __half c64 = (r < 64) ? __float2half(1.f)
                   : __float2half_rn(kspre[((size_t)bh * NCHUNK + c) * MF + (r - 64)]);
        Wh[r * WROW + 64] = c64;
#pragma unroll
        for (int cc = 65; cc < 80; cc++) Wh[r * WROW + cc] = __float2half(0.f);
    }
    __syncthreads();

    int a_r  = lane & 15;
    int a_kh = (lane >> 4) * 8;
    int b_n  = ((lane >> 4) << 3) + (lane & 7);
    int b_kh = ((lane >> 3) & 1) * 8;
    int b_r   = lane & 7;
    int b_mi  = lane >> 3;
    int b_kh2 = (b_mi & 1) * 8;
    int b_no  = (b_mi >> 1) * 8;

    int rbase = warp * 16;

    float acc1[8][4];
#pragma unroll
    for (int j = 0; j < 8; j++)
#pragma unroll
        for (int r = 0; r < 4; r++) acc1[j][r] = 0.f;

#pragma unroll
    for (int ks = 0; ks < 4; ks++) {
        int kb = ks * 16;
        unsigned af[4];
        ldsm_x4(af[0], af[1], af[2], af[3],
                xsb + (rbase + a_r) * (XROW * 2) + (64 + kb + a_kh) * 2);
#pragma unroll
        for (int j16 = 0; j16 < 4; j16++) {
            unsigned bf[4];
            ldsm_x4(bf[0], bf[1], bf[2], bf[3],
                    pksb + (j16 * 16 + b_n) * 144 + (kb + b_kh) * 2);
            mma_f16(acc1[j16 * 2],     af, bf[0], bf[1]);
            mma_f16(acc1[j16 * 2 + 1], af, bf[2], bf[3]);
        }
    }
    {
        int row0 = rbase + g, row1 = row0 + 8;
#pragma unroll
        for (int j = 0; j < 8; j++) {
            int col = j * 8 + 2 * tig;
            __half2 v0 = __floats2half2_rn(col <= row0 ? acc1[j][0] : 0.f,
                                           col + 1 <= row0 ? acc1[j][1] : 0.f);
            __half2 v1 = __floats2half2_rn(col <= row1 ? acc1[j][2] : 0.f,
                                           col + 1 <= row1 ? acc1[j][3] : 0.f);
            *(__half2*)(Xh + row0 * XROW + col) = v0;
            *(__half2*)(Xh + row1 * XROW + col) = v1;
        }
    }
    __syncthreads();

    float acc2[9][4];
#pragma unroll
    for (int j = 0; j < 9; j++)
#pragma unroll
        for (int r = 0; r < 4; r++) acc2[j][r] = 0.f;

#pragma unroll
    for (int ks = 0; ks < 8; ks++) {
        int kb = ks * 16;
        unsigned af[4];
        ldsm_x4(af[0], af[1], af[2], af[3],
                xsb + (rbase + a_r) * (XROW * 2) + (kb + a_kh) * 2);
        unsigned brow = wsb + (kb + b_kh2 + b_r) * (WROW * 2);
#pragma unroll
        for (int p = 0; p < 4; p++) {
            unsigned bf[4];
            ldsm_x4t(bf[0], bf[1], bf[2], bf[3], brow + (p * 16 + b_no) * 2);
            mma_f16(acc2[p * 2],     af, bf[0], bf[1]);
            mma_f16(acc2[p * 2 + 1], af, bf[2], bf[3]);
        }
        unsigned bf[4];
        ldsm_x4t(bf[0], bf[1], bf[2], bf[3], brow + (64 + b_no) * 2);
        mma_f16(acc2[8], af, bf[0], bf[1]);
    }

    float den0 = __shfl_sync(0xffffffffu, acc2[8][0], lane & ~3);
    float den1 = __shfl_sync(0xffffffffu, acc2[8][2], lane & ~3);
    float inv0 = 1.f / den0, inv1 = 1.f / den1;

    int row0 = rbase + g, row1 = row0 + 8;
    __half* c0 = ctx + ((size_t)(b * 1024 + c * CHUNK + row0)) * DMODEL + h * DH;
    __half* c1 = ctx + ((size_t)(b * 1024 + c * CHUNK + row1)) * DMODEL + h * DH;
#pragma unroll
    for (int j = 0; j < 8; j++) {
        int col = j * 8 + 2 * tig;
        *(__half2*)(c0 + col) = __floats2half2_rn(acc2[j][0] * inv0, acc2[j][1] * inv0);
        *(__half2*)(c1 + col) = __floats2half2_rn(acc2[j][2] * inv1, acc2[j][3] * inv1);
    }
}

// ---------------------------------------------------------------------------
static const int INTRA_SMEM = 9216 + 17408 + 43008;     // 69632
static const int GSM_128 = 4 * (128 * 80 + 32 * BROW);  // 75776
static const int GSM_64  = 4 * (64 * 80 + 32 * BROW);   // 55296

extern "C" void kernel_launch(void* const* d_in, const int* in_sizes, int n_in,
                              void* d_out, int out_size)
{
    const float* x      = (const float*)d_in[0];
    const float* ln1_g  = (const float*)d_in[1];
    const float* ln1_b  = (const float*)d_in[2];
    const float* w_attn = (const float*)d_in[3];
    const float* b_attn = (const float*)d_in[4];
    const float* w_feat = (const float*)d_in[5];
    const float* w_proj = (const float*)d_in[6];
    const float* b_proj = (const float*)d_in[7];
    const float* ln2_g  = (const float*)d_in[8];
    const float* ln2_b  = (const float*)d_in[9];
    const float* w_fc   = (const float*)d_in[10];
    const float* b_fc   = (const float*)d_in[11];
    const float* w_out  = (const float*)d_in[12];
    const float* b_out  = (const float*)d_in[13];
    float* out = (float*)d_out;

    float *qkv, *kv, *kvp, *ks, *ksp, *x2;
    __half *phiq, *phik, *ah, *ctxh, *ffnh, *wAh, *wPh, *wFh, *wOh;
    cudaGetSymbolAddress((void**)&qkv,  g_qkv);
    cudaGetSymbolAddress((void**)&phiq, g_phiq);
    cudaGetSymbolAddress((void**)&phik, g_phik);
    cudaGetSymbolAddress((void**)&kv,   g_kv);
    cudaGetSymbolAddress((void**)&kvp,  g_kvp);
    cudaGetSymbolAddress((void**)&ks,   g_ks);
    cudaGetSymbolAddress((void**)&ksp,  g_ksp);
    cudaGetSymbolAddress((void**)&x2,   g_x2);
    cudaGetSymbolAddress((void**)&ah,   g_ah);
    cudaGetSymbolAddress((void**)&ctxh, g_ctxh);
    cudaGetSymbolAddress((void**)&ffnh, g_ffnh);
    cudaGetSymbolAddress((void**)&wAh,  g_wAh);
    cudaGetSymbolAddress((void**)&wPh,  g_wPh);
    cudaGetSymbolAddress((void**)&wFh,  g_wFh);
    cudaGetSymbolAddress((void**)&wOh,  g_wOh);

    cudaFuncSetAttribute(intra_kernel,
        cudaFuncAttributeMaxDynamicSharedMemorySize, INTRA_SMEM);
    cudaFuncSetAttribute(hgemm<128, false, false, false>,
        cudaFuncAttributeMaxDynamicSharedMemorySize, GSM_128);
    cudaFuncSetAttribute(hgemm<128, true, false, true>,
        cudaFuncAttributeMaxDynamicSharedMemorySize, GSM_128);
    cudaFuncSetAttribute(hgemm<64, false, true, false>,
        cudaFuncAttributeMaxDynamicSharedMemorySize, GSM_64);

    conv4_kernel<<<(NW1 + NW2 + NW3 + NW4) / 8 / 256, 256>>>(
        w_attn, w_proj, w_fc, w_out, wAh, wPh, wFh, wOh);

    ln_kernel<<<ROWS, 256>>>(x, ln1_g, ln1_b, ah);
    hgemm<128, false, false, false><<<dim3(D3 / 128, ROWS / 128), 256, GSM_128>>>(
        ah, wAh, b_attn, nullptr, qkv, nullptr, D3, DMODEL);
    phi_kernel<<<dim3(32, BH, 2), 256>>>(qkv, w_feat, phiq, phik);
    chunkkv_kernel<<<dim3(NCHUNK, BH, 2), 256>>>(qkv, phik, kv, ks);
    scan_kernel<<<dim3(BH, 16), 256>>>(kv, ks, kvp, ksp);
    intra_kernel<<<dim3(NCHUNK, BH), 128, INTRA_SMEM>>>(qkv, phiq, phik, kvp, ksp, ctxh);
    hgemm<64, false, true, false><<<dim3(DMODEL / 128, ROWS / 64), 256, GSM_64>>>(
        ctxh, wPh, b_proj, x, x2, nullptr, DMODEL, DMODEL);
    ln_kernel<<<ROWS, 256>>>(x2, ln2_g, ln2_b, ah);
    hgemm<128, true, false, true><<<dim3(DFF / 128, ROWS / 128), 256, GSM_128>>>(
        ah, wFh, b_fc, nullptr, nullptr, ffnh, DFF, DMODEL);
    hgemm<64, false, true, false><<<dim3(DMODEL / 128, ROWS / 64), 256, GSM_64>>>(
        ffnh, wOh, b_out, x2, out, nullptr, DMODEL, DFF);
}

// round 17
// speedup vs baseline: 9.0346x; 1.1684x over previous
#include <cuda_runtime.h>
#include <cuda_fp16.h>
#include <math.h>
#include <stdint.h>

// ---------------------------------------------------------------------------
// B=2, S=1024, D=768, H=12, DH=64, M=64, DFF=3072, rows = 2048
// fp16 mma.sync everywhere: GEMMs (4-stage cp.async), phi projection,
// chunk KV reduction, intra-chunk attention.
// ---------------------------------------------------------------------------

#define ROWS   2048
#define DMODEL 768
#define D3     2304
#define DFF    3072
#define NH     12
#define BH     24
#define DH     64
#define MF     64
#define CHUNK  64
#define NCHUNK 16

__device__ float  g_qkv [ROWS * D3];
__device__ __half g_phiq[BH * 1024 * MF];
__device__ __half g_phik[BH * 1024 * MF];
__device__ float  g_kv  [BH * NCHUNK * MF * DH];
__device__ float  g_kvp [BH * NCHUNK * MF * DH];
__device__ float  g_ks  [BH * NCHUNK * MF];
__device__ float  g_ksp [BH * NCHUNK * MF];
__device__ float  g_x2  [ROWS * DMODEL];
__device__ __half g_ah  [ROWS * DMODEL];
__device__ __half g_ctxh[ROWS * DMODEL];
__device__ __half g_ffnh[ROWS * DFF];
__device__ __half g_wAh [DMODEL * D3];
__device__ __half g_wPh [DMODEL * DMODEL];
__device__ __half g_wFh [DMODEL * DFF];
__device__ __half g_wOh [DFF * DMODEL];

// ---------------------------------------------------------------------------
__device__ __forceinline__ void cp_async16s(unsigned saddr, const void* gsrc) {
    asm volatile("cp.async.cg.shared.global [%0], [%1], 16;\n"
                 :: "r"(saddr), "l"(gsrc));
}
__device__ __forceinline__ void cp_commit() {
    asm volatile("cp.async.commit_group;\n");
}
template <int N>
__device__ __forceinline__ void cp_wait() {
    asm volatile("cp.async.wait_group %0;\n" :: "n"(N));
}
__device__ __forceinline__ void ldsm_x4(unsigned& r0, unsigned& r1,
                                        unsigned& r2, unsigned& r3,
                                        unsigned addr) {
    asm volatile("ldmatrix.sync.aligned.m8n8.x4.shared.b16 {%0,%1,%2,%3}, [%4];"
                 : "=r"(r0), "=r"(r1), "=r"(r2), "=r"(r3) : "r"(addr));
}
__device__ __forceinline__ void ldsm_x4t(unsigned& r0, unsigned& r1,
                                         unsigned& r2, unsigned& r3,
                                         unsigned addr) {
    asm volatile("ldmatrix.sync.aligned.m8n8.x4.trans.shared.b16 {%0,%1,%2,%3}, [%4];"
                 : "=r"(r0), "=r"(r1), "=r"(r2), "=r"(r3) : "r"(addr));
}
__device__ __forceinline__ void mma_f16(float* d, const unsigned* a,
                                        unsigned b0, unsigned b1) {
    asm volatile(
        "mma.sync.aligned.m16n8k16.row.col.f32.f16.f16.f32 "
        "{%0,%1,%2,%3}, {%4,%5,%6,%7}, {%8,%9}, {%0,%1,%2,%3};\n"
        : "+f"(d[0]), "+f"(d[1]), "+f"(d[2]), "+f"(d[3])
        : "r"(a[0]), "r"(a[1]), "r"(a[2]), "r"(a[3]), "r"(b0), "r"(b1));
}

// ---------------------------------------------------------------------------
// fp16 GEMM: C[M,N] = A[M,K] @ W[K,N] + bias (+gelu) (+res)
// ---------------------------------------------------------------------------
#define BROW 272

template <int MT, bool GELU, bool RES, bool HOUT>
__global__ __launch_bounds__(256, 2)
void hgemm(const __half* __restrict__ A, const __half* __restrict__ W,
           const float* __restrict__ bias, const float* __restrict__ res,
           float* __restrict__ Cf, __half* __restrict__ Ch, int N, int K)
{
    constexpr int MI = MT / 32;
    constexpr int A_STAGE = MT * 80;
    constexpr int B_STAGE = 32 * BROW;

    extern __shared__ __align__(16) char dsm[];
    unsigned asb = (unsigned)__cvta_generic_to_shared(dsm);
    unsigned bsb = asb + 4 * A_STAGE;

    int t    = threadIdx.x;
    int lane = t & 31;
    int warp = t >> 5;
    int bm = blockIdx.y * MT;
    int bn = blockIdx.x * 128;
    int mbase = (warp >> 2) * (MT / 2);
    int nbase = (warp & 3) * 32;
    int g   = lane >> 2;
    int tig = lane & 3;

    const __half* Ag0 = A + (size_t)bm * K;

    auto load_tile = [&](int kt, int s) {
        const __half* Ag = Ag0 + (size_t)kt * 32;
        unsigned ab = asb + s * A_STAGE;
#pragma unroll
        for (int i = 0; i < MT / 64; i++) {
            int idx = i * 256 + t, row = idx >> 2, c = idx & 3;
            cp_async16s(ab + row * 80 + c * 16, Ag + (size_t)row * K + c * 8);
        }
        const __half* Bg = W + (size_t)(kt * 32) * N + bn;
        unsigned bb = bsb + s * B_STAGE;
#pragma unroll
        for (int i = 0; i < 2; i++) {
            int idx = i * 256 + t, r = idx >> 4, c = idx & 15;
            cp_async16s(bb + r * BROW + c * 16, Bg + (size_t)r * N + c * 8);
        }
        cp_commit();
    };

    int nk = K >> 5;
    load_tile(0, 0);
    load_tile(1, 1);
    load_tile(2, 2);

    float acc[MI][4][4];
#pragma unroll
    for (int i = 0; i < MI; i++)
#pragma unroll
        for (int j = 0; j < 4; j++)
#pragma unroll
            for (int r = 0; r < 4; r++) acc[i][j][r] = 0.f;

    int a_r  = lane & 15;
    int a_kh = (lane >> 4) * 8;
    int b_r   = lane & 7;
    int b_mi  = lane >> 3;
    int b_kh2 = (b_mi & 1) * 8;
    int b_no  = (b_mi >> 1) * 8;

    for (int kt = 0; kt < nk; kt++) {
        int s = kt & 3;
        cp_wait<2>();
        __syncthreads();
        if (kt + 3 < nk) load_tile(kt + 3, (kt + 3) & 3);
        else cp_commit();

        unsigned as_s = asb + s * A_STAGE;
        unsigned bs_s = bsb + s * B_STAGE;
#pragma unroll
        for (int ks = 0; ks < 2; ks++) {
            int kb = ks * 16;
            unsigned af[MI][4], bfA[4], bfB[4];
#pragma unroll
            for (int i = 0; i < MI; i++) {
                unsigned addr = as_s + (mbase + i * 16 + a_r) * 80
                              + (kb + a_kh) * 2;
                ldsm_x4(af[i][0], af[i][1], af[i][2], af[i][3], addr);
            }
            unsigned brow = bs_s + (kb + b_kh2 + b_r) * BROW;
            ldsm_x4t(bfA[0], bfA[1], bfA[2], bfA[3],
                     brow + (nbase + b_no) * 2);
            ldsm_x4t(bfB[0], bfB[1], bfB[2], bfB[3],
                     brow + (nbase + 16 + b_no) * 2);
#pragma unroll
            for (int i = 0; i < MI; i++) {
                mma_f16(acc[i][0], af[i], bfA[0], bfA[1]);
                mma_f16(acc[i][1], af[i], bfA[2], bfA[3]);
                mma_f16(acc[i][2], af[i], bfB[0], bfB[1]);
                mma_f16(acc[i][3], af[i], bfB[2], bfB[3]);
            }
        }
    }

#pragma unroll
    for (int i = 0; i < MI; i++) {
#pragma unroll
        for (int j = 0; j < 4; j++) {
            int col = bn + nbase + j * 8 + 2 * tig;
            float b0 = bias[col], b1 = bias[col + 1];
#pragma unroll
            for (int half = 0; half < 2; half++) {
                int row = bm + mbase + i * 16 + g + half * 8;
                float v0 = acc[i][j][half * 2 + 0] + b0;
                float v1 = acc[i][j][half * 2 + 1] + b1;
                if (GELU) {
                    float u = v0, cu = u + 0.044715f * u * u * u;
                    v0 = 0.5f * u * (1.f + tanhf(0.7978845608028654f * cu));
                    u = v1; cu = u + 0.044715f * u * u * u;
                    v1 = 0.5f * u * (1.f + tanhf(0.7978845608028654f * cu));
                }
                if (RES) {
                    v0 += res[(size_t)row * N + col];
                    v1 += res[(size_t)row * N + col + 1];
                }
                if (HOUT) {
                    *(__half2*)&Ch[(size_t)row * N + col] =
                        __floats2half2_rn(v0, v1);
                } else {
                    *(float2*)&Cf[(size_t)row * N + col] = make_float2(v0, v1);
                }
            }
        }
    }
}

// ---------------------------------------------------------------------------
// merged fp32 -> fp16 convert for all four weights (one launch)
// ---------------------------------------------------------------------------
#define NW1 (DMODEL * D3)
#define NW2 (DMODEL * DMODEL)
#define NW3 (DMODEL * DFF)
#define NW4 (DFF * DMODEL)

__global__ void conv4_kernel(const float* __restrict__ s1, const float* __restrict__ s2,
                             const float* __restrict__ s3, const float* __restrict__ s4,
                             __half* __restrict__ d1, __half* __restrict__ d2,
                             __half* __restrict__ d3, __half* __restrict__ d4)
{
    long i = (long)(blockIdx.x * 256 + threadIdx.x) * 8;
    const float* s; __half* d; long off;
    if      (i < NW1)                   { s = s1; d = d1; off = i; }
    else if (i < NW1 + NW2)             { s = s2; d = d2; off = i - NW1; }
    else if (i < NW1 + NW2 + NW3)       { s = s3; d = d3; off = i - NW1 - NW2; }
    else if (i < NW1 + NW2 + NW3 + NW4) { s = s4; d = d4; off = i - NW1 - NW2 - NW3; }
    else return;
    float4 a = *(const float4*)(s + off);
    float4 b = *(const float4*)(s + off + 4);
    union { __half2 h[4]; uint4 v; } u;
    u.h[0] = __floats2half2_rn(a.x, a.y);
    u.h[1] = __floats2half2_rn(a.z, a.w);
    u.h[2] = __floats2half2_rn(b.x, b.y);
    u.h[3] = __floats2half2_rn(b.z, b.w);
    *(uint4*)(d + off) = u.v;
}

// ---------------------------------------------------------------------------
// LayerNorm -> half
// ---------------------------------------------------------------------------
__global__ void ln_kernel(const float* __restrict__ in,
                          const float* __restrict__ gamma,
                          const float* __restrict__ beta,
                          __half* __restrict__ out)
{
    int row = blockIdx.x;
    int t = threadIdx.x;
    const float* p = in + (size_t)row * DMODEL;
    float v[3];
    float s = 0.f, s2 = 0.f;
#pragma unroll
    for (int i = 0; i < 3; i++) {
        v[i] = p[t + i * 256];
        s += v[i];
        s2 += v[i] * v[i];
    }
#pragma unroll
    for (int o = 16; o; o >>= 1) {
        s  += __shfl_xor_sync(0xffffffffu, s, o);
        s2 += __shfl_xor_sync(0xffffffffu, s2, o);
    }
    __shared__ float ss[8], ss2[8];
    if ((t & 31) == 0) { ss[t >> 5] = s; ss2[t >> 5] = s2; }
    __syncthreads();
    s = 0.f; s2 = 0.f;
#pragma unroll
    for (int i = 0; i < 8; i++) { s += ss[i]; s2 += ss2[i]; }
    float mu  = s * (1.f / DMODEL);
    float var = s2 * (1.f / DMODEL) - mu * mu;
    float rstd = rsqrtf(var + 1e-5f);
    __half* q = out + (size_t)row * DMODEL;
#pragma unroll
    for (int i = 0; i < 3; i++) {
        int c = t + i * 256;
        q[c] = __float2half_rn((v[i] - mu) * rstd * gamma[c] + beta[c]);
    }
}

// ---------------------------------------------------------------------------
// Tensorized FAVOR+ features: proj = x_h @ wf^T via mma (64x64x64 per block),
// phi = exp(proj - 0.5|x_h|^2)/8 + 1e-6 (sq from the SAME half x => consistent).
// grid (NCHUNK, BH, 2), 128 threads (4 warps x 16 token rows).
// ---------------------------------------------------------------------------
__global__ __launch_bounds__(128)
void phi_mma_kernel(const float* __restrict__ qkv,
                    const float* __restrict__ wf,
                    __half* __restrict__ phiq,
                    __half* __restrict__ phik)
{
    __shared__ __align__(16) __half Xh[64 * 72];
    __shared__ __align__(16) __half Wfh[64 * 72];
    __shared__ float sqs[64];
    unsigned xsb = (unsigned)__cvta_generic_to_shared(Xh);
    unsigned wsb = (unsigned)__cvta_generic_to_shared(Wfh);

    int c   = blockIdx.x;
    int bh  = blockIdx.y;
    int isk = blockIdx.z;
    int h = bh % NH, b = bh / NH;
    int t = threadIdx.x;
    int lane = t & 31, warp = t >> 5;
    int g = lane >> 2, tig = lane & 3;

    // stage x (scaled, half) and wf (half)
    const float sc = 0.3535533905932738f;
#pragma unroll
    for (int k = 0; k < 8; k++) {
        int idx = t + k * 128, r = idx >> 4, ch = idx & 15;
        float4 v = *(const float4*)(qkv + ((size_t)(b * 1024 + c * CHUNK + r)) * D3
                                    + isk * DMODEL + h * DH + ch * 4);
        *(__half2*)(Xh + r * 72 + ch * 4)     = __floats2half2_rn(v.x * sc, v.y * sc);
        *(__half2*)(Xh + r * 72 + ch * 4 + 2) = __floats2half2_rn(v.z * sc, v.w * sc);
        float4 w = *(const float4*)(wf + r * 64 + ch * 4);
        *(__half2*)(Wfh + r * 72 + ch * 4)     = __floats2half2_rn(w.x, w.y);
        *(__half2*)(Wfh + r * 72 + ch * 4 + 2) = __floats2half2_rn(w.z, w.w);
    }
    __syncthreads();
    if (t < 64) {
        float sq = 0.f;
#pragma unroll
        for (int ch = 0; ch < 32; ch++) {
            float2 v = __half22float2(*(__half2*)(Xh + t * 72 + ch * 2));
            sq += v.x * v.x + v.y * v.y;
        }
        sqs[t] = 0.5f * sq;
    }
    __syncthreads();

    int a_r  = lane & 15;
    int a_kh = (lane >> 4) * 8;
    int b_n  = ((lane >> 4) << 3) + (lane & 7);
    int b_kh = ((lane >> 3) & 1) * 8;
    int rbase = warp * 16;

    float acc[8][4];
#pragma unroll
    for (int j = 0; j < 8; j++)
#pragma unroll
        for (int r = 0; r < 4; r++) acc[j][r] = 0.f;

#pragma unroll
    for (int ks = 0; ks < 4; ks++) {
        int kb = ks * 16;
        unsigned af[4];
        ldsm_x4(af[0], af[1], af[2], af[3],
                xsb + (rbase + a_r) * 144 + (kb + a_kh) * 2);
#pragma unroll
        for (int j16 = 0; j16 < 4; j16++) {
            unsigned bf[4];
            ldsm_x4(bf[0], bf[1], bf[2], bf[3],
                    wsb + (j16 * 16 + b_n) * 144 + (kb + b_kh) * 2);
            mma_f16(acc[j16 * 2],     af, bf[0], bf[1]);
            mma_f16(acc[j16 * 2 + 1], af, bf[2], bf[3]);
        }
    }

    int row0 = rbase + g, row1 = row0 + 8;
    float sq0 = sqs[row0], sq1 = sqs[row1];
    __half* dst = (isk ? phik : phiq) + ((size_t)bh * 1024 + c * CHUNK) * MF;
#pragma unroll
    for (int j = 0; j < 8; j++) {
        int col = j * 8 + 2 * tig;
        float e00 = expf(acc[j][0] - sq0) * 0.125f + 1e-6f;
        float e01 = expf(acc[j][1] - sq0) * 0.125f + 1e-6f;
        float e10 = expf(acc[j][2] - sq1) * 0.125f + 1e-6f;
        float e11 = expf(acc[j][3] - sq1) * 0.125f + 1e-6f;
        *(__half2*)(dst + (size_t)row0 * MF + col) = __floats2half2_rn(e00, e01);
        *(__half2*)(dst + (size_t)row1 * MF + col) = __floats2half2_rn(e10, e11);
    }
}

// ---------------------------------------------------------------------------
// Tensorized chunk KV: kv[m][d] = sum_s pk[s][m] * v[s][d], ks[m] = sum_s pk[s][m]
// A = pk^T (transpose-staged [m][s]); B = [v | 1] (trans ldsm), fp32 acc.
// grid (NCHUNK, BH), 128 threads.
// ---------------------------------------------------------------------------
#define VROW 88

__global__ __launch_bounds__(128)
void chunkkv_mma_kernel(const float* __restrict__ qkv,
                        const __half* __restrict__ phik,
                        float* __restrict__ kvs,
                        float* __restrict__ ks)
{
    __shared__ __align__(16) __half pkT[64 * 72];   // [m][s]
    __shared__ __align__(16) __half Vh[64 * VROW];  // [s][d | 1 | 0pad]
    unsigned psb = (unsigned)__cvta_generic_to_shared(pkT);
    unsigned vsb = (unsigned)__cvta_generic_to_shared(Vh);

    int c  = blockIdx.x;
    int bh = blockIdx.y;
    int h = bh % NH, b = bh / NH;
    int t = threadIdx.x;
    int lane = t & 31, warp = t >> 5;
    int g = lane >> 2, tig = lane & 3;

    // stage v -> half
#pragma unroll
    for (int k = 0; k < 8; k++) {
        int idx = t + k * 128, s = idx >> 4, ch = idx & 15;
        float4 v = *(const float4*)(qkv + ((size_t)(b * 1024 + c * CHUNK + s)) * D3
                                    + 2 * DMODEL + h * DH + ch * 4);
        *(__half2*)(Vh + s * VROW + ch * 4)     = __floats2half2_rn(v.x, v.y);
        *(__half2*)(Vh + s * VROW + ch * 4 + 2) = __floats2half2_rn(v.z, v.w);
    }
    // ones column + zero pad (cols 64..79)
    if (t < 64) {
        Vh[t * VROW + 64] = __float2half(1.f);
#pragma unroll
        for (int cc = 65; cc < 80; cc++) Vh[t * VROW + cc] = __float2half(0.f);
    }
    // stage pk transposed: global [s][m] -> smem [m][s]
    const __half* pkg = phik + ((size_t)bh * 1024 + c * CHUNK) * MF;
#pragma unroll
    for (int k = 0; k < 4; k++) {
        int idx = t + k * 128, s = idx >> 3, ch = idx & 7;
        union { uint4 u; __half hh[8]; } cv;
        cv.u = *(const uint4*)(pkg + (size_t)s * MF + ch * 8);
#pragma unroll
        for (int e = 0; e < 8; e++)
            pkT[(ch * 8 + e) * 72 + s] = cv.hh[e];
    }
    __syncthreads();

    int a_r  = lane & 15;
    int a_kh = (lane >> 4) * 8;
    int b_r   = lane & 7;
    int b_mi  = lane >> 3;
    int b_kh2 = (b_mi & 1) * 8;
    int b_no  = (b_mi >> 1) * 8;
    int rbase = warp * 16;

    float acc[9][4];
#pragma unroll
    for (int j = 0; j < 9; j++)
#pragma unroll
        for (int r = 0; r < 4; r++) acc[j][r] = 0.f;

#pragma unroll
    for (int ks4 = 0; ks4 < 4; ks4++) {
        int kb = ks4 * 16;
        unsigned af[4];
        ldsm_x4(af[0], af[1], af[2], af[3],
                psb + (rbase + a_r) * 144 + (kb + a_kh) * 2);
        unsigned brow = vsb + (kb + b_kh2 + b_r) * (VROW * 2);
#pragma unroll
        for (int p = 0; p < 4; p++) {
            unsigned bf[4];
            ldsm_x4t(bf[0], bf[1], bf[2], bf[3], brow + (p * 16 + b_no) * 2);
            mma_f16(acc[p * 2],     af, bf[0], bf[1]);
            mma_f16(acc[p * 2 + 1], af, bf[2], bf[3]);
        }
        unsigned bf[4];
        ldsm_x4t(bf[0], bf[1], bf[2], bf[3], brow + (64 + b_no) * 2);
        mma_f16(acc[8], af, bf[0], bf[1]);
    }

    int row0 = rbase + g, row1 = row0 + 8;   // m indices
    float* dst = kvs + ((size_t)bh * NCHUNK + c) * (MF * DH);
#pragma unroll
    for (int j = 0; j < 8; j++) {
        int col = j * 8 + 2 * tig;
        *(float2*)(dst + (size_t)row0 * DH + col) = make_float2(acc[j][0], acc[j][1]);
        *(float2*)(dst + (size_t)row1 * DH + col) = make_float2(acc[j][2], acc[j][3]);
    }
    if (tig == 0) {
        float* kd = ks + ((size_t)bh * NCHUNK + c) * MF;
        kd[row0] = acc[8][0];
        kd[row1] = acc[8][2];
    }
}

// ---------------------------------------------------------------------------
// Exclusive prefix over chunk states
// ---------------------------------------------------------------------------
__global__ void scan_kernel(const float* __restrict__ kvs,
                            const float* __restrict__ ks,
                            float* __restrict__ kvp,
                            float* __restrict__ ksp)
{
    int bh = blockIdx.x;
    int grp = blockIdx.y;
    int t = threadIdx.x;
    int idx = grp * 256 + t;

    float acc = 0.f;
    size_t base = (size_t)bh * NCHUNK * (MF * DH) + idx;
#pragma unroll
    for (int c = 0; c < NCHUNK; c++) {
        float v = kvs[base + (size_t)c * (MF * DH)];
        kvp[base + (size_t)c * (MF * DH)] = acc;
        acc += v;
    }
    if (grp == 0 && t < MF) {
        float a2 = 0.f;
        size_t kb = (size_t)bh * NCHUNK * MF + t;
#pragma unroll
        for (int c = 0; c < NCHUNK; c++) {
            float v = ks[kb + (size_t)c * MF];
            ksp[kb + (size_t)c * MF] = a2;
            a2 += v;
        }
    }
}

// ---------------------------------------------------------------------------
// Tensorized intra-chunk causal combine.
// ---------------------------------------------------------------------------
#define XROW 136
#define WROW 168

__global__ __launch_bounds__(128)
void intra_kernel(const float* __restrict__ qkv,
                  const __half* __restrict__ phiq,
                  const __half* __restrict__ phik,
                  const float* __restrict__ kvpre,
                  const float* __restrict__ kspre,
                  __half* __restrict__ ctx)
{
    extern __shared__ __align__(16) char ism[];
    __half* pkh = (__half*)ism;                    // 64*72
    __half* Xh  = (__half*)(ism + 9216);           // 64*136
    __half* Wh  = (__half*)(ism + 9216 + 17408);   // 128*168
    unsigned pksb = (unsigned)__cvta_generic_to_shared(pkh);
    unsigned xsb  = (unsigned)__cvta_generic_to_shared(Xh);
    unsigned wsb  = (unsigned)__cvta_generic_to_shared(Wh);

    int c  = blockIdx.x;
    int bh = blockIdx.y;
    int h = bh % NH, b = bh / NH;
    int t = threadIdx.x;
    int lane = t & 31, warp = t >> 5;
    int g = lane >> 2, tig = lane & 3;

    const __half* pkg = phik + ((size_t)bh * 1024 + c * CHUNK) * MF;
    const __half* pqg = phiq + ((size_t)bh * 1024 + c * CHUNK) * MF;
#pragma unroll
    for (int k = 0; k < 4; k++) {
        int idx = t + k * 128, r = idx >> 3, ch = idx & 7;
        uint4 vk = *(const uint4*)(pkg + (size_t)r * MF + ch * 8);
        *(uint4*)(pkh + r * 72 + ch * 8) = vk;
        uint4 vq = *(const uint4*)(pqg + (size_t)r * MF + ch * 8);
        *(uint4*)(Xh + r * XROW + 64 + ch * 8) = vq;
    }
    size_t kvbase = ((size_t)bh * NCHUNK + c) * (MF * DH);
#pragma unroll
    for (int k = 0; k < 8; k++) {
        int idx = t + k * 128, r = idx >> 4, ch = idx & 15;
        float4 fv = *(const float4*)(qkv + ((size_t)(b * 1024 + c * CHUNK + r)) * D3
                                     + 2 * DMODEL + h * DH + ch * 4);
        __half2 h0 = __floats2half2_rn(fv.x, fv.y);
        __half2 h1 = __floats2half2_rn(fv.z, fv.w);
        *(__half2*)(Wh + r * WROW + ch * 4)     = h0;
        *(__half2*)(Wh + r * WROW + ch * 4 + 2) = h1;
        float4 fk = *(const float4*)(kvpre + kvbase + (size_t)r * DH + ch * 4);
        h0 = __floats2half2_rn(fk.x, fk.y);
        h1 = __floats2half2_rn(fk.z, fk.w);
        *(__half2*)(Wh + (64 + r) * WROW + ch * 4)     = h0;
        *(__half2*)(Wh + (64 + r) * WROW + ch * 4 + 2) = h1;
    }
    {
        int r = t;
        __half c64 = (r < 64) ? __float2half(1.f)
                   : __float2half_rn(kspre[((size_t)bh * NCHUNK + c) * MF + (r - 64)]);
        Wh[r * WROW + 64] = c64;
#pragma unroll
        for (int cc = 65; cc < 80; cc++) Wh[r * WROW + cc] = __float2half(0.f);
    }
    __syncthreads();

    int a_r  = lane & 15;
    int a_kh = (lane >> 4) * 8;
    int b_n  = ((lane >> 4) << 3) + (lane & 7);
    int b_kh = ((lane >> 3) & 1) * 8;
    int b_r   = lane & 7;
    int b_mi  = lane >> 3;
    int b_kh2 = (b_mi & 1) * 8;
    int b_no  = (b_mi >> 1) * 8;

    int rbase = warp * 16;

    float acc1[8][4];
#pragma unroll
    for (int j = 0; j < 8; j++)
#pragma unroll
        for (int r = 0; r < 4; r++) acc1[j][r] = 0.f;

#pragma unroll
    for (int ks = 0; ks < 4; ks++) {
        int kb = ks * 16;
        unsigned af[4];
        ldsm_x4(af[0], af[1], af[2], af[3],
                xsb + (rbase + a_r) * (XROW * 2) + (64 + kb + a_kh) * 2);
#pragma unroll
        for (int j16 = 0; j16 < 4; j16++) {
            unsigned bf[4];
            ldsm_x4(bf[0], bf[1], bf[2], bf[3],
                    pksb + (j16 * 16 + b_n) * 144 + (kb + b_kh) * 2);
            mma_f16(acc1[j16 * 2],     af, bf[0], bf[1]);
            mma_f16(acc1[j16 * 2 + 1], af, bf[2], bf[3]);
        }
    }
    {
        int row0 = rbase + g, row1 = row0 + 8;
#pragma unroll
        for (int j = 0; j < 8; j++) {
            int col = j * 8 + 2 * tig;
            __half2 v0 = __floats2half2_rn(col <= row0 ? acc1[j][0] : 0.f,
                                           col + 1 <= row0 ? acc1[j][1] : 0.f);
            __half2 v1 = __floats2half2_rn(col <= row1 ? acc1[j][2] : 0.f,
                                           col + 1 <= row1 ? acc1[j][3] : 0.f);
            *(__half2*)(Xh + row0 * XROW + col) = v0;
            *(__half2*)(Xh + row1 * XROW + col) = v1;
        }
    }
    __syncthreads();

    float acc2[9][4];
#pragma unroll
    for (int j = 0; j < 9; j++)
#pragma unroll
        for (int r = 0; r < 4; r++) acc2[j][r] = 0.f;

#pragma unroll
    for (int ks = 0; ks < 8; ks++) {
        int kb = ks * 16;
        unsigned af[4];
        ldsm_x4(af[0], af[1], af[2], af[3],
                xsb + (rbase + a_r) * (XROW * 2) + (kb + a_kh) * 2);
        unsigned brow = wsb + (kb + b_kh2 + b_r) * (WROW * 2);
#pragma unroll
        for (int p = 0; p < 4; p++) {
            unsigned bf[4];
            ldsm_x4t(bf[0], bf[1], bf[2], bf[3], brow + (p * 16 + b_no) * 2);
            mma_f16(acc2[p * 2],     af, bf[0], bf[1]);
            mma_f16(acc2[p * 2 + 1], af, bf[2], bf[3]);
        }
        unsigned bf[4];
        ldsm_x4t(bf[0], bf[1], bf[2], bf[3], brow + (64 + b_no) * 2);
        mma_f16(acc2[8], af, bf[0], bf[1]);
    }

    float den0 = __shfl_sync(0xffffffffu, acc2[8][0], lane & ~3);
    float den1 = __shfl_sync(0xffffffffu, acc2[8][2], lane & ~3);
    float inv0 = 1.f / den0, inv1 = 1.f / den1;

    int row0 = rbase + g, row1 = row0 + 8;
    __half* c0 = ctx + ((size_t)(b * 1024 + c * CHUNK + row0)) * DMODEL + h * DH;
    __half* c1 = ctx + ((size_t)(b * 1024 + c * CHUNK + row1)) * DMODEL + h * DH;
#pragma unroll
    for (int j = 0; j < 8; j++) {
        int col = j * 8 + 2 * tig;
        *(__half2*)(c0 + col) = __floats2half2_rn(acc2[j][0] * inv0, acc2[j][1] * inv0);
        *(__half2*)(c1 + col) = __floats2half2_rn(acc2[j][2] * inv1, acc2[j][3] * inv1);
    }
}

// ---------------------------------------------------------------------------
static const int INTRA_SMEM = 9216 + 17408 + 43008;     // 69632
static const int GSM_128 = 4 * (128 * 80 + 32 * BROW);  // 75776
static const int GSM_64  = 4 * (64 * 80 + 32 * BROW);   // 55296

extern "C" void kernel_launch(void* const* d_in, const int* in_sizes, int n_in,
                              void* d_out, int out_size)
{
    const float* x      = (const float*)d_in[0];
    const float* ln1_g  = (const float*)d_in[1];
    const float* ln1_b  = (const float*)d_in[2];
    const float* w_attn = (const float*)d_in[3];
    const float* b_attn = (const float*)d_in[4];
    const float* w_feat = (const float*)d_in[5];
    const float* w_proj = (const float*)d_in[6];
    const float* b_proj = (const float*)d_in[7];
    const float* ln2_g  = (const float*)d_in[8];
    const float* ln2_b  = (const float*)d_in[9];
    const float* w_fc   = (const float*)d_in[10];
    const float* b_fc   = (const float*)d_in[11];
    const float* w_out  = (const float*)d_in[12];
    const float* b_out  = (const float*)d_in[13];
    float* out = (float*)d_out;

    float *qkv, *kv, *kvp, *ks, *ksp, *x2;
    __half *phiq, *phik, *ah, *ctxh, *ffnh, *wAh, *wPh, *wFh, *wOh;
    cudaGetSymbolAddress((void**)&qkv,  g_qkv);
    cudaGetSymbolAddress((void**)&phiq, g_phiq);
    cudaGetSymbolAddress((void**)&phik, g_phik);
    cudaGetSymbolAddress((void**)&kv,   g_kv);
    cudaGetSymbolAddress((void**)&kvp,  g_kvp);
    cudaGetSymbolAddress((void**)&ks,   g_ks);
    cudaGetSymbolAddress((void**)&ksp,  g_ksp);
    cudaGetSymbolAddress((void**)&x2,   g_x2);
    cudaGetSymbolAddress((void**)&ah,   g_ah);
    cudaGetSymbolAddress((void**)&ctxh, g_ctxh);
    cudaGetSymbolAddress((void**)&ffnh, g_ffnh);
    cudaGetSymbolAddress((void**)&wAh,  g_wAh);
    cudaGetSymbolAddress((void**)&wPh,  g_wPh);
    cudaGetSymbolAddress((void**)&wFh,  g_wFh);
    cudaGetSymbolAddress((void**)&wOh,  g_wOh);

    cudaFuncSetAttribute(intra_kernel,
        cudaFuncAttributeMaxDynamicSharedMemorySize, INTRA_SMEM);
    cudaFuncSetAttribute(hgemm<128, false, false, false>,
        cudaFuncAttributeMaxDynamicSharedMemorySize, GSM_128);
    cudaFuncSetAttribute(hgemm<128, true, false, true>,
        cudaFuncAttributeMaxDynamicSharedMemorySize, GSM_128);
    cudaFuncSetAttribute(hgemm<64, false, true, false>,
        cudaFuncAttributeMaxDynamicSharedMemorySize, GSM_64);

    conv4_kernel<<<(NW1 + NW2 + NW3 + NW4) / 8 / 256, 256>>>(
        w_attn, w_proj, w_fc, w_out, wAh, wPh, wFh, wOh);

    ln_kernel<<<ROWS, 256>>>(x, ln1_g, ln1_b, ah);
    hgemm<128, false, false, false><<<dim3(D3 / 128, ROWS / 128), 256, GSM_128>>>(
        ah, wAh, b_attn, nullptr, qkv, nullptr, D3, DMODEL);
    phi_mma_kernel<<<dim3(NCHUNK, BH, 2), 128>>>(qkv, w_feat, phiq, phik);
    chunkkv_mma_kernel<<<dim3(NCHUNK, BH), 128>>>(qkv, phik, kv, ks);
    scan_kernel<<<dim3(BH, 16), 256>>>(kv, ks, kvp, ksp);
    intra_kernel<<<dim3(NCHUNK, BH), 128, INTRA_SMEM>>>(qkv, phiq, phik, kvp, ksp, ctxh);
    hgemm<64, false, true, false><<<dim3(DMODEL / 128, ROWS / 64), 256, GSM_64>>>(
        ctxh, wPh, b_proj, x, x2, nullptr, DMODEL, DMODEL);
    ln_kernel<<<ROWS, 256>>>(x2, ln2_g, ln2_b, ah);
    hgemm<128, true, false, true><<<dim3(DFF / 128, ROWS / 128), 256, GSM_128>>>(
        ah, wFh, b_fc, nullptr, nullptr, ffnh, DFF, DMODEL);
    hgemm<64, false, true, false><<<dim3(DMODEL / 128, ROWS / 64), 256, GSM_64>>>(
        ffnh, wOh, b_out, x2, out, nullptr, DMODEL, DFF);
}